// round 1
// baseline (speedup 1.0000x reference)
#include <cuda_runtime.h>
#include <cuda_bf16.h>
#include <math.h>

// Problem constants
#define B 4
#define N 2048
#define D 1024
#define H 16
#define HD 64
#define BN (B * N)            // 8192 rows
#define SCALE 0.125f          // 1/sqrt(64)

// Scratch (device globals: no allocations allowed)
__device__ float g_qkv[BN * 3 * D];   // [8192, 3072]
__device__ float g_att[BN * D];       // [8192, 1024]  attention output, head-concat layout

// ---------------------------------------------------------------------------
// GEMM: C[M,N] = A[M,K] @ W[K,N] + bias[N]   (all row-major, dims % 64 == 0, K % 16 == 0)
// 64x64 tile, BK=16, 256 threads, 4x4 register tile per thread.
// ---------------------------------------------------------------------------
__global__ __launch_bounds__(256) void gemm_bias_kernel(
    const float* __restrict__ A, const float* __restrict__ W,
    const float* __restrict__ bias, float* __restrict__ C,
    int M, int Nn, int K)
{
    __shared__ __align__(16) float As[16][64];  // [k][m]
    __shared__ __align__(16) float Bs[16][64];  // [k][n]

    const int tid = threadIdx.x;
    const int tx = tid & 15;          // n sub-tile
    const int ty = tid >> 4;          // m sub-tile
    const int m0 = blockIdx.y * 64;
    const int n0 = blockIdx.x * 64;

    float c[4][4];
#pragma unroll
    for (int i = 0; i < 4; i++)
#pragma unroll
        for (int j = 0; j < 4; j++) c[i][j] = 0.0f;

    const int a_row = tid >> 2;       // 0..63
    const int a_kq  = tid & 3;        // 0..3 (float4 along K)
    const int b_row = tid >> 4;       // 0..15 (k)
    const int b_cq  = tid & 15;       // 0..15 (float4 along N)

    for (int k0 = 0; k0 < K; k0 += 16) {
        // Load A tile (64 rows x 16 k), transpose into As[k][m]
        float4 av = *reinterpret_cast<const float4*>(&A[(size_t)(m0 + a_row) * K + k0 + a_kq * 4]);
        As[a_kq * 4 + 0][a_row] = av.x;
        As[a_kq * 4 + 1][a_row] = av.y;
        As[a_kq * 4 + 2][a_row] = av.z;
        As[a_kq * 4 + 3][a_row] = av.w;
        // Load W tile (16 k x 64 n)
        *reinterpret_cast<float4*>(&Bs[b_row][b_cq * 4]) =
            *reinterpret_cast<const float4*>(&W[(size_t)(k0 + b_row) * Nn + n0 + b_cq * 4]);
        __syncthreads();

#pragma unroll
        for (int k = 0; k < 16; k++) {
            float4 a4 = *reinterpret_cast<const float4*>(&As[k][ty * 4]);
            float4 b4 = *reinterpret_cast<const float4*>(&Bs[k][tx * 4]);
            float a[4] = {a4.x, a4.y, a4.z, a4.w};
            float b[4] = {b4.x, b4.y, b4.z, b4.w};
#pragma unroll
            for (int i = 0; i < 4; i++)
#pragma unroll
                for (int j = 0; j < 4; j++) c[i][j] += a[i] * b[j];
        }
        __syncthreads();
    }

#pragma unroll
    for (int i = 0; i < 4; i++) {
        const int row = m0 + ty * 4 + i;
        float4 bv = *reinterpret_cast<const float4*>(&bias[n0 + tx * 4]);
        float4 ov;
        ov.x = c[i][0] + bv.x;
        ov.y = c[i][1] + bv.y;
        ov.z = c[i][2] + bv.z;
        ov.w = c[i][3] + bv.w;
        *reinterpret_cast<float4*>(&C[(size_t)row * Nn + n0 + tx * 4]) = ov;
    }
}

// ---------------------------------------------------------------------------
// Attention: one query per thread, flash-style online softmax.
// qkv layout per row (b*N+n): [ q(1024) | k(1024) | v(1024) ], head h at cols h*64.
// Block: 128 threads = 128 consecutive queries of one (b,h).
// Streams K/V in 64-key smem tiles; all threads walk the same key index, so
// the Ks/Vs reads are warp-broadcast (conflict-free).
// ---------------------------------------------------------------------------
__global__ __launch_bounds__(128) void attn_kernel(
    const float* __restrict__ qkv, float* __restrict__ att)
{
    __shared__ __align__(16) float Ks[64][64];
    __shared__ __align__(16) float Vs[64][64];

    const int tid = threadIdx.x;
    const int b = blockIdx.z;
    const int h = blockIdx.y;
    const int n = blockIdx.x * 128 + tid;

    const size_t row_base = (size_t)(b * N + n) * (3 * D);
    const int hcol = h * HD;

    // Load this thread's query into registers
    float q[HD];
#pragma unroll
    for (int j = 0; j < HD / 4; j++) {
        float4 v = *reinterpret_cast<const float4*>(&qkv[row_base + hcol + j * 4]);
        q[4 * j + 0] = v.x; q[4 * j + 1] = v.y; q[4 * j + 2] = v.z; q[4 * j + 3] = v.w;
    }

    float o[HD];
#pragma unroll
    for (int d = 0; d < HD; d++) o[d] = 0.0f;
    float m = -1e30f;
    float l = 0.0f;

    for (int kt = 0; kt < N / 64; kt++) {
        // Cooperative load of 64 keys + 64 values (4096 floats each) -> 8 float4/thread each
#pragma unroll
        for (int r = 0; r < 8; r++) {
            int f = tid + r * 128;          // float4 index, 0..1023
            int key = f >> 4;               // 16 float4 per key row
            int d4 = f & 15;
            size_t grow = (size_t)(b * N + kt * 64 + key) * (3 * D);
            *reinterpret_cast<float4*>(&Ks[key][d4 * 4]) =
                *reinterpret_cast<const float4*>(&qkv[grow + D + hcol + d4 * 4]);
            *reinterpret_cast<float4*>(&Vs[key][d4 * 4]) =
                *reinterpret_cast<const float4*>(&qkv[grow + 2 * D + hcol + d4 * 4]);
        }
        __syncthreads();

#pragma unroll 4
        for (int key = 0; key < 64; key++) {
            // s = q . K[key]
            const float4* kr = reinterpret_cast<const float4*>(Ks[key]);
            float s = 0.0f;
#pragma unroll
            for (int j = 0; j < 16; j++) {
                float4 kv = kr[j];
                s += q[4 * j + 0] * kv.x + q[4 * j + 1] * kv.y
                   + q[4 * j + 2] * kv.z + q[4 * j + 3] * kv.w;
            }
            s *= SCALE;

            if (s > m) {
                float alpha = __expf(m - s);
                l *= alpha;
#pragma unroll
                for (int d = 0; d < HD; d++) o[d] *= alpha;
                m = s;
            }
            float p = __expf(s - m);
            l += p;
            const float4* vr = reinterpret_cast<const float4*>(Vs[key]);
#pragma unroll
            for (int j = 0; j < 16; j++) {
                float4 vv = vr[j];
                o[4 * j + 0] += p * vv.x;
                o[4 * j + 1] += p * vv.y;
                o[4 * j + 2] += p * vv.z;
                o[4 * j + 3] += p * vv.w;
            }
        }
        __syncthreads();
    }

    const float inv_l = 1.0f / l;
    float* orow = &att[(size_t)(b * N + n) * D + hcol];
#pragma unroll
    for (int j = 0; j < HD / 4; j++) {
        float4 v;
        v.x = o[4 * j + 0] * inv_l;
        v.y = o[4 * j + 1] * inv_l;
        v.z = o[4 * j + 2] * inv_l;
        v.w = o[4 * j + 3] * inv_l;
        *reinterpret_cast<float4*>(&orow[j * 4]) = v;
    }
}

// ---------------------------------------------------------------------------
extern "C" void kernel_launch(void* const* d_in, const int* in_sizes, int n_in,
                              void* d_out, int out_size)
{
    const float* x     = (const float*)d_in[0];
    const float* Wqkv  = (const float*)d_in[1];
    const float* bqkv  = (const float*)d_in[2];
    const float* Wproj = (const float*)d_in[3];
    const float* bproj = (const float*)d_in[4];
    float* out = (float*)d_out;

    void* p;
    cudaGetSymbolAddress(&p, g_qkv);
    float* qkv = (float*)p;
    cudaGetSymbolAddress(&p, g_att);
    float* att = (float*)p;

    // 1) qkv = x @ Wqkv + bqkv   [8192, 3072]
    gemm_bias_kernel<<<dim3(3 * D / 64, BN / 64), 256>>>(x, Wqkv, bqkv, qkv, BN, 3 * D, D);
    // 2) attention -> att [8192, 1024]
    attn_kernel<<<dim3(N / 128, H, B), 128>>>(qkv, att);
    // 3) out = att @ Wproj + bproj  [8192, 1024]
    gemm_bias_kernel<<<dim3(D / 64, BN / 64), 256>>>(att, Wproj, bproj, out, BN, D, D);
}

// round 2
// speedup vs baseline: 1.6900x; 1.6900x over previous
#include <cuda_runtime.h>
#include <cuda_bf16.h>
#include <math.h>
#include <stdint.h>

// Problem constants
#define B 4
#define N 2048
#define D 1024
#define H 16
#define HD 64
#define BN (B * N)            // 8192 rows
#define SCALE 0.125f          // 1/sqrt(64)

// Scratch (device globals: no allocations allowed)
__device__ float g_qkv[BN * 3 * D];   // [8192, 3072]
__device__ float g_att[BN * D];       // [8192, 1024]

// ---------------------------------------------------------------------------
// tf32 helpers
// ---------------------------------------------------------------------------
__device__ __forceinline__ uint32_t f2tf(float x) {
    uint32_t r; asm("cvt.rna.tf32.f32 %0, %1;" : "=r"(r) : "f"(x)); return r;
}
__device__ __forceinline__ void split_tf(float x, uint32_t& h, uint32_t& l) {
    h = f2tf(x);
    float lo = x - __uint_as_float(h);
    l = f2tf(lo);
}
__device__ __forceinline__ void mma8(float* c, const uint32_t* a, const uint32_t* b) {
    asm volatile(
        "mma.sync.aligned.m16n8k8.row.col.f32.tf32.tf32.f32 "
        "{%0,%1,%2,%3}, {%4,%5,%6,%7}, {%8,%9}, {%0,%1,%2,%3};"
        : "+f"(c[0]), "+f"(c[1]), "+f"(c[2]), "+f"(c[3])
        : "r"(a[0]), "r"(a[1]), "r"(a[2]), "r"(a[3]), "r"(b[0]), "r"(b[1]));
}

// ---------------------------------------------------------------------------
// GEMM: C[M,Nn] = A[M,K] @ W[K,Nn] + bias  (3xTF32, fp32-accurate)
// 128x128 block tile, BK=16, 256 threads, 8 warps as 4(m) x 2(n), warp 32x64.
// smem: Ah/Al [2][16][136] (k-major), Bh/Bl [2][16][136]. Double buffered.
// ---------------------------------------------------------------------------
#define GBK 16
#define GSTR 136
#define GTILE (GBK * GSTR)    // 2176 u32

__global__ __launch_bounds__(256) void gemm3_tf32(
    const float* __restrict__ A, const float* __restrict__ W,
    const float* __restrict__ bias, float* __restrict__ C,
    int M, int Nn, int K)
{
    extern __shared__ uint32_t sm[];
    uint32_t* Ah = sm;                 // [2][GBK][GSTR]  As[k][m]
    uint32_t* Al = sm + 2 * GTILE;
    uint32_t* Bh = sm + 4 * GTILE;     // Bs[k][n]
    uint32_t* Bl = sm + 6 * GTILE;

    const int tid  = threadIdx.x;
    const int lane = tid & 31, warp = tid >> 5;
    const int g = lane >> 2, cq = lane & 3;
    const int wm = (warp >> 1) * 32, wn = (warp & 1) * 64;
    const int m0 = blockIdx.y * 128, n0 = blockIdx.x * 128;

    float acc[2][8][4];
#pragma unroll
    for (int mt = 0; mt < 2; mt++)
#pragma unroll
        for (int nt = 0; nt < 8; nt++)
#pragma unroll
            for (int k = 0; k < 4; k++) acc[mt][nt][k] = 0.0f;

    float4 ra[2], rb[2];

    auto ldg = [&](int k0) {
#pragma unroll
        for (int i = 0; i < 2; i++) {
            int f = tid + i * 256;
            int m = f >> 2, kq = f & 3;
            ra[i] = *(const float4*)&A[(size_t)(m0 + m) * K + k0 + kq * 4];
            int k = f >> 5, nq = f & 31;
            rb[i] = *(const float4*)&W[(size_t)(k0 + k) * Nn + n0 + nq * 4];
        }
    };
    auto sts = [&](int buf) {
#pragma unroll
        for (int i = 0; i < 2; i++) {
            int f = tid + i * 256;
            int m = f >> 2, kq = f & 3;
            float va[4] = {ra[i].x, ra[i].y, ra[i].z, ra[i].w};
#pragma unroll
            for (int j = 0; j < 4; j++) {
                uint32_t h, l; split_tf(va[j], h, l);
                Ah[buf * GTILE + (kq * 4 + j) * GSTR + m] = h;
                Al[buf * GTILE + (kq * 4 + j) * GSTR + m] = l;
            }
            int k = f >> 5, nq = f & 31;
            float vb[4] = {rb[i].x, rb[i].y, rb[i].z, rb[i].w};
#pragma unroll
            for (int j = 0; j < 4; j++) {
                uint32_t h, l; split_tf(vb[j], h, l);
                Bh[buf * GTILE + k * GSTR + nq * 4 + j] = h;
                Bl[buf * GTILE + k * GSTR + nq * 4 + j] = l;
            }
        }
    };
    auto compute = [&](int buf) {
#pragma unroll
        for (int kc = 0; kc < 2; kc++) {
            const uint32_t* pAh = &Ah[buf * GTILE + kc * 8 * GSTR];
            const uint32_t* pAl = &Al[buf * GTILE + kc * 8 * GSTR];
            uint32_t ah[2][4], al[2][4];
#pragma unroll
            for (int mt = 0; mt < 2; mt++) {
                int mb = wm + mt * 16;
                ah[mt][0] = pAh[cq * GSTR + mb + g];
                ah[mt][1] = pAh[cq * GSTR + mb + g + 8];
                ah[mt][2] = pAh[(cq + 4) * GSTR + mb + g];
                ah[mt][3] = pAh[(cq + 4) * GSTR + mb + g + 8];
                al[mt][0] = pAl[cq * GSTR + mb + g];
                al[mt][1] = pAl[cq * GSTR + mb + g + 8];
                al[mt][2] = pAl[(cq + 4) * GSTR + mb + g];
                al[mt][3] = pAl[(cq + 4) * GSTR + mb + g + 8];
            }
            const uint32_t* pBh = &Bh[buf * GTILE + kc * 8 * GSTR];
            const uint32_t* pBl = &Bl[buf * GTILE + kc * 8 * GSTR];
#pragma unroll
            for (int nt = 0; nt < 8; nt++) {
                int nb = wn + nt * 8 + g;
                uint32_t bh[2], bl[2];
                bh[0] = pBh[cq * GSTR + nb];
                bh[1] = pBh[(cq + 4) * GSTR + nb];
                bl[0] = pBl[cq * GSTR + nb];
                bl[1] = pBl[(cq + 4) * GSTR + nb];
#pragma unroll
                for (int mt = 0; mt < 2; mt++) {
                    mma8(acc[mt][nt], ah[mt], bh);
                    mma8(acc[mt][nt], al[mt], bh);
                    mma8(acc[mt][nt], ah[mt], bl);
                }
            }
        }
    };

    const int nit = K / GBK;
    ldg(0);
    sts(0);
    __syncthreads();
    for (int it = 0; it < nit; it++) {
        int buf = it & 1;
        if (it + 1 < nit) ldg((it + 1) * GBK);
        compute(buf);
        if (it + 1 < nit) { sts(buf ^ 1); __syncthreads(); }
    }

    // epilogue with bias
#pragma unroll
    for (int mt = 0; mt < 2; mt++) {
#pragma unroll
        for (int nt = 0; nt < 8; nt++) {
            int row = m0 + wm + mt * 16 + g;
            int col = n0 + wn + nt * 8 + 2 * cq;
            float b0 = bias[col], b1 = bias[col + 1];
            *(float2*)&C[(size_t)row * Nn + col] =
                make_float2(acc[mt][nt][0] + b0, acc[mt][nt][1] + b1);
            *(float2*)&C[(size_t)(row + 8) * Nn + col] =
                make_float2(acc[mt][nt][2] + b0, acc[mt][nt][3] + b1);
        }
    }
}

// ---------------------------------------------------------------------------
// Attention (3xTF32 flash): 128 queries/block, 64-key tiles, 8 warps,
// each warp owns 16 query rows (no cross-warp softmax reduce).
// smem (stride 68 -> conflict-free fragment reads):
//   Qh/Ql[128][68], Kh/Kl[64][68] (key-major), Vh/Vl[64][68] (d-major, i.e.
//   V transposed), Ph/Pl[128][68].
// ---------------------------------------------------------------------------
#define QS 68

__global__ __launch_bounds__(256) void attn_tf32(
    const float* __restrict__ qkv, float* __restrict__ att)
{
    extern __shared__ uint32_t sm[];
    uint32_t* Qh = sm;                    // 128*68 = 8704
    uint32_t* Ql = Qh + 8704;
    uint32_t* Kh = Ql + 8704;             // 64*68 = 4352
    uint32_t* Kl = Kh + 4352;
    uint32_t* Vh = Kl + 4352;             // [d][key]
    uint32_t* Vl = Vh + 4352;
    uint32_t* Ph = Vl + 4352;             // 128*68
    uint32_t* Pl = Ph + 8704;

    const int tid  = threadIdx.x;
    const int lane = tid & 31, warp = tid >> 5;
    const int g = lane >> 2, cq = lane & 3;
    const int b = blockIdx.z, h = blockIdx.y;
    const int q0 = blockIdx.x * 128;
    const int hcol = h * HD;
    const size_t base = (size_t)(b * N) * (3 * D);

    // stage Q (hi/lo)
#pragma unroll
    for (int i = 0; i < 8; i++) {
        int idx = tid + i * 256;
        int row = idx >> 4, dq = idx & 15;
        float4 v = *(const float4*)&qkv[base + (size_t)(q0 + row) * (3 * D) + hcol + dq * 4];
        float a[4] = {v.x, v.y, v.z, v.w};
#pragma unroll
        for (int j = 0; j < 4; j++) {
            uint32_t hh, ll; split_tf(a[j], hh, ll);
            Qh[row * QS + dq * 4 + j] = hh;
            Ql[row * QS + dq * 4 + j] = ll;
        }
    }

    float m0v = -1e30f, m1v = -1e30f, l0 = 0.0f, l1 = 0.0f;
    float o[8][4];
#pragma unroll
    for (int nt = 0; nt < 8; nt++)
#pragma unroll
        for (int k = 0; k < 4; k++) o[nt][k] = 0.0f;

    const int rb_ = warp * 16;

    for (int kb = 0; kb < N / 64; kb++) {
        __syncthreads();   // Q staged (iter 0); K/V free to overwrite (iter > 0)

        // stage K (key-major) and V (transposed, d-major)
#pragma unroll
        for (int i = 0; i < 4; i++) {
            int idx = tid + i * 256;
            int key = idx >> 4, dq = idx & 15;
            size_t grow = base + (size_t)(kb * 64 + key) * (3 * D) + hcol + dq * 4;
            float4 kv = *(const float4*)&qkv[grow + D];
            float4 vv = *(const float4*)&qkv[grow + 2 * D];
            float ka[4] = {kv.x, kv.y, kv.z, kv.w};
            float va[4] = {vv.x, vv.y, vv.z, vv.w};
#pragma unroll
            for (int j = 0; j < 4; j++) {
                uint32_t hh, ll;
                split_tf(ka[j], hh, ll);
                Kh[key * QS + dq * 4 + j] = hh;
                Kl[key * QS + dq * 4 + j] = ll;
                split_tf(va[j], hh, ll);
                Vh[(dq * 4 + j) * QS + key] = hh;
                Vl[(dq * 4 + j) * QS + key] = ll;
            }
        }
        __syncthreads();

        // S = Q @ K^T   (warp: 16 q rows x 64 keys, K-dim = 64)
        float s[8][4];
#pragma unroll
        for (int nt = 0; nt < 8; nt++)
#pragma unroll
            for (int k = 0; k < 4; k++) s[nt][k] = 0.0f;

#pragma unroll
        for (int kc = 0; kc < 8; kc++) {
            uint32_t ah[4], al[4];
            ah[0] = Qh[(rb_ + g) * QS + kc * 8 + cq];
            ah[1] = Qh[(rb_ + g + 8) * QS + kc * 8 + cq];
            ah[2] = Qh[(rb_ + g) * QS + kc * 8 + cq + 4];
            ah[3] = Qh[(rb_ + g + 8) * QS + kc * 8 + cq + 4];
            al[0] = Ql[(rb_ + g) * QS + kc * 8 + cq];
            al[1] = Ql[(rb_ + g + 8) * QS + kc * 8 + cq];
            al[2] = Ql[(rb_ + g) * QS + kc * 8 + cq + 4];
            al[3] = Ql[(rb_ + g + 8) * QS + kc * 8 + cq + 4];
#pragma unroll
            for (int nt = 0; nt < 8; nt++) {
                uint32_t bh[2], bl[2];
                bh[0] = Kh[(nt * 8 + g) * QS + kc * 8 + cq];
                bh[1] = Kh[(nt * 8 + g) * QS + kc * 8 + cq + 4];
                bl[0] = Kl[(nt * 8 + g) * QS + kc * 8 + cq];
                bl[1] = Kl[(nt * 8 + g) * QS + kc * 8 + cq + 4];
                mma8(s[nt], ah, bh);
                mma8(s[nt], al, bh);
                mma8(s[nt], ah, bl);
            }
        }

        // online softmax (rows g and g+8 of this warp's 16)
        float rm0 = -1e30f, rm1 = -1e30f;
#pragma unroll
        for (int nt = 0; nt < 8; nt++) {
            s[nt][0] *= SCALE; s[nt][1] *= SCALE; s[nt][2] *= SCALE; s[nt][3] *= SCALE;
            rm0 = fmaxf(rm0, fmaxf(s[nt][0], s[nt][1]));
            rm1 = fmaxf(rm1, fmaxf(s[nt][2], s[nt][3]));
        }
        rm0 = fmaxf(rm0, __shfl_xor_sync(0xffffffff, rm0, 1));
        rm0 = fmaxf(rm0, __shfl_xor_sync(0xffffffff, rm0, 2));
        rm1 = fmaxf(rm1, __shfl_xor_sync(0xffffffff, rm1, 1));
        rm1 = fmaxf(rm1, __shfl_xor_sync(0xffffffff, rm1, 2));

        float nm0 = fmaxf(m0v, rm0), nm1 = fmaxf(m1v, rm1);
        float a0 = __expf(m0v - nm0), a1 = __expf(m1v - nm1);
        m0v = nm0; m1v = nm1;

        float rs0 = 0.0f, rs1 = 0.0f;
#pragma unroll
        for (int nt = 0; nt < 8; nt++) {
            float p0 = __expf(s[nt][0] - nm0);
            float p1 = __expf(s[nt][1] - nm0);
            float p2 = __expf(s[nt][2] - nm1);
            float p3 = __expf(s[nt][3] - nm1);
            rs0 += p0 + p1;
            rs1 += p2 + p3;
            int c0 = nt * 8 + 2 * cq;
            uint32_t hh, ll;
            split_tf(p0, hh, ll); Ph[(rb_ + g) * QS + c0] = hh;     Pl[(rb_ + g) * QS + c0] = ll;
            split_tf(p1, hh, ll); Ph[(rb_ + g) * QS + c0 + 1] = hh; Pl[(rb_ + g) * QS + c0 + 1] = ll;
            split_tf(p2, hh, ll); Ph[(rb_ + g + 8) * QS + c0] = hh;     Pl[(rb_ + g + 8) * QS + c0] = ll;
            split_tf(p3, hh, ll); Ph[(rb_ + g + 8) * QS + c0 + 1] = hh; Pl[(rb_ + g + 8) * QS + c0 + 1] = ll;
        }
        rs0 += __shfl_xor_sync(0xffffffff, rs0, 1);
        rs0 += __shfl_xor_sync(0xffffffff, rs0, 2);
        rs1 += __shfl_xor_sync(0xffffffff, rs1, 1);
        rs1 += __shfl_xor_sync(0xffffffff, rs1, 2);
        l0 = l0 * a0 + rs0;
        l1 = l1 * a1 + rs1;
#pragma unroll
        for (int nt = 0; nt < 8; nt++) {
            o[nt][0] *= a0; o[nt][1] *= a0; o[nt][2] *= a1; o[nt][3] *= a1;
        }
        __syncwarp();

        // O += P @ V   (warp: 16 q rows x 64 d, K-dim = 64 keys)
#pragma unroll
        for (int kc = 0; kc < 8; kc++) {
            uint32_t ah[4], al[4];
            ah[0] = Ph[(rb_ + g) * QS + kc * 8 + cq];
            ah[1] = Ph[(rb_ + g + 8) * QS + kc * 8 + cq];
            ah[2] = Ph[(rb_ + g) * QS + kc * 8 + cq + 4];
            ah[3] = Ph[(rb_ + g + 8) * QS + kc * 8 + cq + 4];
            al[0] = Pl[(rb_ + g) * QS + kc * 8 + cq];
            al[1] = Pl[(rb_ + g + 8) * QS + kc * 8 + cq];
            al[2] = Pl[(rb_ + g) * QS + kc * 8 + cq + 4];
            al[3] = Pl[(rb_ + g + 8) * QS + kc * 8 + cq + 4];
#pragma unroll
            for (int nt = 0; nt < 8; nt++) {
                uint32_t bh[2], bl[2];
                bh[0] = Vh[(nt * 8 + g) * QS + kc * 8 + cq];
                bh[1] = Vh[(nt * 8 + g) * QS + kc * 8 + cq + 4];
                bl[0] = Vl[(nt * 8 + g) * QS + kc * 8 + cq];
                bl[1] = Vl[(nt * 8 + g) * QS + kc * 8 + cq + 4];
                mma8(o[nt], ah, bh);
                mma8(o[nt], al, bh);
                mma8(o[nt], ah, bl);
            }
        }
    }

    // normalize + write to att (head-concat layout)
    float inv0 = 1.0f / l0, inv1 = 1.0f / l1;
#pragma unroll
    for (int nt = 0; nt < 8; nt++) {
        int col = hcol + nt * 8 + 2 * cq;
        size_t r0o = (size_t)(b * N + q0 + rb_ + g) * D + col;
        size_t r1o = (size_t)(b * N + q0 + rb_ + g + 8) * D + col;
        *(float2*)&att[r0o] = make_float2(o[nt][0] * inv0, o[nt][1] * inv0);
        *(float2*)&att[r1o] = make_float2(o[nt][2] * inv1, o[nt][3] * inv1);
    }
}

// ---------------------------------------------------------------------------
extern "C" void kernel_launch(void* const* d_in, const int* in_sizes, int n_in,
                              void* d_out, int out_size)
{
    const float* x     = (const float*)d_in[0];
    const float* Wqkv  = (const float*)d_in[1];
    const float* bqkv  = (const float*)d_in[2];
    const float* Wproj = (const float*)d_in[3];
    const float* bproj = (const float*)d_in[4];
    float* out = (float*)d_out;

    void* p;
    cudaGetSymbolAddress(&p, g_qkv);
    float* qkv = (float*)p;
    cudaGetSymbolAddress(&p, g_att);
    float* att = (float*)p;

    const int gemm_smem = 8 * GTILE * 4;       // 69632 B
    const int attn_smem = 52224 * 4;           // 208896 B
    cudaFuncSetAttribute(gemm3_tf32, cudaFuncAttributeMaxDynamicSharedMemorySize, gemm_smem);
    cudaFuncSetAttribute(attn_tf32, cudaFuncAttributeMaxDynamicSharedMemorySize, attn_smem);

    // 1) qkv = x @ Wqkv + bqkv     [8192, 3072]
    gemm3_tf32<<<dim3(3 * D / 128, BN / 128), 256, gemm_smem>>>(x, Wqkv, bqkv, qkv, BN, 3 * D, D);
    // 2) attention -> att          [8192, 1024]
    attn_tf32<<<dim3(N / 128, H, B), 256, attn_smem>>>(qkv, att);
    // 3) out = att @ Wproj + bproj [8192, 1024]
    gemm3_tf32<<<dim3(D / 128, BN / 128), 256, gemm_smem>>>(att, Wproj, bproj, out, BN, D, D);
}

// round 4
// speedup vs baseline: 3.2660x; 1.9325x over previous
#include <cuda_runtime.h>
#include <cuda_bf16.h>
#include <math.h>
#include <stdint.h>

// Problem constants
#define B 4
#define N 2048
#define D 1024
#define H 16
#define HD 64
#define BN (B * N)            // 8192 rows
#define SCALE 0.125f          // 1/sqrt(64)

// Scratch (device globals: no allocations allowed)
__device__ float g_qkv[BN * 3 * D];   // [8192, 3072]
__device__ float g_att[BN * D];       // [8192, 1024]

// ---------------------------------------------------------------------------
// bf16 split helpers: x = hi + lo, hi/lo bf16; packs (x0,x1) pairs into u32.
// ---------------------------------------------------------------------------
__device__ __forceinline__ void split2(float x0, float x1, uint32_t& h, uint32_t& l) {
    __nv_bfloat162 hh = __floats2bfloat162_rn(x0, x1);
    float r0 = x0 - __bfloat162float(hh.x);
    float r1 = x1 - __bfloat162float(hh.y);
    __nv_bfloat162 ll = __floats2bfloat162_rn(r0, r1);
    h = *reinterpret_cast<uint32_t*>(&hh);
    l = *reinterpret_cast<uint32_t*>(&ll);
}

// m16n8k16 bf16 mma, fp32 accumulate
__device__ __forceinline__ void mma16(float* c, const uint32_t* a, const uint32_t* b) {
    asm volatile(
        "mma.sync.aligned.m16n8k16.row.col.f32.bf16.bf16.f32 "
        "{%0,%1,%2,%3}, {%4,%5,%6,%7}, {%8,%9}, {%0,%1,%2,%3};"
        : "+f"(c[0]), "+f"(c[1]), "+f"(c[2]), "+f"(c[3])
        : "r"(a[0]), "r"(a[1]), "r"(a[2]), "r"(a[3]), "r"(b[0]), "r"(b[1]));
}

// ---------------------------------------------------------------------------
// GEMM: C[M,Nn] = A[M,K] @ W[K,Nn] + bias   (3xBF16, fp32-accurate)
// 128x128 block tile, BK=32 (16 k-pairs), 256 threads, 8 warps 4(m)x2(n),
// warp tile 32x64. Single-buffered smem, 2 CTAs/SM for overlap.
// A tiles [m][kpair] stride 20 (banks 20g+cq: conflict-free).
// B tiles [kpair][n] stride 136 (banks 8cq+g: conflict-free).
// ---------------------------------------------------------------------------
#define ASTR 20
#define BSTR 136

__global__ __launch_bounds__(256, 2) void gemm_bf16x3(
    const float* __restrict__ A, const float* __restrict__ W,
    const float* __restrict__ bias, float* __restrict__ C,
    int M, int Nn, int K)
{
    __shared__ uint32_t sm[9472];
    uint32_t* Ah = sm;             // 128*20 = 2560
    uint32_t* Al = sm + 2560;
    uint32_t* Bh = sm + 5120;      // 16*136 = 2176
    uint32_t* Bl = sm + 7296;

    const int tid = threadIdx.x;
    const int lane = tid & 31, warp = tid >> 5;
    const int g = lane >> 2, cq = lane & 3;
    const int wm = (warp >> 1) * 32, wn = (warp & 1) * 64;
    const int m0 = blockIdx.y * 128, n0 = blockIdx.x * 128;

    float acc[2][8][4];
#pragma unroll
    for (int mt = 0; mt < 2; mt++)
#pragma unroll
        for (int nt = 0; nt < 8; nt++)
#pragma unroll
            for (int k = 0; k < 4; k++) acc[mt][nt][k] = 0.0f;

    const int nchunks = K / 32;
    for (int chunk = 0; chunk < nchunks; chunk++) {
        const int k0 = chunk * 32;
        __syncthreads();   // previous compute done (WAR)

        // stage A [128 m][32 k] -> pairs
#pragma unroll
        for (int i = 0; i < 4; i++) {
            int f = tid + i * 256;
            int m = f >> 3, kq = f & 7;
            float4 v = *(const float4*)&A[(size_t)(m0 + m) * K + k0 + kq * 4];
            uint32_t h0, l0, h1, l1;
            split2(v.x, v.y, h0, l0);
            split2(v.z, v.w, h1, l1);
            *(uint2*)&Ah[m * ASTR + 2 * kq] = make_uint2(h0, h1);
            *(uint2*)&Al[m * ASTR + 2 * kq] = make_uint2(l0, l1);
        }
        // stage B: W rows k0+2kp, k0+2kp+1 paired elementwise
#pragma unroll
        for (int i = 0; i < 2; i++) {
            int f = tid + i * 256;
            int kp = f >> 5, n4 = f & 31;
            const float* w0 = &W[(size_t)(k0 + 2 * kp) * Nn + n0 + n4 * 4];
            const float* w1 = &W[(size_t)(k0 + 2 * kp + 1) * Nn + n0 + n4 * 4];
            float4 a4 = *(const float4*)w0;
            float4 b4 = *(const float4*)w1;
            uint32_t h[4], l[4];
            split2(a4.x, b4.x, h[0], l[0]);
            split2(a4.y, b4.y, h[1], l[1]);
            split2(a4.z, b4.z, h[2], l[2]);
            split2(a4.w, b4.w, h[3], l[3]);
            *(uint4*)&Bh[kp * BSTR + n4 * 4] = make_uint4(h[0], h[1], h[2], h[3]);
            *(uint4*)&Bl[kp * BSTR + n4 * 4] = make_uint4(l[0], l[1], l[2], l[3]);
        }
        __syncthreads();

        // compute: 2 k16 steps
#pragma unroll
        for (int kc = 0; kc < 2; kc++) {
            uint32_t ah[2][4], al[2][4];
#pragma unroll
            for (int mt = 0; mt < 2; mt++) {
                int r0 = (wm + mt * 16 + g) * ASTR + kc * 8;
                int r1 = (wm + mt * 16 + g + 8) * ASTR + kc * 8;
                ah[mt][0] = Ah[r0 + cq];
                ah[mt][1] = Ah[r1 + cq];
                ah[mt][2] = Ah[r0 + cq + 4];
                ah[mt][3] = Ah[r1 + cq + 4];
                al[mt][0] = Al[r0 + cq];
                al[mt][1] = Al[r1 + cq];
                al[mt][2] = Al[r0 + cq + 4];
                al[mt][3] = Al[r1 + cq + 4];
            }
#pragma unroll
            for (int nt = 0; nt < 8; nt++) {
                int nb = wn + nt * 8 + g;
                uint32_t bh[2], bl[2];
                bh[0] = Bh[(kc * 8 + cq) * BSTR + nb];
                bh[1] = Bh[(kc * 8 + cq + 4) * BSTR + nb];
                bl[0] = Bl[(kc * 8 + cq) * BSTR + nb];
                bl[1] = Bl[(kc * 8 + cq + 4) * BSTR + nb];
#pragma unroll
                for (int mt = 0; mt < 2; mt++) {
                    mma16(acc[mt][nt], ah[mt], bh);
                    mma16(acc[mt][nt], al[mt], bh);
                    mma16(acc[mt][nt], ah[mt], bl);
                }
            }
        }
    }

    // epilogue with bias
#pragma unroll
    for (int mt = 0; mt < 2; mt++) {
#pragma unroll
        for (int nt = 0; nt < 8; nt++) {
            int row = m0 + wm + mt * 16 + g;
            int col = n0 + wn + nt * 8 + 2 * cq;
            float b0 = bias[col], b1 = bias[col + 1];
            *(float2*)&C[(size_t)row * Nn + col] =
                make_float2(acc[mt][nt][0] + b0, acc[mt][nt][1] + b1);
            *(float2*)&C[(size_t)(row + 8) * Nn + col] =
                make_float2(acc[mt][nt][2] + b0, acc[mt][nt][3] + b1);
        }
    }
}

// ---------------------------------------------------------------------------
// Attention (3xBF16 flash): 128 queries/block, 64-key tiles, 8 warps,
// each warp owns 16 query rows. All tiles pair-packed u32, stride 36
// (banks 4g+cq: conflict-free fragment loads).
//   Qh/Ql[128][36] (d-pairs), Kh/Kl[64][36] (d-pairs),
//   Vh/Vl[64][36] (V^T: row d, key-pairs), Ph/Pl[128][36] (key-pairs).
// ---------------------------------------------------------------------------
#define QS2 36

__global__ __launch_bounds__(256, 2) void attn_bf16x3(
    const float* __restrict__ qkv, float* __restrict__ att)
{
    extern __shared__ uint32_t sm[];
    uint32_t* Qh = sm;                    // 128*36 = 4608
    uint32_t* Ql = Qh + 4608;
    uint32_t* Kh = Ql + 4608;             // 64*36 = 2304
    uint32_t* Kl = Kh + 2304;
    uint32_t* Vh = Kl + 2304;
    uint32_t* Vl = Vh + 2304;
    uint32_t* Ph = Vl + 2304;             // 128*36
    uint32_t* Pl = Ph + 4608;
    // total 27648 u32 = 110592 B

    const int tid  = threadIdx.x;
    const int lane = tid & 31, warp = tid >> 5;
    const int g = lane >> 2, cq = lane & 3;
    const int b = blockIdx.z, h = blockIdx.y;
    const int q0 = blockIdx.x * 128;
    const int hcol = h * HD;
    const size_t base = (size_t)(b * N) * (3 * D);

    // stage Q (pairs along d)
#pragma unroll
    for (int i = 0; i < 8; i++) {
        int idx = tid + i * 256;
        int row = idx >> 4, dq = idx & 15;
        float4 v = *(const float4*)&qkv[base + (size_t)(q0 + row) * (3 * D) + hcol + dq * 4];
        uint32_t h0, l0, h1, l1;
        split2(v.x, v.y, h0, l0);
        split2(v.z, v.w, h1, l1);
        *(uint2*)&Qh[row * QS2 + 2 * dq] = make_uint2(h0, h1);
        *(uint2*)&Ql[row * QS2 + 2 * dq] = make_uint2(l0, l1);
    }

    float m0v = -1e30f, m1v = -1e30f, l0s = 0.0f, l1s = 0.0f;
    float o[8][4];
#pragma unroll
    for (int nt = 0; nt < 8; nt++)
#pragma unroll
        for (int k = 0; k < 4; k++) o[nt][k] = 0.0f;

    const int rb_ = warp * 16;

    for (int kb = 0; kb < N / 64; kb++) {
        __syncthreads();   // Q staged (iter 0); K/V free to overwrite (iter > 0)

        // stage K (pairs along d)
#pragma unroll
        for (int i = 0; i < 4; i++) {
            int idx = tid + i * 256;
            int key = idx >> 4, dq = idx & 15;
            size_t grow = base + (size_t)(kb * 64 + key) * (3 * D) + hcol + dq * 4;
            float4 v = *(const float4*)&qkv[grow + D];
            uint32_t h0, l0, h1, l1;
            split2(v.x, v.y, h0, l0);
            split2(v.z, v.w, h1, l1);
            *(uint2*)&Kh[key * QS2 + 2 * dq] = make_uint2(h0, h1);
            *(uint2*)&Kl[key * QS2 + 2 * dq] = make_uint2(l0, l1);
        }
        // stage V transposed: Vh[d][keypair], pair = (key 2kp, 2kp+1)
#pragma unroll
        for (int i = 0; i < 2; i++) {
            int idx = tid + i * 256;
            int kp = idx >> 4, dq = idx & 15;
            size_t g0r = base + (size_t)(kb * 64 + 2 * kp) * (3 * D) + 2 * D + hcol + dq * 4;
            size_t g1r = g0r + 3 * D;
            float4 v0 = *(const float4*)&qkv[g0r];
            float4 v1 = *(const float4*)&qkv[g1r];
            float a0[4] = {v0.x, v0.y, v0.z, v0.w};
            float a1[4] = {v1.x, v1.y, v1.z, v1.w};
#pragma unroll
            for (int j = 0; j < 4; j++) {
                uint32_t hh, ll;
                split2(a0[j], a1[j], hh, ll);
                Vh[(dq * 4 + j) * QS2 + kp] = hh;
                Vl[(dq * 4 + j) * QS2 + kp] = ll;
            }
        }
        __syncthreads();

        // S = Q @ K^T  (warp: 16 q rows x 64 keys, d = 64 -> 4 k16 steps)
        float s[8][4];
#pragma unroll
        for (int nt = 0; nt < 8; nt++)
#pragma unroll
            for (int k = 0; k < 4; k++) s[nt][k] = 0.0f;

#pragma unroll
        for (int kc = 0; kc < 4; kc++) {
            uint32_t ah[4], al[4];
            int r0 = (rb_ + g) * QS2 + kc * 8;
            int r1 = (rb_ + g + 8) * QS2 + kc * 8;
            ah[0] = Qh[r0 + cq]; ah[1] = Qh[r1 + cq];
            ah[2] = Qh[r0 + cq + 4]; ah[3] = Qh[r1 + cq + 4];
            al[0] = Ql[r0 + cq]; al[1] = Ql[r1 + cq];
            al[2] = Ql[r0 + cq + 4]; al[3] = Ql[r1 + cq + 4];
#pragma unroll
            for (int nt = 0; nt < 8; nt++) {
                int kr = (nt * 8 + g) * QS2 + kc * 8;
                uint32_t bh[2], bl[2];
                bh[0] = Kh[kr + cq]; bh[1] = Kh[kr + cq + 4];
                bl[0] = Kl[kr + cq]; bl[1] = Kl[kr + cq + 4];
                mma16(s[nt], ah, bh);
                mma16(s[nt], al, bh);
                mma16(s[nt], ah, bl);
            }
        }

        // online softmax (rows g, g+8)
        float rm0 = -1e30f, rm1 = -1e30f;
#pragma unroll
        for (int nt = 0; nt < 8; nt++) {
            s[nt][0] *= SCALE; s[nt][1] *= SCALE; s[nt][2] *= SCALE; s[nt][3] *= SCALE;
            rm0 = fmaxf(rm0, fmaxf(s[nt][0], s[nt][1]));
            rm1 = fmaxf(rm1, fmaxf(s[nt][2], s[nt][3]));
        }
        rm0 = fmaxf(rm0, __shfl_xor_sync(0xffffffff, rm0, 1));
        rm0 = fmaxf(rm0, __shfl_xor_sync(0xffffffff, rm0, 2));
        rm1 = fmaxf(rm1, __shfl_xor_sync(0xffffffff, rm1, 1));
        rm1 = fmaxf(rm1, __shfl_xor_sync(0xffffffff, rm1, 2));

        float nm0 = fmaxf(m0v, rm0), nm1 = fmaxf(m1v, rm1);
        float a0 = __expf(m0v - nm0), a1 = __expf(m1v - nm1);
        m0v = nm0; m1v = nm1;

        float rs0 = 0.0f, rs1 = 0.0f;
#pragma unroll
        for (int nt = 0; nt < 8; nt++) {
            float p0 = __expf(s[nt][0] - nm0);
            float p1 = __expf(s[nt][1] - nm0);
            float p2 = __expf(s[nt][2] - nm1);
            float p3 = __expf(s[nt][3] - nm1);
            rs0 += p0 + p1;
            rs1 += p2 + p3;
            uint32_t hh, ll;
            split2(p0, p1, hh, ll);
            Ph[(rb_ + g) * QS2 + nt * 4 + cq] = hh;
            Pl[(rb_ + g) * QS2 + nt * 4 + cq] = ll;
            split2(p2, p3, hh, ll);
            Ph[(rb_ + g + 8) * QS2 + nt * 4 + cq] = hh;
            Pl[(rb_ + g + 8) * QS2 + nt * 4 + cq] = ll;
        }
        rs0 += __shfl_xor_sync(0xffffffff, rs0, 1);
        rs0 += __shfl_xor_sync(0xffffffff, rs0, 2);
        rs1 += __shfl_xor_sync(0xffffffff, rs1, 1);
        rs1 += __shfl_xor_sync(0xffffffff, rs1, 2);
        l0s = l0s * a0 + rs0;
        l1s = l1s * a1 + rs1;
#pragma unroll
        for (int nt = 0; nt < 8; nt++) {
            o[nt][0] *= a0; o[nt][1] *= a0; o[nt][2] *= a1; o[nt][3] *= a1;
        }
        __syncwarp();

        // O += P @ V  (warp: 16 q rows x 64 d, keys = 64 -> 4 k16 steps)
#pragma unroll
        for (int kc = 0; kc < 4; kc++) {
            uint32_t ah[4], al[4];
            int r0 = (rb_ + g) * QS2 + kc * 8;
            int r1 = (rb_ + g + 8) * QS2 + kc * 8;
            ah[0] = Ph[r0 + cq]; ah[1] = Ph[r1 + cq];
            ah[2] = Ph[r0 + cq + 4]; ah[3] = Ph[r1 + cq + 4];
            al[0] = Pl[r0 + cq]; al[1] = Pl[r1 + cq];
            al[2] = Pl[r0 + cq + 4]; al[3] = Pl[r1 + cq + 4];
#pragma unroll
            for (int nt = 0; nt < 8; nt++) {
                int vr = (nt * 8 + g) * QS2 + kc * 8;
                uint32_t bh[2], bl[2];
                bh[0] = Vh[vr + cq]; bh[1] = Vh[vr + cq + 4];
                bl[0] = Vl[vr + cq]; bl[1] = Vl[vr + cq + 4];
                mma16(o[nt], ah, bh);
                mma16(o[nt], al, bh);
                mma16(o[nt], ah, bl);
            }
        }
    }

    // normalize + write
    float inv0 = 1.0f / l0s, inv1 = 1.0f / l1s;
#pragma unroll
    for (int nt = 0; nt < 8; nt++) {
        int col = hcol + nt * 8 + 2 * cq;
        size_t r0o = (size_t)(b * N + q0 + rb_ + g) * D + col;
        size_t r1o = (size_t)(b * N + q0 + rb_ + g + 8) * D + col;
        *(float2*)&att[r0o] = make_float2(o[nt][0] * inv0, o[nt][1] * inv0);
        *(float2*)&att[r1o] = make_float2(o[nt][2] * inv1, o[nt][3] * inv1);
    }
}

// ---------------------------------------------------------------------------
extern "C" void kernel_launch(void* const* d_in, const int* in_sizes, int n_in,
                              void* d_out, int out_size)
{
    const float* x     = (const float*)d_in[0];
    const float* Wqkv  = (const float*)d_in[1];
    const float* bqkv  = (const float*)d_in[2];
    const float* Wproj = (const float*)d_in[3];
    const float* bproj = (const float*)d_in[4];
    float* out = (float*)d_out;

    void* p;
    cudaGetSymbolAddress(&p, g_qkv);
    float* qkv = (float*)p;
    cudaGetSymbolAddress(&p, g_att);
    float* att = (float*)p;

    const int attn_smem = 27648 * 4;   // 110592 B
    cudaFuncSetAttribute(attn_bf16x3, cudaFuncAttributeMaxDynamicSharedMemorySize, attn_smem);

    // 1) qkv = x @ Wqkv + bqkv     [8192, 3072]
    gemm_bf16x3<<<dim3(3 * D / 128, BN / 128), 256>>>(x, Wqkv, bqkv, qkv, BN, 3 * D, D);
    // 2) attention -> att          [8192, 1024]
    attn_bf16x3<<<dim3(N / 128, H, B), 256, attn_smem>>>(qkv, att);
    // 3) out = att @ Wproj + bproj [8192, 1024]
    gemm_bf16x3<<<dim3(D / 128, BN / 128), 256>>>(att, Wproj, bproj, out, BN, D, D);
}

// round 5
// speedup vs baseline: 3.5568x; 1.0890x over previous
#include <cuda_runtime.h>
#include <cuda_bf16.h>
#include <math.h>
#include <stdint.h>

// Problem constants
#define B 4
#define N 2048
#define D 1024
#define H 16
#define HD 64
#define BN (B * N)            // 8192
#define SCALE 0.125f
#define KW 512                // D/2 words per row (k-pairs)

// Scratch (device globals; all u32 = packed bf16x2 hi/lo pairs)
__device__ uint32_t g_xh[BN * 512],      g_xl[BN * 512];       // x split, d-pairs
__device__ uint32_t g_wqkvh[3072 * 512], g_wqkvl[3072 * 512];  // Wqkv^T [n][kpair]
__device__ uint32_t g_wprojh[1024 * 512], g_wprojl[1024 * 512];// Wproj^T [n][kpair]
__device__ uint32_t g_qkvh[BN * 1536],   g_qkvl[BN * 1536];    // qkv split, col-pairs
__device__ uint32_t g_atth[BN * 512],    g_attl[BN * 512];     // att split, d-pairs
__device__ uint32_t g_vth[64 * 64 * 1024], g_vtl[64 * 64 * 1024]; // V^T [bh][d][keypair]

// ---------------------------------------------------------------------------
// helpers
// ---------------------------------------------------------------------------
__device__ __forceinline__ void split2(float x0, float x1, uint32_t& h, uint32_t& l) {
    __nv_bfloat162 hh = __floats2bfloat162_rn(x0, x1);
    float r0 = x0 - __bfloat162float(hh.x);
    float r1 = x1 - __bfloat162float(hh.y);
    __nv_bfloat162 ll = __floats2bfloat162_rn(r0, r1);
    h = *reinterpret_cast<uint32_t*>(&hh);
    l = *reinterpret_cast<uint32_t*>(&ll);
}
__device__ __forceinline__ void mma16(float* c, const uint32_t* a, const uint32_t* b) {
    asm volatile(
        "mma.sync.aligned.m16n8k16.row.col.f32.bf16.bf16.f32 "
        "{%0,%1,%2,%3}, {%4,%5,%6,%7}, {%8,%9}, {%0,%1,%2,%3};"
        : "+f"(c[0]), "+f"(c[1]), "+f"(c[2]), "+f"(c[3])
        : "r"(a[0]), "r"(a[1]), "r"(a[2]), "r"(a[3]), "r"(b[0]), "r"(b[1]));
}
__device__ __forceinline__ uint32_t smem_u32(const void* p) {
    uint32_t a;
    asm("{ .reg .u64 t; cvta.to.shared.u64 t, %1; cvt.u32.u64 %0, t; }" : "=r"(a) : "l"(p));
    return a;
}
#define CP_ASYNC16(dst, src) \
    asm volatile("cp.async.cg.shared.global [%0], [%1], 16;" :: "r"(dst), "l"(src))
#define CP_COMMIT() asm volatile("cp.async.commit_group;" ::: "memory")
#define CP_WAIT(n)  asm volatile("cp.async.wait_group %0;" :: "n"(n) : "memory")

// ---------------------------------------------------------------------------
// split_x: x fp32 -> hi/lo bf16 pairs (d-pairs).  1 float4 -> 2 words / thread.
// ---------------------------------------------------------------------------
__global__ void split_x_k(const float* __restrict__ x,
                          uint32_t* __restrict__ xh, uint32_t* __restrict__ xl)
{
    int i = blockIdx.x * blockDim.x + threadIdx.x;   // float4 index
    float4 v = ((const float4*)x)[i];
    uint32_t h0, l0, h1, l1;
    split2(v.x, v.y, h0, l0);
    split2(v.z, v.w, h1, l1);
    ((uint2*)xh)[i] = make_uint2(h0, h1);
    ((uint2*)xl)[i] = make_uint2(l0, l1);
}

// ---------------------------------------------------------------------------
// wsplit: W[K][Nn] fp32 -> W^T split [n][kpair].  64x64 tiles via smem.
// ---------------------------------------------------------------------------
__global__ __launch_bounds__(256) void wsplit_k(
    const float* __restrict__ W, uint32_t* __restrict__ Wth, uint32_t* __restrict__ Wtl,
    int K, int Nn)
{
    __shared__ float sw[64 * 68];
    const int tid = threadIdx.x;
    const int k0 = blockIdx.y * 64, n0 = blockIdx.x * 64;
#pragma unroll
    for (int i = 0; i < 4; i++) {
        int f = tid + i * 256;
        int k = f >> 4, nq = f & 15;
        float4 v = *(const float4*)&W[(size_t)(k0 + k) * Nn + n0 + nq * 4];
        *(float4*)&sw[k * 68 + nq * 4] = v;
    }
    __syncthreads();
    const int n = tid >> 2, kq = tid & 3;
    uint32_t hb[8], lb[8];
#pragma unroll
    for (int j = 0; j < 8; j++) {
        int kp = kq * 8 + j;
        split2(sw[(2 * kp) * 68 + n], sw[(2 * kp + 1) * 68 + n], hb[j], lb[j]);
    }
    size_t o = (size_t)(n0 + n) * (K / 2) + k0 / 2 + kq * 8;
    *(uint4*)&Wth[o]     = make_uint4(hb[0], hb[1], hb[2], hb[3]);
    *(uint4*)&Wth[o + 4] = make_uint4(hb[4], hb[5], hb[6], hb[7]);
    *(uint4*)&Wtl[o]     = make_uint4(lb[0], lb[1], lb[2], lb[3]);
    *(uint4*)&Wtl[o + 4] = make_uint4(lb[4], lb[5], lb[6], lb[7]);
}

// ---------------------------------------------------------------------------
// vtrans: qkv split (v section, d-pairs) -> V^T split [bh][d][keypair]
// block = (kb: 64 keys) x (bh). smem transpose, byte_perm repack.
// ---------------------------------------------------------------------------
__global__ __launch_bounds__(256) void vtrans_k(
    const uint32_t* __restrict__ qh, const uint32_t* __restrict__ ql,
    uint32_t* __restrict__ vth, uint32_t* __restrict__ vtl)
{
    __shared__ uint32_t sc[2][32 * 66];   // [hi/lo][dp][key], stride 66
    const int tid = threadIdx.x;
    const int kb = blockIdx.x, bh = blockIdx.y;
    const int b = bh >> 4, h = bh & 15;
#pragma unroll
    for (int i = 0; i < 2; i++) {
        int f = tid + i * 256;
        int key = f >> 3, q = (f & 7) * 4;
        size_t src = (size_t)(b * 2048 + kb * 64 + key) * 1536 + 1024 + h * 32 + q;
        uint4 vh = *(const uint4*)&qh[src];
        uint4 vl = *(const uint4*)&ql[src];
        sc[0][(q + 0) * 66 + key] = vh.x; sc[0][(q + 1) * 66 + key] = vh.y;
        sc[0][(q + 2) * 66 + key] = vh.z; sc[0][(q + 3) * 66 + key] = vh.w;
        sc[1][(q + 0) * 66 + key] = vl.x; sc[1][(q + 1) * 66 + key] = vl.y;
        sc[1][(q + 2) * 66 + key] = vl.z; sc[1][(q + 3) * 66 + key] = vl.w;
    }
    __syncthreads();
#pragma unroll
    for (int i = 0; i < 8; i++) {
        int f = tid + i * 256;
        int d = f >> 5, kp = f & 31;
        uint32_t sel = (d & 1) ? 0x7632u : 0x5410u;
        uint2 wh = *(const uint2*)&sc[0][(d >> 1) * 66 + 2 * kp];
        uint2 wl = *(const uint2*)&sc[1][(d >> 1) * 66 + 2 * kp];
        size_t dst = (size_t)(bh * 64 + d) * 1024 + kb * 32 + kp;
        vth[dst] = __byte_perm(wh.x, wh.y, sel);
        vtl[dst] = __byte_perm(wl.x, wl.y, sel);
    }
}

// ---------------------------------------------------------------------------
// GEMM on split inputs: C = A @ W + bias  (3 bf16 mma terms, fp32 accum)
// A split [M][K/2] row-major, W^T split [Nn][K/2] row-major.
// 128x128 tile, BK=32 (16 kpairs), 256 thr, warps 4(m)x2(n), warp 32x64.
// cp.async double-buffered.  SPLIT_OUT: write C as hi/lo pairs; else fp32.
// smem/buf: Ah,Al,Bh,Bl each [128][20] u32 -> 10240 u32/buf, 2 bufs = 81920 B.
// ---------------------------------------------------------------------------
#define TSTR 20
#define TILE_U32 2560
#define BUF_U32 10240
#define GSMEM_BYTES (2 * BUF_U32 * 4)

template <bool SPLIT_OUT>
__global__ __launch_bounds__(256, 2) void gemm_sp(
    const uint32_t* __restrict__ Ah_g, const uint32_t* __restrict__ Al_g,
    const uint32_t* __restrict__ Bh_g, const uint32_t* __restrict__ Bl_g,
    const float* __restrict__ bias,
    float* __restrict__ C, uint32_t* __restrict__ Ch, uint32_t* __restrict__ Cl,
    int M, int Nn, int K)
{
    extern __shared__ uint32_t sm[];
    const uint32_t sb = smem_u32(sm);
    const int tid = threadIdx.x;
    const int lane = tid & 31, warp = tid >> 5;
    const int g = lane >> 2, cq = lane & 3;
    const int wm = (warp >> 1) * 32, wn = (warp & 1) * 64;
    const int m0 = blockIdx.y * 128, n0 = blockIdx.x * 128;
    const int kwtot = K / 2;

    float acc[2][8][4];
#pragma unroll
    for (int mt = 0; mt < 2; mt++)
#pragma unroll
        for (int nt = 0; nt < 8; nt++)
#pragma unroll
            for (int k = 0; k < 4; k++) acc[mt][nt][k] = 0.0f;

    auto issue = [&](int c, int buf) {
        const int kw = c * 16;
        const uint32_t bb = sb + buf * (BUF_U32 * 4);
#pragma unroll
        for (int i = 0; i < 2; i++) {
            int f = tid + i * 256;
            int r = f >> 2, q = (f & 3) * 4;
            uint32_t d0 = bb + (r * TSTR + q) * 4;
            CP_ASYNC16(d0,                 &Ah_g[(size_t)(m0 + r) * kwtot + kw + q]);
            CP_ASYNC16(d0 + TILE_U32 * 4,  &Al_g[(size_t)(m0 + r) * kwtot + kw + q]);
            CP_ASYNC16(d0 + TILE_U32 * 8,  &Bh_g[(size_t)(n0 + r) * kwtot + kw + q]);
            CP_ASYNC16(d0 + TILE_U32 * 12, &Bl_g[(size_t)(n0 + r) * kwtot + kw + q]);
        }
        CP_COMMIT();
    };

    const int nch = K / 32;
    issue(0, 0);
    for (int c = 0; c < nch; c++) {
        if (c + 1 < nch) { issue(c + 1, (c + 1) & 1); CP_WAIT(1); }
        else             { CP_WAIT(0); }
        __syncthreads();

        const uint32_t* Ahs = sm + (c & 1) * BUF_U32;
        const uint32_t* Als = Ahs + TILE_U32;
        const uint32_t* Bhs = Ahs + 2 * TILE_U32;
        const uint32_t* Bls = Ahs + 3 * TILE_U32;
#pragma unroll
        for (int kc = 0; kc < 2; kc++) {
            uint32_t ah[2][4], al[2][4];
#pragma unroll
            for (int mt = 0; mt < 2; mt++) {
                int r0 = (wm + mt * 16 + g) * TSTR + kc * 8;
                int r1 = (wm + mt * 16 + g + 8) * TSTR + kc * 8;
                ah[mt][0] = Ahs[r0 + cq]; ah[mt][1] = Ahs[r1 + cq];
                ah[mt][2] = Ahs[r0 + cq + 4]; ah[mt][3] = Ahs[r1 + cq + 4];
                al[mt][0] = Als[r0 + cq]; al[mt][1] = Als[r1 + cq];
                al[mt][2] = Als[r0 + cq + 4]; al[mt][3] = Als[r1 + cq + 4];
            }
#pragma unroll
            for (int nt = 0; nt < 8; nt++) {
                int nb = (wn + nt * 8 + g) * TSTR + kc * 8;
                uint32_t bh[2], bl[2];
                bh[0] = Bhs[nb + cq]; bh[1] = Bhs[nb + cq + 4];
                bl[0] = Bls[nb + cq]; bl[1] = Bls[nb + cq + 4];
#pragma unroll
                for (int mt = 0; mt < 2; mt++) {
                    mma16(acc[mt][nt], ah[mt], bh);
                    mma16(acc[mt][nt], al[mt], bh);
                    mma16(acc[mt][nt], ah[mt], bl);
                }
            }
        }
        __syncthreads();
    }

#pragma unroll
    for (int mt = 0; mt < 2; mt++) {
#pragma unroll
        for (int nt = 0; nt < 8; nt++) {
            int row = m0 + wm + mt * 16 + g;
            int col = n0 + wn + nt * 8 + 2 * cq;
            float b0 = bias[col], b1 = bias[col + 1];
            float v00 = acc[mt][nt][0] + b0, v01 = acc[mt][nt][1] + b1;
            float v10 = acc[mt][nt][2] + b0, v11 = acc[mt][nt][3] + b1;
            if (SPLIT_OUT) {
                int wc = col >> 1;
                uint32_t hh, ll;
                split2(v00, v01, hh, ll);
                Ch[(size_t)row * (Nn / 2) + wc] = hh;
                Cl[(size_t)row * (Nn / 2) + wc] = ll;
                split2(v10, v11, hh, ll);
                Ch[(size_t)(row + 8) * (Nn / 2) + wc] = hh;
                Cl[(size_t)(row + 8) * (Nn / 2) + wc] = ll;
            } else {
                *(float2*)&C[(size_t)row * Nn + col] = make_float2(v00, v01);
                *(float2*)&C[(size_t)(row + 8) * Nn + col] = make_float2(v10, v11);
            }
        }
    }
}

// ---------------------------------------------------------------------------
// Attention (3xBF16 flash) on split inputs. 128 q/block, 64-key tiles, 8 warps,
// warp owns 16 q rows. Tiles u32 pairs, stride 36 (conflict-free fragments).
// Q/K staged from qkv split (d-pairs); V from precomputed V^T split. cp.async.
// Output written split (d-pairs) for GEMM2.
// ---------------------------------------------------------------------------
#define QS2 36
#define AO_QH 0
#define AO_QL 4608
#define AO_KH 9216
#define AO_KL 11520
#define AO_VH 13824
#define AO_VL 16128
#define AO_PH 18432
#define AO_PL 23040
#define ATT_SMEM_U32 27648

__global__ __launch_bounds__(256, 2) void attn_sp(
    const uint32_t* __restrict__ qh_g, const uint32_t* __restrict__ ql_g,
    const uint32_t* __restrict__ vth,  const uint32_t* __restrict__ vtl,
    uint32_t* __restrict__ atth, uint32_t* __restrict__ attl)
{
    extern __shared__ uint32_t sm[];
    const uint32_t sb = smem_u32(sm);
    uint32_t* Qh = sm + AO_QH;
    uint32_t* Ql = sm + AO_QL;
    uint32_t* Kh = sm + AO_KH;
    uint32_t* Kl = sm + AO_KL;
    uint32_t* Vh = sm + AO_VH;
    uint32_t* Vl = sm + AO_VL;
    uint32_t* Ph = sm + AO_PH;
    uint32_t* Pl = sm + AO_PL;

    const int tid  = threadIdx.x;
    const int lane = tid & 31, warp = tid >> 5;
    const int g = lane >> 2, cq = lane & 3;
    const int b = blockIdx.z, h = blockIdx.y;
    const int bh = b * H + h;
    const int q0 = blockIdx.x * 128;

    // stage Q (cp.async): 128 rows x 32 words, hi+lo
#pragma unroll
    for (int i = 0; i < 4; i++) {
        int f = tid + i * 256;
        int row = f >> 3, q = (f & 7) * 4;
        size_t src = (size_t)(b * 2048 + q0 + row) * 1536 + h * 32 + q;
        uint32_t dst = sb + (AO_QH + row * QS2 + q) * 4;
        CP_ASYNC16(dst, &qh_g[src]);
        CP_ASYNC16(dst + AO_QL * 4, &ql_g[src]);
    }
    CP_COMMIT();

    float m0v = -1e30f, m1v = -1e30f, l0s = 0.0f, l1s = 0.0f;
    float o[8][4];
#pragma unroll
    for (int nt = 0; nt < 8; nt++)
#pragma unroll
        for (int k = 0; k < 4; k++) o[nt][k] = 0.0f;

    const int rb_ = warp * 16;

    for (int kb = 0; kb < N / 64; kb++) {
        __syncthreads();   // prior compute done; K/V free to overwrite

        // stage K and V^T tiles (cp.async): 64 rows x 32 words each, hi+lo
#pragma unroll
        for (int i = 0; i < 2; i++) {
            int f = tid + i * 256;
            int row = f >> 3, q = (f & 7) * 4;
            size_t ksrc = (size_t)(b * 2048 + kb * 64 + row) * 1536 + 512 + h * 32 + q;
            uint32_t kdst = sb + (AO_KH + row * QS2 + q) * 4;
            CP_ASYNC16(kdst, &qh_g[ksrc]);
            CP_ASYNC16(kdst + (AO_KL - AO_KH) * 4, &ql_g[ksrc]);
            size_t vsrc = (size_t)(bh * 64 + row) * 1024 + kb * 32 + q;
            uint32_t vdst = sb + (AO_VH + row * QS2 + q) * 4;
            CP_ASYNC16(vdst, &vth[vsrc]);
            CP_ASYNC16(vdst + (AO_VL - AO_VH) * 4, &vtl[vsrc]);
        }
        CP_COMMIT();
        CP_WAIT(0);
        __syncthreads();

        // S = Q @ K^T
        float s[8][4];
#pragma unroll
        for (int nt = 0; nt < 8; nt++)
#pragma unroll
            for (int k = 0; k < 4; k++) s[nt][k] = 0.0f;

#pragma unroll
        for (int kc = 0; kc < 4; kc++) {
            uint32_t ah[4], al[4];
            int r0 = (rb_ + g) * QS2 + kc * 8;
            int r1 = (rb_ + g + 8) * QS2 + kc * 8;
            ah[0] = Qh[r0 + cq]; ah[1] = Qh[r1 + cq];
            ah[2] = Qh[r0 + cq + 4]; ah[3] = Qh[r1 + cq + 4];
            al[0] = Ql[r0 + cq]; al[1] = Ql[r1 + cq];
            al[2] = Ql[r0 + cq + 4]; al[3] = Ql[r1 + cq + 4];
#pragma unroll
            for (int nt = 0; nt < 8; nt++) {
                int kr = (nt * 8 + g) * QS2 + kc * 8;
                uint32_t bh2[2], bl2[2];
                bh2[0] = Kh[kr + cq]; bh2[1] = Kh[kr + cq + 4];
                bl2[0] = Kl[kr + cq]; bl2[1] = Kl[kr + cq + 4];
                mma16(s[nt], ah, bh2);
                mma16(s[nt], al, bh2);
                mma16(s[nt], ah, bl2);
            }
        }

        // online softmax
        float rm0 = -1e30f, rm1 = -1e30f;
#pragma unroll
        for (int nt = 0; nt < 8; nt++) {
            s[nt][0] *= SCALE; s[nt][1] *= SCALE; s[nt][2] *= SCALE; s[nt][3] *= SCALE;
            rm0 = fmaxf(rm0, fmaxf(s[nt][0], s[nt][1]));
            rm1 = fmaxf(rm1, fmaxf(s[nt][2], s[nt][3]));
        }
        rm0 = fmaxf(rm0, __shfl_xor_sync(0xffffffff, rm0, 1));
        rm0 = fmaxf(rm0, __shfl_xor_sync(0xffffffff, rm0, 2));
        rm1 = fmaxf(rm1, __shfl_xor_sync(0xffffffff, rm1, 1));
        rm1 = fmaxf(rm1, __shfl_xor_sync(0xffffffff, rm1, 2));

        float nm0 = fmaxf(m0v, rm0), nm1 = fmaxf(m1v, rm1);
        float a0 = __expf(m0v - nm0), a1 = __expf(m1v - nm1);
        m0v = nm0; m1v = nm1;

        float rs0 = 0.0f, rs1 = 0.0f;
#pragma unroll
        for (int nt = 0; nt < 8; nt++) {
            float p0 = __expf(s[nt][0] - nm0);
            float p1 = __expf(s[nt][1] - nm0);
            float p2 = __expf(s[nt][2] - nm1);
            float p3 = __expf(s[nt][3] - nm1);
            rs0 += p0 + p1;
            rs1 += p2 + p3;
            uint32_t hh, ll;
            split2(p0, p1, hh, ll);
            Ph[(rb_ + g) * QS2 + nt * 4 + cq] = hh;
            Pl[(rb_ + g) * QS2 + nt * 4 + cq] = ll;
            split2(p2, p3, hh, ll);
            Ph[(rb_ + g + 8) * QS2 + nt * 4 + cq] = hh;
            Pl[(rb_ + g + 8) * QS2 + nt * 4 + cq] = ll;
        }
        rs0 += __shfl_xor_sync(0xffffffff, rs0, 1);
        rs0 += __shfl_xor_sync(0xffffffff, rs0, 2);
        rs1 += __shfl_xor_sync(0xffffffff, rs1, 1);
        rs1 += __shfl_xor_sync(0xffffffff, rs1, 2);
        l0s = l0s * a0 + rs0;
        l1s = l1s * a1 + rs1;
#pragma unroll
        for (int nt = 0; nt < 8; nt++) {
            o[nt][0] *= a0; o[nt][1] *= a0; o[nt][2] *= a1; o[nt][3] *= a1;
        }
        __syncwarp();

        // O += P @ V
#pragma unroll
        for (int kc = 0; kc < 4; kc++) {
            uint32_t ah[4], al[4];
            int r0 = (rb_ + g) * QS2 + kc * 8;
            int r1 = (rb_ + g + 8) * QS2 + kc * 8;
            ah[0] = Ph[r0 + cq]; ah[1] = Ph[r1 + cq];
            ah[2] = Ph[r0 + cq + 4]; ah[3] = Ph[r1 + cq + 4];
            al[0] = Pl[r0 + cq]; al[1] = Pl[r1 + cq];
            al[2] = Pl[r0 + cq + 4]; al[3] = Pl[r1 + cq + 4];
#pragma unroll
            for (int nt = 0; nt < 8; nt++) {
                int vr = (nt * 8 + g) * QS2 + kc * 8;
                uint32_t bh2[2], bl2[2];
                bh2[0] = Vh[vr + cq]; bh2[1] = Vh[vr + cq + 4];
                bl2[0] = Vl[vr + cq]; bl2[1] = Vl[vr + cq + 4];
                mma16(o[nt], ah, bh2);
                mma16(o[nt], al, bh2);
                mma16(o[nt], ah, bl2);
            }
        }
    }

    // normalize + write split att (d-pairs)
    float inv0 = 1.0f / l0s, inv1 = 1.0f / l1s;
#pragma unroll
    for (int nt = 0; nt < 8; nt++) {
        int wc = h * 32 + nt * 4 + cq;
        size_t r0o = (size_t)(b * 2048 + q0 + rb_ + g) * 512 + wc;
        size_t r1o = (size_t)(b * 2048 + q0 + rb_ + g + 8) * 512 + wc;
        uint32_t hh, ll;
        split2(o[nt][0] * inv0, o[nt][1] * inv0, hh, ll);
        atth[r0o] = hh; attl[r0o] = ll;
        split2(o[nt][2] * inv1, o[nt][3] * inv1, hh, ll);
        atth[r1o] = hh; attl[r1o] = ll;
    }
}

// ---------------------------------------------------------------------------
extern "C" void kernel_launch(void* const* d_in, const int* in_sizes, int n_in,
                              void* d_out, int out_size)
{
    const float* x     = (const float*)d_in[0];
    const float* Wqkv  = (const float*)d_in[1];
    const float* bqkv  = (const float*)d_in[2];
    const float* Wproj = (const float*)d_in[3];
    const float* bproj = (const float*)d_in[4];
    float* out = (float*)d_out;

    void* p;
    uint32_t *xh, *xl, *wqh, *wql, *wph, *wpl, *qh, *ql, *ath, *atl, *vth, *vtl;
    cudaGetSymbolAddress(&p, g_xh);    xh = (uint32_t*)p;
    cudaGetSymbolAddress(&p, g_xl);    xl = (uint32_t*)p;
    cudaGetSymbolAddress(&p, g_wqkvh); wqh = (uint32_t*)p;
    cudaGetSymbolAddress(&p, g_wqkvl); wql = (uint32_t*)p;
    cudaGetSymbolAddress(&p, g_wprojh); wph = (uint32_t*)p;
    cudaGetSymbolAddress(&p, g_wprojl); wpl = (uint32_t*)p;
    cudaGetSymbolAddress(&p, g_qkvh);  qh = (uint32_t*)p;
    cudaGetSymbolAddress(&p, g_qkvl);  ql = (uint32_t*)p;
    cudaGetSymbolAddress(&p, g_atth);  ath = (uint32_t*)p;
    cudaGetSymbolAddress(&p, g_attl);  atl = (uint32_t*)p;
    cudaGetSymbolAddress(&p, g_vth);   vth = (uint32_t*)p;
    cudaGetSymbolAddress(&p, g_vtl);   vtl = (uint32_t*)p;

    cudaFuncSetAttribute(gemm_sp<true>,  cudaFuncAttributeMaxDynamicSharedMemorySize, GSMEM_BYTES);
    cudaFuncSetAttribute(gemm_sp<false>, cudaFuncAttributeMaxDynamicSharedMemorySize, GSMEM_BYTES);
    cudaFuncSetAttribute(attn_sp, cudaFuncAttributeMaxDynamicSharedMemorySize, ATT_SMEM_U32 * 4);

    // prep: split x, transpose+split weights
    split_x_k<<<BN * D / 4 / 256, 256>>>(x, xh, xl);
    wsplit_k<<<dim3(3 * D / 64, D / 64), 256>>>(Wqkv, wqh, wql, D, 3 * D);
    wsplit_k<<<dim3(D / 64, D / 64), 256>>>(Wproj, wph, wpl, D, D);

    // 1) qkv = x @ Wqkv + bqkv  (split output)
    gemm_sp<true><<<dim3(3 * D / 128, BN / 128), 256, GSMEM_BYTES>>>(
        xh, xl, wqh, wql, bqkv, nullptr, qh, ql, BN, 3 * D, D);

    // 1b) build V^T split
    vtrans_k<<<dim3(N / 64, B * H), 256>>>(qh, ql, vth, vtl);

    // 2) attention -> att (split)
    attn_sp<<<dim3(N / 128, H, B), 256, ATT_SMEM_U32 * 4>>>(qh, ql, vth, vtl, ath, atl);

    // 3) out = att @ Wproj + bproj  (fp32 output)
    gemm_sp<false><<<dim3(D / 128, BN / 128), 256, GSMEM_BYTES>>>(
        ath, atl, wph, wpl, bproj, out, nullptr, nullptr, BN, D, D);
}

// round 6
// speedup vs baseline: 3.6569x; 1.0282x over previous
#include <cuda_runtime.h>
#include <cuda_bf16.h>
#include <math.h>
#include <stdint.h>

// Problem constants
#define B 4
#define N 2048
#define D 1024
#define H 16
#define HD 64
#define BN (B * N)            // 8192
#define SCALE 0.125f

// Scratch (device globals; all u32 = packed bf16x2 hi/lo pairs)
__device__ uint32_t g_xh[BN * 512],      g_xl[BN * 512];       // x split, d-pairs
__device__ uint32_t g_wqkvh[3072 * 512], g_wqkvl[3072 * 512];  // Wqkv^T [n][kpair]
__device__ uint32_t g_wprojh[1024 * 512], g_wprojl[1024 * 512];// Wproj^T [n][kpair]
__device__ uint32_t g_qkvh[BN * 1536],   g_qkvl[BN * 1536];    // qkv split, col-pairs
__device__ uint32_t g_atth[BN * 512],    g_attl[BN * 512];     // att split, d-pairs
__device__ uint32_t g_vth[64 * 64 * 1024], g_vtl[64 * 64 * 1024]; // V^T [bh][d][keypair]

// ---------------------------------------------------------------------------
// helpers
// ---------------------------------------------------------------------------
__device__ __forceinline__ void split2(float x0, float x1, uint32_t& h, uint32_t& l) {
    __nv_bfloat162 hh = __floats2bfloat162_rn(x0, x1);
    float r0 = x0 - __bfloat162float(hh.x);
    float r1 = x1 - __bfloat162float(hh.y);
    __nv_bfloat162 ll = __floats2bfloat162_rn(r0, r1);
    h = *reinterpret_cast<uint32_t*>(&hh);
    l = *reinterpret_cast<uint32_t*>(&ll);
}
__device__ __forceinline__ void mma16(float* c, const uint32_t* a, const uint32_t* b) {
    asm volatile(
        "mma.sync.aligned.m16n8k16.row.col.f32.bf16.bf16.f32 "
        "{%0,%1,%2,%3}, {%4,%5,%6,%7}, {%8,%9}, {%0,%1,%2,%3};"
        : "+f"(c[0]), "+f"(c[1]), "+f"(c[2]), "+f"(c[3])
        : "r"(a[0]), "r"(a[1]), "r"(a[2]), "r"(a[3]), "r"(b[0]), "r"(b[1]));
}
__device__ __forceinline__ void ldsm4(uint32_t addr, uint32_t* r) {
    asm volatile("ldmatrix.sync.aligned.m8n8.x4.shared.b16 {%0,%1,%2,%3}, [%4];"
        : "=r"(r[0]), "=r"(r[1]), "=r"(r[2]), "=r"(r[3]) : "r"(addr));
}
__device__ __forceinline__ uint32_t smem_u32(const void* p) {
    uint32_t a;
    asm("{ .reg .u64 t; cvta.to.shared.u64 t, %1; cvt.u32.u64 %0, t; }" : "=r"(a) : "l"(p));
    return a;
}
#define CP_ASYNC16(dst, src) \
    asm volatile("cp.async.cg.shared.global [%0], [%1], 16;" :: "r"(dst), "l"(src))
#define CP_COMMIT() asm volatile("cp.async.commit_group;" ::: "memory")
#define CP_WAIT(n)  asm volatile("cp.async.wait_group %0;" :: "n"(n) : "memory")

// ---------------------------------------------------------------------------
// split_x: x fp32 -> hi/lo bf16 pairs (d-pairs)
// ---------------------------------------------------------------------------
__global__ void split_x_k(const float* __restrict__ x,
                          uint32_t* __restrict__ xh, uint32_t* __restrict__ xl)
{
    int i = blockIdx.x * blockDim.x + threadIdx.x;
    float4 v = ((const float4*)x)[i];
    uint32_t h0, l0, h1, l1;
    split2(v.x, v.y, h0, l0);
    split2(v.z, v.w, h1, l1);
    ((uint2*)xh)[i] = make_uint2(h0, h1);
    ((uint2*)xl)[i] = make_uint2(l0, l1);
}

// ---------------------------------------------------------------------------
// wsplit: W[K][Nn] fp32 -> W^T split [n][kpair]
// ---------------------------------------------------------------------------
__global__ __launch_bounds__(256) void wsplit_k(
    const float* __restrict__ W, uint32_t* __restrict__ Wth, uint32_t* __restrict__ Wtl,
    int K, int Nn)
{
    __shared__ float sw[64 * 68];
    const int tid = threadIdx.x;
    const int k0 = blockIdx.y * 64, n0 = blockIdx.x * 64;
#pragma unroll
    for (int i = 0; i < 4; i++) {
        int f = tid + i * 256;
        int k = f >> 4, nq = f & 15;
        float4 v = *(const float4*)&W[(size_t)(k0 + k) * Nn + n0 + nq * 4];
        *(float4*)&sw[k * 68 + nq * 4] = v;
    }
    __syncthreads();
    const int n = tid >> 2, kq = tid & 3;
    uint32_t hb[8], lb[8];
#pragma unroll
    for (int j = 0; j < 8; j++) {
        int kp = kq * 8 + j;
        split2(sw[(2 * kp) * 68 + n], sw[(2 * kp + 1) * 68 + n], hb[j], lb[j]);
    }
    size_t o = (size_t)(n0 + n) * (K / 2) + k0 / 2 + kq * 8;
    *(uint4*)&Wth[o]     = make_uint4(hb[0], hb[1], hb[2], hb[3]);
    *(uint4*)&Wth[o + 4] = make_uint4(hb[4], hb[5], hb[6], hb[7]);
    *(uint4*)&Wtl[o]     = make_uint4(lb[0], lb[1], lb[2], lb[3]);
    *(uint4*)&Wtl[o + 4] = make_uint4(lb[4], lb[5], lb[6], lb[7]);
}

// ---------------------------------------------------------------------------
// vtrans: qkv split (v section, d-pairs) -> V^T split [bh][d][keypair]
// ---------------------------------------------------------------------------
__global__ __launch_bounds__(256) void vtrans_k(
    const uint32_t* __restrict__ qh, const uint32_t* __restrict__ ql,
    uint32_t* __restrict__ vth, uint32_t* __restrict__ vtl)
{
    __shared__ uint32_t sc[2][32 * 66];
    const int tid = threadIdx.x;
    const int kb = blockIdx.x, bh = blockIdx.y;
    const int b = bh >> 4, h = bh & 15;
#pragma unroll
    for (int i = 0; i < 2; i++) {
        int f = tid + i * 256;
        int key = f >> 3, q = (f & 7) * 4;
        size_t src = (size_t)(b * 2048 + kb * 64 + key) * 1536 + 1024 + h * 32 + q;
        uint4 vh = *(const uint4*)&qh[src];
        uint4 vl = *(const uint4*)&ql[src];
        sc[0][(q + 0) * 66 + key] = vh.x; sc[0][(q + 1) * 66 + key] = vh.y;
        sc[0][(q + 2) * 66 + key] = vh.z; sc[0][(q + 3) * 66 + key] = vh.w;
        sc[1][(q + 0) * 66 + key] = vl.x; sc[1][(q + 1) * 66 + key] = vl.y;
        sc[1][(q + 2) * 66 + key] = vl.z; sc[1][(q + 3) * 66 + key] = vl.w;
    }
    __syncthreads();
#pragma unroll
    for (int i = 0; i < 8; i++) {
        int f = tid + i * 256;
        int d = f >> 5, kp = f & 31;
        uint32_t sel = (d & 1) ? 0x7632u : 0x5410u;
        uint2 wh = *(const uint2*)&sc[0][(d >> 1) * 66 + 2 * kp];
        uint2 wl = *(const uint2*)&sc[1][(d >> 1) * 66 + 2 * kp];
        size_t dst = (size_t)(bh * 64 + d) * 1024 + kb * 32 + kp;
        vth[dst] = __byte_perm(wh.x, wh.y, sel);
        vtl[dst] = __byte_perm(wl.x, wl.y, sel);
    }
}

// ---------------------------------------------------------------------------
// GEMM on split inputs (3 bf16 mma terms, fp32 accum), ldmatrix fragments.
// 128x128 tile, BK=32 (16 kpairs), 256 thr, warps 4(m)x2(n), warp 32x64.
// ---------------------------------------------------------------------------
#define TSTR 20
#define TILE_U32 2560
#define BUF_U32 10240
#define GSMEM_BYTES (2 * BUF_U32 * 4)

template <bool SPLIT_OUT>
__global__ __launch_bounds__(256, 2) void gemm_sp(
    const uint32_t* __restrict__ Ah_g, const uint32_t* __restrict__ Al_g,
    const uint32_t* __restrict__ Bh_g, const uint32_t* __restrict__ Bl_g,
    const float* __restrict__ bias,
    float* __restrict__ C, uint32_t* __restrict__ Ch, uint32_t* __restrict__ Cl,
    int M, int Nn, int K)
{
    extern __shared__ uint32_t sm[];
    const uint32_t sb = smem_u32(sm);
    const int tid = threadIdx.x;
    const int lane = tid & 31, warp = tid >> 5;
    const int g = lane >> 2, cq = lane & 3;
    const int wm = (warp >> 1) * 32, wn = (warp & 1) * 64;
    const int m0 = blockIdx.y * 128, n0 = blockIdx.x * 128;
    const int kwtot = K / 2;

    // ldmatrix lane addressing
    const int a_r = lane & 15, a_c = (lane >> 4) * 4;              // A/x4 per (mt,h|l)
    const int b_r = lane & 7, b_c = ((lane >> 3) & 1) * 4;         // B/x4 hi+lo combined
    const uint32_t b_tile = (lane < 16 ? 2u : 3u) * TILE_U32;

    float acc[2][8][4];
#pragma unroll
    for (int mt = 0; mt < 2; mt++)
#pragma unroll
        for (int nt = 0; nt < 8; nt++)
#pragma unroll
            for (int k = 0; k < 4; k++) acc[mt][nt][k] = 0.0f;

    auto issue = [&](int c, int buf) {
        const int kw = c * 16;
        const uint32_t bb = sb + buf * (BUF_U32 * 4);
#pragma unroll
        for (int i = 0; i < 2; i++) {
            int f = tid + i * 256;
            int r = f >> 2, q = (f & 3) * 4;
            uint32_t d0 = bb + (r * TSTR + q) * 4;
            CP_ASYNC16(d0,                 &Ah_g[(size_t)(m0 + r) * kwtot + kw + q]);
            CP_ASYNC16(d0 + TILE_U32 * 4,  &Al_g[(size_t)(m0 + r) * kwtot + kw + q]);
            CP_ASYNC16(d0 + TILE_U32 * 8,  &Bh_g[(size_t)(n0 + r) * kwtot + kw + q]);
            CP_ASYNC16(d0 + TILE_U32 * 12, &Bl_g[(size_t)(n0 + r) * kwtot + kw + q]);
        }
        CP_COMMIT();
    };

    const int nch = K / 32;
    issue(0, 0);
    for (int c = 0; c < nch; c++) {
        if (c + 1 < nch) { issue(c + 1, (c + 1) & 1); CP_WAIT(1); }
        else             { CP_WAIT(0); }
        __syncthreads();

        const uint32_t bufb = sb + (c & 1) * (BUF_U32 * 4);
#pragma unroll
        for (int kc = 0; kc < 2; kc++) {
            uint32_t ah[2][4], al[2][4];
#pragma unroll
            for (int mt = 0; mt < 2; mt++) {
                uint32_t aoff = bufb + ((wm + mt * 16 + a_r) * TSTR + kc * 8 + a_c) * 4;
                ldsm4(aoff, ah[mt]);
                ldsm4(aoff + TILE_U32 * 4, al[mt]);
            }
#pragma unroll
            for (int nt = 0; nt < 8; nt++) {
                uint32_t boff = bufb + (b_tile + (wn + nt * 8 + b_r) * TSTR + kc * 8 + b_c) * 4;
                uint32_t bb[4];
                ldsm4(boff, bb);
#pragma unroll
                for (int mt = 0; mt < 2; mt++) {
                    mma16(acc[mt][nt], ah[mt], bb);       // hi*hi
                    mma16(acc[mt][nt], al[mt], bb);       // lo*hi
                    mma16(acc[mt][nt], ah[mt], bb + 2);   // hi*lo
                }
            }
        }
        __syncthreads();
    }

#pragma unroll
    for (int mt = 0; mt < 2; mt++) {
#pragma unroll
        for (int nt = 0; nt < 8; nt++) {
            int row = m0 + wm + mt * 16 + g;
            int col = n0 + wn + nt * 8 + 2 * cq;
            float b0 = bias[col], b1 = bias[col + 1];
            float v00 = acc[mt][nt][0] + b0, v01 = acc[mt][nt][1] + b1;
            float v10 = acc[mt][nt][2] + b0, v11 = acc[mt][nt][3] + b1;
            if (SPLIT_OUT) {
                int wc = col >> 1;
                uint32_t hh, ll;
                split2(v00, v01, hh, ll);
                Ch[(size_t)row * (Nn / 2) + wc] = hh;
                Cl[(size_t)row * (Nn / 2) + wc] = ll;
                split2(v10, v11, hh, ll);
                Ch[(size_t)(row + 8) * (Nn / 2) + wc] = hh;
                Cl[(size_t)(row + 8) * (Nn / 2) + wc] = ll;
            } else {
                *(float2*)&C[(size_t)row * Nn + col] = make_float2(v00, v01);
                *(float2*)&C[(size_t)(row + 8) * Nn + col] = make_float2(v10, v11);
            }
        }
    }
}

// ---------------------------------------------------------------------------
// Attention (3xBF16 flash), ldmatrix fragments. 128 q/block, 64-key tiles,
// 8 warps; warp owns 16 q rows. Tiles u32 pairs, stride 36.
// ---------------------------------------------------------------------------
#define QS2 36
#define AO_QH 0
#define AO_QL 4608
#define AO_KH 9216
#define AO_KL 11520
#define AO_VH 13824
#define AO_VL 16128
#define AO_PH 18432
#define AO_PL 23040
#define ATT_SMEM_U32 27648

__global__ __launch_bounds__(256, 2) void attn_sp(
    const uint32_t* __restrict__ qh_g, const uint32_t* __restrict__ ql_g,
    const uint32_t* __restrict__ vth,  const uint32_t* __restrict__ vtl,
    uint32_t* __restrict__ atth, uint32_t* __restrict__ attl)
{
    extern __shared__ uint32_t sm[];
    const uint32_t sb = smem_u32(sm);
    uint32_t* Ph = sm + AO_PH;
    uint32_t* Pl = sm + AO_PL;

    const int tid  = threadIdx.x;
    const int lane = tid & 31, warp = tid >> 5;
    const int g = lane >> 2, cq = lane & 3;
    const int b = blockIdx.z, h = blockIdx.y;
    const int bh = b * H + h;
    const int q0 = blockIdx.x * 128;

    const int a_r = lane & 15, a_c = (lane >> 4) * 4;
    const int b_r = lane & 7, b_c = ((lane >> 3) & 1) * 4;
    const uint32_t k_tile = (lane < 16 ? AO_KH : AO_KL);
    const uint32_t v_tile = (lane < 16 ? AO_VH : AO_VL);

    // stage Q (cp.async): 128 rows x 32 words, hi+lo
#pragma unroll
    for (int i = 0; i < 4; i++) {
        int f = tid + i * 256;
        int row = f >> 3, q = (f & 7) * 4;
        size_t src = (size_t)(b * 2048 + q0 + row) * 1536 + h * 32 + q;
        uint32_t dst = sb + (AO_QH + row * QS2 + q) * 4;
        CP_ASYNC16(dst, &qh_g[src]);
        CP_ASYNC16(dst + AO_QL * 4, &ql_g[src]);
    }
    CP_COMMIT();

    float m0v = -1e30f, m1v = -1e30f, l0s = 0.0f, l1s = 0.0f;
    float o[8][4];
#pragma unroll
    for (int nt = 0; nt < 8; nt++)
#pragma unroll
        for (int k = 0; k < 4; k++) o[nt][k] = 0.0f;

    const int rb_ = warp * 16;

    for (int kb = 0; kb < N / 64; kb++) {
        __syncthreads();

        // stage K and V^T tiles (cp.async)
#pragma unroll
        for (int i = 0; i < 2; i++) {
            int f = tid + i * 256;
            int row = f >> 3, q = (f & 7) * 4;
            size_t ksrc = (size_t)(b * 2048 + kb * 64 + row) * 1536 + 512 + h * 32 + q;
            uint32_t kdst = sb + (AO_KH + row * QS2 + q) * 4;
            CP_ASYNC16(kdst, &qh_g[ksrc]);
            CP_ASYNC16(kdst + (AO_KL - AO_KH) * 4, &ql_g[ksrc]);
            size_t vsrc = (size_t)(bh * 64 + row) * 1024 + kb * 32 + q;
            uint32_t vdst = sb + (AO_VH + row * QS2 + q) * 4;
            CP_ASYNC16(vdst, &vth[vsrc]);
            CP_ASYNC16(vdst + (AO_VL - AO_VH) * 4, &vtl[vsrc]);
        }
        CP_COMMIT();
        CP_WAIT(0);
        __syncthreads();

        // S = Q @ K^T
        float s[8][4];
#pragma unroll
        for (int nt = 0; nt < 8; nt++)
#pragma unroll
            for (int k = 0; k < 4; k++) s[nt][k] = 0.0f;

#pragma unroll
        for (int kc = 0; kc < 4; kc++) {
            uint32_t qh4[4], ql4[4];
            uint32_t qoff = sb + (AO_QH + (rb_ + a_r) * QS2 + kc * 8 + a_c) * 4;
            ldsm4(qoff, qh4);
            ldsm4(qoff + AO_QL * 4, ql4);
#pragma unroll
            for (int nt = 0; nt < 8; nt++) {
                uint32_t koff = sb + (k_tile + (nt * 8 + b_r) * QS2 + kc * 8 + b_c) * 4;
                uint32_t kk[4];
                ldsm4(koff, kk);
                mma16(s[nt], qh4, kk);
                mma16(s[nt], ql4, kk);
                mma16(s[nt], qh4, kk + 2);
            }
        }

        // online softmax
        float rm0 = -1e30f, rm1 = -1e30f;
#pragma unroll
        for (int nt = 0; nt < 8; nt++) {
            s[nt][0] *= SCALE; s[nt][1] *= SCALE; s[nt][2] *= SCALE; s[nt][3] *= SCALE;
            rm0 = fmaxf(rm0, fmaxf(s[nt][0], s[nt][1]));
            rm1 = fmaxf(rm1, fmaxf(s[nt][2], s[nt][3]));
        }
        rm0 = fmaxf(rm0, __shfl_xor_sync(0xffffffff, rm0, 1));
        rm0 = fmaxf(rm0, __shfl_xor_sync(0xffffffff, rm0, 2));
        rm1 = fmaxf(rm1, __shfl_xor_sync(0xffffffff, rm1, 1));
        rm1 = fmaxf(rm1, __shfl_xor_sync(0xffffffff, rm1, 2));

        float nm0 = fmaxf(m0v, rm0), nm1 = fmaxf(m1v, rm1);
        float a0 = __expf(m0v - nm0), a1 = __expf(m1v - nm1);
        m0v = nm0; m1v = nm1;

        float rs0 = 0.0f, rs1 = 0.0f;
#pragma unroll
        for (int nt = 0; nt < 8; nt++) {
            float p0 = __expf(s[nt][0] - nm0);
            float p1 = __expf(s[nt][1] - nm0);
            float p2 = __expf(s[nt][2] - nm1);
            float p3 = __expf(s[nt][3] - nm1);
            rs0 += p0 + p1;
            rs1 += p2 + p3;
            uint32_t hh, ll;
            split2(p0, p1, hh, ll);
            Ph[(rb_ + g) * QS2 + nt * 4 + cq] = hh;
            Pl[(rb_ + g) * QS2 + nt * 4 + cq] = ll;
            split2(p2, p3, hh, ll);
            Ph[(rb_ + g + 8) * QS2 + nt * 4 + cq] = hh;
            Pl[(rb_ + g + 8) * QS2 + nt * 4 + cq] = ll;
        }
        rs0 += __shfl_xor_sync(0xffffffff, rs0, 1);
        rs0 += __shfl_xor_sync(0xffffffff, rs0, 2);
        rs1 += __shfl_xor_sync(0xffffffff, rs1, 1);
        rs1 += __shfl_xor_sync(0xffffffff, rs1, 2);
        l0s = l0s * a0 + rs0;
        l1s = l1s * a1 + rs1;
#pragma unroll
        for (int nt = 0; nt < 8; nt++) {
            o[nt][0] *= a0; o[nt][1] *= a0; o[nt][2] *= a1; o[nt][3] *= a1;
        }
        __syncwarp();

        // O += P @ V
#pragma unroll
        for (int kc = 0; kc < 4; kc++) {
            uint32_t ph4[4], pl4[4];
            uint32_t poff = sb + (AO_PH + (rb_ + a_r) * QS2 + kc * 8 + a_c) * 4;
            ldsm4(poff, ph4);
            ldsm4(poff + (AO_PL - AO_PH) * 4, pl4);
#pragma unroll
            for (int nt = 0; nt < 8; nt++) {
                uint32_t voff = sb + (v_tile + (nt * 8 + b_r) * QS2 + kc * 8 + b_c) * 4;
                uint32_t vv[4];
                ldsm4(voff, vv);
                mma16(o[nt], ph4, vv);
                mma16(o[nt], pl4, vv);
                mma16(o[nt], ph4, vv + 2);
            }
        }
    }

    // normalize + write split att (d-pairs)
    float inv0 = 1.0f / l0s, inv1 = 1.0f / l1s;
#pragma unroll
    for (int nt = 0; nt < 8; nt++) {
        int wc = h * 32 + nt * 4 + cq;
        size_t r0o = (size_t)(b * 2048 + q0 + rb_ + g) * 512 + wc;
        size_t r1o = (size_t)(b * 2048 + q0 + rb_ + g + 8) * 512 + wc;
        uint32_t hh, ll;
        split2(o[nt][0] * inv0, o[nt][1] * inv0, hh, ll);
        atth[r0o] = hh; attl[r0o] = ll;
        split2(o[nt][2] * inv1, o[nt][3] * inv1, hh, ll);
        atth[r1o] = hh; attl[r1o] = ll;
    }
}

// ---------------------------------------------------------------------------
extern "C" void kernel_launch(void* const* d_in, const int* in_sizes, int n_in,
                              void* d_out, int out_size)
{
    const float* x     = (const float*)d_in[0];
    const float* Wqkv  = (const float*)d_in[1];
    const float* bqkv  = (const float*)d_in[2];
    const float* Wproj = (const float*)d_in[3];
    const float* bproj = (const float*)d_in[4];
    float* out = (float*)d_out;

    void* p;
    uint32_t *xh, *xl, *wqh, *wql, *wph, *wpl, *qh, *ql, *ath, *atl, *vth, *vtl;
    cudaGetSymbolAddress(&p, g_xh);    xh = (uint32_t*)p;
    cudaGetSymbolAddress(&p, g_xl);    xl = (uint32_t*)p;
    cudaGetSymbolAddress(&p, g_wqkvh); wqh = (uint32_t*)p;
    cudaGetSymbolAddress(&p, g_wqkvl); wql = (uint32_t*)p;
    cudaGetSymbolAddress(&p, g_wprojh); wph = (uint32_t*)p;
    cudaGetSymbolAddress(&p, g_wprojl); wpl = (uint32_t*)p;
    cudaGetSymbolAddress(&p, g_qkvh);  qh = (uint32_t*)p;
    cudaGetSymbolAddress(&p, g_qkvl);  ql = (uint32_t*)p;
    cudaGetSymbolAddress(&p, g_atth);  ath = (uint32_t*)p;
    cudaGetSymbolAddress(&p, g_attl);  atl = (uint32_t*)p;
    cudaGetSymbolAddress(&p, g_vth);   vth = (uint32_t*)p;
    cudaGetSymbolAddress(&p, g_vtl);   vtl = (uint32_t*)p;

    cudaFuncSetAttribute(gemm_sp<true>,  cudaFuncAttributeMaxDynamicSharedMemorySize, GSMEM_BYTES);
    cudaFuncSetAttribute(gemm_sp<false>, cudaFuncAttributeMaxDynamicSharedMemorySize, GSMEM_BYTES);
    cudaFuncSetAttribute(attn_sp, cudaFuncAttributeMaxDynamicSharedMemorySize, ATT_SMEM_U32 * 4);

    // prep: split x, transpose+split weights
    split_x_k<<<BN * D / 4 / 256, 256>>>(x, xh, xl);
    wsplit_k<<<dim3(3 * D / 64, D / 64), 256>>>(Wqkv, wqh, wql, D, 3 * D);
    wsplit_k<<<dim3(D / 64, D / 64), 256>>>(Wproj, wph, wpl, D, D);

    // 1) qkv = x @ Wqkv + bqkv  (split output)
    gemm_sp<true><<<dim3(3 * D / 128, BN / 128), 256, GSMEM_BYTES>>>(
        xh, xl, wqh, wql, bqkv, nullptr, qh, ql, BN, 3 * D, D);

    // 1b) build V^T split
    vtrans_k<<<dim3(N / 64, B * H), 256>>>(qh, ql, vth, vtl);

    // 2) attention -> att (split)
    attn_sp<<<dim3(N / 128, H, B), 256, ATT_SMEM_U32 * 4>>>(qh, ql, vth, vtl, ath, atl);

    // 3) out = att @ Wproj + bproj  (fp32 output)
    gemm_sp<false><<<dim3(D / 128, BN / 128), 256, GSMEM_BYTES>>>(
        ath, atl, wph, wpl, bproj, out, nullptr, nullptr, BN, D, D);
}

// round 7
// speedup vs baseline: 3.9468x; 1.0793x over previous
#include <cuda_runtime.h>
#include <cuda_bf16.h>
#include <math.h>
#include <stdint.h>

// Problem constants
#define B 4
#define N 2048
#define D 1024
#define H 16
#define HD 64
#define BN (B * N)            // 8192
#define SCALE 0.125f

// Scratch (device globals; all u32 = packed bf16x2 hi/lo pairs)
__device__ uint32_t g_xh[BN * 512],      g_xl[BN * 512];       // x split, d-pairs
__device__ uint32_t g_wqkvh[3072 * 512], g_wqkvl[3072 * 512];  // Wqkv^T [n][kpair]
__device__ uint32_t g_wprojh[1024 * 512], g_wprojl[1024 * 512];// Wproj^T [n][kpair]
__device__ uint32_t g_qkvh[BN * 1536],   g_qkvl[BN * 1536];    // qkv split, col-pairs
__device__ uint32_t g_atth[BN * 512],    g_attl[BN * 512];     // att split, d-pairs
__device__ uint32_t g_vth[64 * 64 * 1024], g_vtl[64 * 64 * 1024]; // V^T [bh][d][keypair]

// ---------------------------------------------------------------------------
// helpers
// ---------------------------------------------------------------------------
__device__ __forceinline__ void split2(float x0, float x1, uint32_t& h, uint32_t& l) {
    __nv_bfloat162 hh = __floats2bfloat162_rn(x0, x1);
    float r0 = x0 - __bfloat162float(hh.x);
    float r1 = x1 - __bfloat162float(hh.y);
    __nv_bfloat162 ll = __floats2bfloat162_rn(r0, r1);
    h = *reinterpret_cast<uint32_t*>(&hh);
    l = *reinterpret_cast<uint32_t*>(&ll);
}
__device__ __forceinline__ void mma16(float* c, const uint32_t* a, const uint32_t* b) {
    asm volatile(
        "mma.sync.aligned.m16n8k16.row.col.f32.bf16.bf16.f32 "
        "{%0,%1,%2,%3}, {%4,%5,%6,%7}, {%8,%9}, {%0,%1,%2,%3};"
        : "+f"(c[0]), "+f"(c[1]), "+f"(c[2]), "+f"(c[3])
        : "r"(a[0]), "r"(a[1]), "r"(a[2]), "r"(a[3]), "r"(b[0]), "r"(b[1]));
}
__device__ __forceinline__ void ldsm4(uint32_t addr, uint32_t* r) {
    asm volatile("ldmatrix.sync.aligned.m8n8.x4.shared.b16 {%0,%1,%2,%3}, [%4];"
        : "=r"(r[0]), "=r"(r[1]), "=r"(r[2]), "=r"(r[3]) : "r"(addr));
}
__device__ __forceinline__ uint32_t smem_u32(const void* p) {
    uint32_t a;
    asm("{ .reg .u64 t; cvta.to.shared.u64 t, %1; cvt.u32.u64 %0, t; }" : "=r"(a) : "l"(p));
    return a;
}
#define CP_ASYNC16(dst, src) \
    asm volatile("cp.async.cg.shared.global [%0], [%1], 16;" :: "r"(dst), "l"(src))
#define CP_COMMIT() asm volatile("cp.async.commit_group;" ::: "memory")
#define CP_WAIT(n)  asm volatile("cp.async.wait_group %0;" :: "n"(n) : "memory")

// ---------------------------------------------------------------------------
// split_x: x fp32 -> hi/lo bf16 pairs (d-pairs)
// ---------------------------------------------------------------------------
__global__ void split_x_k(const float* __restrict__ x,
                          uint32_t* __restrict__ xh, uint32_t* __restrict__ xl)
{
    int i = blockIdx.x * blockDim.x + threadIdx.x;
    float4 v = ((const float4*)x)[i];
    uint32_t h0, l0, h1, l1;
    split2(v.x, v.y, h0, l0);
    split2(v.z, v.w, h1, l1);
    ((uint2*)xh)[i] = make_uint2(h0, h1);
    ((uint2*)xl)[i] = make_uint2(l0, l1);
}

// ---------------------------------------------------------------------------
// wsplit: W[K][Nn] fp32 -> W^T split [n][kpair]
// ---------------------------------------------------------------------------
__global__ __launch_bounds__(256) void wsplit_k(
    const float* __restrict__ W, uint32_t* __restrict__ Wth, uint32_t* __restrict__ Wtl,
    int K, int Nn)
{
    __shared__ float sw[64 * 68];
    const int tid = threadIdx.x;
    const int k0 = blockIdx.y * 64, n0 = blockIdx.x * 64;
#pragma unroll
    for (int i = 0; i < 4; i++) {
        int f = tid + i * 256;
        int k = f >> 4, nq = f & 15;
        float4 v = *(const float4*)&W[(size_t)(k0 + k) * Nn + n0 + nq * 4];
        *(float4*)&sw[k * 68 + nq * 4] = v;
    }
    __syncthreads();
    const int n = tid >> 2, kq = tid & 3;
    uint32_t hb[8], lb[8];
#pragma unroll
    for (int j = 0; j < 8; j++) {
        int kp = kq * 8 + j;
        split2(sw[(2 * kp) * 68 + n], sw[(2 * kp + 1) * 68 + n], hb[j], lb[j]);
    }
    size_t o = (size_t)(n0 + n) * (K / 2) + k0 / 2 + kq * 8;
    *(uint4*)&Wth[o]     = make_uint4(hb[0], hb[1], hb[2], hb[3]);
    *(uint4*)&Wth[o + 4] = make_uint4(hb[4], hb[5], hb[6], hb[7]);
    *(uint4*)&Wtl[o]     = make_uint4(lb[0], lb[1], lb[2], lb[3]);
    *(uint4*)&Wtl[o + 4] = make_uint4(lb[4], lb[5], lb[6], lb[7]);
}

// ---------------------------------------------------------------------------
// vtrans: qkv split (v section, d-pairs) -> V^T split [bh][d][keypair]
// ---------------------------------------------------------------------------
__global__ __launch_bounds__(256) void vtrans_k(
    const uint32_t* __restrict__ qh, const uint32_t* __restrict__ ql,
    uint32_t* __restrict__ vth, uint32_t* __restrict__ vtl)
{
    __shared__ uint32_t sc[2][32 * 66];
    const int tid = threadIdx.x;
    const int kb = blockIdx.x, bh = blockIdx.y;
    const int b = bh >> 4, h = bh & 15;
#pragma unroll
    for (int i = 0; i < 2; i++) {
        int f = tid + i * 256;
        int key = f >> 3, q = (f & 7) * 4;
        size_t src = (size_t)(b * 2048 + kb * 64 + key) * 1536 + 1024 + h * 32 + q;
        uint4 vh = *(const uint4*)&qh[src];
        uint4 vl = *(const uint4*)&ql[src];
        sc[0][(q + 0) * 66 + key] = vh.x; sc[0][(q + 1) * 66 + key] = vh.y;
        sc[0][(q + 2) * 66 + key] = vh.z; sc[0][(q + 3) * 66 + key] = vh.w;
        sc[1][(q + 0) * 66 + key] = vl.x; sc[1][(q + 1) * 66 + key] = vl.y;
        sc[1][(q + 2) * 66 + key] = vl.z; sc[1][(q + 3) * 66 + key] = vl.w;
    }
    __syncthreads();
#pragma unroll
    for (int i = 0; i < 8; i++) {
        int f = tid + i * 256;
        int d = f >> 5, kp = f & 31;
        uint32_t sel = (d & 1) ? 0x7632u : 0x5410u;
        uint2 wh = *(const uint2*)&sc[0][(d >> 1) * 66 + 2 * kp];
        uint2 wl = *(const uint2*)&sc[1][(d >> 1) * 66 + 2 * kp];
        size_t dst = (size_t)(bh * 64 + d) * 1024 + kb * 32 + kp;
        vth[dst] = __byte_perm(wh.x, wh.y, sel);
        vtl[dst] = __byte_perm(wl.x, wl.y, sel);
    }
}

// ---------------------------------------------------------------------------
// GEMM on split inputs (3 bf16 mma terms, fp32 accum), ldmatrix fragments.
// 128x128 tile, BK=32 (16 kpairs), 256 thr, warps 4(m)x2(n), warp 32x64.
// Single-barrier-per-chunk pipeline:
//   pre: issue(0); loop c: CP_WAIT(0) [free], sync, issue(c+1), compute(c).
// ---------------------------------------------------------------------------
#define TSTR 20
#define TILE_U32 2560
#define BUF_U32 10240
#define GSMEM_BYTES (2 * BUF_U32 * 4)

template <bool SPLIT_OUT>
__global__ __launch_bounds__(256, 2) void gemm_sp(
    const uint32_t* __restrict__ Ah_g, const uint32_t* __restrict__ Al_g,
    const uint32_t* __restrict__ Bh_g, const uint32_t* __restrict__ Bl_g,
    const float* __restrict__ bias,
    float* __restrict__ C, uint32_t* __restrict__ Ch, uint32_t* __restrict__ Cl,
    int M, int Nn, int K)
{
    extern __shared__ uint32_t sm[];
    const uint32_t sb = smem_u32(sm);
    const int tid = threadIdx.x;
    const int lane = tid & 31, warp = tid >> 5;
    const int g = lane >> 2, cq = lane & 3;
    const int wm = (warp >> 1) * 32, wn = (warp & 1) * 64;
    const int m0 = blockIdx.y * 128, n0 = blockIdx.x * 128;
    const int kwtot = K / 2;

    const int a_r = lane & 15, a_c = (lane >> 4) * 4;
    const int b_r = lane & 7, b_c = ((lane >> 3) & 1) * 4;
    const uint32_t b_tile = (lane < 16 ? 2u : 3u) * TILE_U32;

    float acc[2][8][4];
#pragma unroll
    for (int mt = 0; mt < 2; mt++)
#pragma unroll
        for (int nt = 0; nt < 8; nt++)
#pragma unroll
            for (int k = 0; k < 4; k++) acc[mt][nt][k] = 0.0f;

    auto issue = [&](int c, int buf) {
        const int kw = c * 16;
        const uint32_t bb = sb + buf * (BUF_U32 * 4);
#pragma unroll
        for (int i = 0; i < 2; i++) {
            int f = tid + i * 256;
            int r = f >> 2, q = (f & 3) * 4;
            uint32_t d0 = bb + (r * TSTR + q) * 4;
            CP_ASYNC16(d0,                 &Ah_g[(size_t)(m0 + r) * kwtot + kw + q]);
            CP_ASYNC16(d0 + TILE_U32 * 4,  &Al_g[(size_t)(m0 + r) * kwtot + kw + q]);
            CP_ASYNC16(d0 + TILE_U32 * 8,  &Bh_g[(size_t)(n0 + r) * kwtot + kw + q]);
            CP_ASYNC16(d0 + TILE_U32 * 12, &Bl_g[(size_t)(n0 + r) * kwtot + kw + q]);
        }
        CP_COMMIT();
    };

    const int nch = K / 32;
    issue(0, 0);
    for (int c = 0; c < nch; c++) {
        CP_WAIT(0);            // group c landed during previous compute phase
        __syncthreads();       // also releases WAR on buffer (c+1)&1
        if (c + 1 < nch) issue(c + 1, (c + 1) & 1);

        const uint32_t bufb = sb + (c & 1) * (BUF_U32 * 4);
#pragma unroll
        for (int kc = 0; kc < 2; kc++) {
            uint32_t ah[2][4], al[2][4];
#pragma unroll
            for (int mt = 0; mt < 2; mt++) {
                uint32_t aoff = bufb + ((wm + mt * 16 + a_r) * TSTR + kc * 8 + a_c) * 4;
                ldsm4(aoff, ah[mt]);
                ldsm4(aoff + TILE_U32 * 4, al[mt]);
            }
#pragma unroll
            for (int nt = 0; nt < 8; nt++) {
                uint32_t boff = bufb + (b_tile + (wn + nt * 8 + b_r) * TSTR + kc * 8 + b_c) * 4;
                uint32_t bb[4];
                ldsm4(boff, bb);
#pragma unroll
                for (int mt = 0; mt < 2; mt++) mma16(acc[mt][nt], ah[mt], bb);
#pragma unroll
                for (int mt = 0; mt < 2; mt++) mma16(acc[mt][nt], al[mt], bb);
#pragma unroll
                for (int mt = 0; mt < 2; mt++) mma16(acc[mt][nt], ah[mt], bb + 2);
            }
        }
    }

#pragma unroll
    for (int mt = 0; mt < 2; mt++) {
#pragma unroll
        for (int nt = 0; nt < 8; nt++) {
            int row = m0 + wm + mt * 16 + g;
            int col = n0 + wn + nt * 8 + 2 * cq;
            float b0 = bias[col], b1 = bias[col + 1];
            float v00 = acc[mt][nt][0] + b0, v01 = acc[mt][nt][1] + b1;
            float v10 = acc[mt][nt][2] + b0, v11 = acc[mt][nt][3] + b1;
            if (SPLIT_OUT) {
                int wc = col >> 1;
                uint32_t hh, ll;
                split2(v00, v01, hh, ll);
                Ch[(size_t)row * (Nn / 2) + wc] = hh;
                Cl[(size_t)row * (Nn / 2) + wc] = ll;
                split2(v10, v11, hh, ll);
                Ch[(size_t)(row + 8) * (Nn / 2) + wc] = hh;
                Cl[(size_t)(row + 8) * (Nn / 2) + wc] = ll;
            } else {
                *(float2*)&C[(size_t)row * Nn + col] = make_float2(v00, v01);
                *(float2*)&C[(size_t)(row + 8) * Nn + col] = make_float2(v10, v11);
            }
        }
    }
}

// ---------------------------------------------------------------------------
// Attention (3xBF16 flash): register-resident P, double-buffered K/V,
// one barrier per key-tile. 128 q/block, 64-key tiles, 8 warps (16 q rows each).
// smem u32 layout: Q hi@0 lo@4608 (9216), then 2 KV buffers of 9216:
//   per buffer: KH@0, KL@2304, VH@4608, VL@6912.
// ---------------------------------------------------------------------------
#define QS2 36
#define KVBUF 9216
#define AKV0 9216
#define ATT_SMEM_U32 (9216 + 2 * KVBUF)   // 27648 u32 = 110592 B

__global__ __launch_bounds__(256, 2) void attn_sp(
    const uint32_t* __restrict__ qh_g, const uint32_t* __restrict__ ql_g,
    const uint32_t* __restrict__ vth,  const uint32_t* __restrict__ vtl,
    uint32_t* __restrict__ atth, uint32_t* __restrict__ attl)
{
    extern __shared__ uint32_t sm[];
    const uint32_t sb = smem_u32(sm);

    const int tid  = threadIdx.x;
    const int lane = tid & 31, warp = tid >> 5;
    const int g = lane >> 2, cq = lane & 3;
    const int b = blockIdx.z, h = blockIdx.y;
    const int bh = b * H + h;
    const int q0 = blockIdx.x * 128;

    const int a_r = lane & 15, a_c = (lane >> 4) * 4;
    const int b_r = lane & 7, b_c = ((lane >> 3) & 1) * 4;
    const uint32_t hl_off = (lane < 16 ? 0u : 2304u);

    // stage Q (group 1)
#pragma unroll
    for (int i = 0; i < 4; i++) {
        int f = tid + i * 256;
        int row = f >> 3, q = (f & 7) * 4;
        size_t src = (size_t)(b * 2048 + q0 + row) * 1536 + h * 32 + q;
        uint32_t dst = sb + (row * QS2 + q) * 4;
        CP_ASYNC16(dst, &qh_g[src]);
        CP_ASYNC16(dst + 4608 * 4, &ql_g[src]);
    }
    CP_COMMIT();

    auto issue_kv = [&](int kb, int buf) {
        const uint32_t kvb = AKV0 + buf * KVBUF;
#pragma unroll
        for (int i = 0; i < 2; i++) {
            int f = tid + i * 256;
            int row = f >> 3, q = (f & 7) * 4;
            size_t ksrc = (size_t)(b * 2048 + kb * 64 + row) * 1536 + 512 + h * 32 + q;
            uint32_t kdst = sb + (kvb + row * QS2 + q) * 4;
            CP_ASYNC16(kdst, &qh_g[ksrc]);
            CP_ASYNC16(kdst + 2304 * 4, &ql_g[ksrc]);
            size_t vsrc = (size_t)(bh * 64 + row) * 1024 + kb * 32 + q;
            uint32_t vdst = sb + (kvb + 4608 + row * QS2 + q) * 4;
            CP_ASYNC16(vdst, &vth[vsrc]);
            CP_ASYNC16(vdst + 2304 * 4, &vtl[vsrc]);
        }
        CP_COMMIT();
    };
    issue_kv(0, 0);

    float m0v = -1e30f, m1v = -1e30f, l0s = 0.0f, l1s = 0.0f;
    float o[8][4];
#pragma unroll
    for (int nt = 0; nt < 8; nt++)
#pragma unroll
        for (int k = 0; k < 4; k++) o[nt][k] = 0.0f;

    const int rb_ = warp * 16;
    const int NKB = N / 64;

    for (int kb = 0; kb < NKB; kb++) {
        CP_WAIT(0);            // Q + kv(kb) landed
        __syncthreads();       // releases WAR on buffer (kb+1)&1
        if (kb + 1 < NKB) issue_kv(kb + 1, (kb + 1) & 1);

        const uint32_t kvb = AKV0 + (kb & 1) * KVBUF;
        const uint32_t k_tile = kvb + hl_off;
        const uint32_t v_tile = kvb + 4608 + hl_off;

        // S = Q @ K^T
        float s[8][4];
#pragma unroll
        for (int nt = 0; nt < 8; nt++)
#pragma unroll
            for (int k = 0; k < 4; k++) s[nt][k] = 0.0f;

#pragma unroll
        for (int kc = 0; kc < 4; kc++) {
            uint32_t qh4[4], ql4[4];
            uint32_t qoff = sb + ((rb_ + a_r) * QS2 + kc * 8 + a_c) * 4;
            ldsm4(qoff, qh4);
            ldsm4(qoff + 4608 * 4, ql4);
#pragma unroll
            for (int nt = 0; nt < 8; nt++) {
                uint32_t koff = sb + (k_tile + (nt * 8 + b_r) * QS2 + kc * 8 + b_c) * 4;
                uint32_t kk[4];
                ldsm4(koff, kk);
                mma16(s[nt], qh4, kk);
                mma16(s[nt], ql4, kk);
                mma16(s[nt], qh4, kk + 2);
            }
        }

        // online softmax -> register P fragments
        float rm0 = -1e30f, rm1 = -1e30f;
#pragma unroll
        for (int nt = 0; nt < 8; nt++) {
            s[nt][0] *= SCALE; s[nt][1] *= SCALE; s[nt][2] *= SCALE; s[nt][3] *= SCALE;
            rm0 = fmaxf(rm0, fmaxf(s[nt][0], s[nt][1]));
            rm1 = fmaxf(rm1, fmaxf(s[nt][2], s[nt][3]));
        }
        rm0 = fmaxf(rm0, __shfl_xor_sync(0xffffffff, rm0, 1));
        rm0 = fmaxf(rm0, __shfl_xor_sync(0xffffffff, rm0, 2));
        rm1 = fmaxf(rm1, __shfl_xor_sync(0xffffffff, rm1, 1));
        rm1 = fmaxf(rm1, __shfl_xor_sync(0xffffffff, rm1, 2));

        float nm0 = fmaxf(m0v, rm0), nm1 = fmaxf(m1v, rm1);
        float a0 = __expf(m0v - nm0), a1 = __expf(m1v - nm1);
        m0v = nm0; m1v = nm1;

        uint32_t phg[8], plg[8], phh[8], plh[8];
        float rs0 = 0.0f, rs1 = 0.0f;
#pragma unroll
        for (int nt = 0; nt < 8; nt++) {
            float p0 = __expf(s[nt][0] - nm0);
            float p1 = __expf(s[nt][1] - nm0);
            float p2 = __expf(s[nt][2] - nm1);
            float p3 = __expf(s[nt][3] - nm1);
            rs0 += p0 + p1;
            rs1 += p2 + p3;
            split2(p0, p1, phg[nt], plg[nt]);
            split2(p2, p3, phh[nt], plh[nt]);
        }
        rs0 += __shfl_xor_sync(0xffffffff, rs0, 1);
        rs0 += __shfl_xor_sync(0xffffffff, rs0, 2);
        rs1 += __shfl_xor_sync(0xffffffff, rs1, 1);
        rs1 += __shfl_xor_sync(0xffffffff, rs1, 2);
        l0s = l0s * a0 + rs0;
        l1s = l1s * a1 + rs1;
#pragma unroll
        for (int nt = 0; nt < 8; nt++) {
            o[nt][0] *= a0; o[nt][1] *= a0; o[nt][2] *= a1; o[nt][3] *= a1;
        }

        // O += P @ V   (P fragments straight from registers)
#pragma unroll
        for (int kcb = 0; kcb < 4; kcb++) {
            uint32_t ah4[4] = {phg[2 * kcb], phh[2 * kcb], phg[2 * kcb + 1], phh[2 * kcb + 1]};
            uint32_t al4[4] = {plg[2 * kcb], plh[2 * kcb], plg[2 * kcb + 1], plh[2 * kcb + 1]};
#pragma unroll
            for (int nt = 0; nt < 8; nt++) {
                uint32_t voff = sb + (v_tile + (nt * 8 + b_r) * QS2 + kcb * 8 + b_c) * 4;
                uint32_t vv[4];
                ldsm4(voff, vv);
                mma16(o[nt], ah4, vv);
                mma16(o[nt], al4, vv);
                mma16(o[nt], ah4, vv + 2);
            }
        }
    }

    // normalize + write split att (d-pairs)
    float inv0 = 1.0f / l0s, inv1 = 1.0f / l1s;
#pragma unroll
    for (int nt = 0; nt < 8; nt++) {
        int wc = h * 32 + nt * 4 + cq;
        size_t r0o = (size_t)(b * 2048 + q0 + rb_ + g) * 512 + wc;
        size_t r1o = (size_t)(b * 2048 + q0 + rb_ + g + 8) * 512 + wc;
        uint32_t hh, ll;
        split2(o[nt][0] * inv0, o[nt][1] * inv0, hh, ll);
        atth[r0o] = hh; attl[r0o] = ll;
        split2(o[nt][2] * inv1, o[nt][3] * inv1, hh, ll);
        atth[r1o] = hh; attl[r1o] = ll;
    }
}

// ---------------------------------------------------------------------------
extern "C" void kernel_launch(void* const* d_in, const int* in_sizes, int n_in,
                              void* d_out, int out_size)
{
    const float* x     = (const float*)d_in[0];
    const float* Wqkv  = (const float*)d_in[1];
    const float* bqkv  = (const float*)d_in[2];
    const float* Wproj = (const float*)d_in[3];
    const float* bproj = (const float*)d_in[4];
    float* out = (float*)d_out;

    void* p;
    uint32_t *xh, *xl, *wqh, *wql, *wph, *wpl, *qh, *ql, *ath, *atl, *vth, *vtl;
    cudaGetSymbolAddress(&p, g_xh);    xh = (uint32_t*)p;
    cudaGetSymbolAddress(&p, g_xl);    xl = (uint32_t*)p;
    cudaGetSymbolAddress(&p, g_wqkvh); wqh = (uint32_t*)p;
    cudaGetSymbolAddress(&p, g_wqkvl); wql = (uint32_t*)p;
    cudaGetSymbolAddress(&p, g_wprojh); wph = (uint32_t*)p;
    cudaGetSymbolAddress(&p, g_wprojl); wpl = (uint32_t*)p;
    cudaGetSymbolAddress(&p, g_qkvh);  qh = (uint32_t*)p;
    cudaGetSymbolAddress(&p, g_qkvl);  ql = (uint32_t*)p;
    cudaGetSymbolAddress(&p, g_atth);  ath = (uint32_t*)p;
    cudaGetSymbolAddress(&p, g_attl);  atl = (uint32_t*)p;
    cudaGetSymbolAddress(&p, g_vth);   vth = (uint32_t*)p;
    cudaGetSymbolAddress(&p, g_vtl);   vtl = (uint32_t*)p;

    cudaFuncSetAttribute(gemm_sp<true>,  cudaFuncAttributeMaxDynamicSharedMemorySize, GSMEM_BYTES);
    cudaFuncSetAttribute(gemm_sp<false>, cudaFuncAttributeMaxDynamicSharedMemorySize, GSMEM_BYTES);
    cudaFuncSetAttribute(attn_sp, cudaFuncAttributeMaxDynamicSharedMemorySize, ATT_SMEM_U32 * 4);

    // prep: split x, transpose+split weights
    split_x_k<<<BN * D / 4 / 256, 256>>>(x, xh, xl);
    wsplit_k<<<dim3(3 * D / 64, D / 64), 256>>>(Wqkv, wqh, wql, D, 3 * D);
    wsplit_k<<<dim3(D / 64, D / 64), 256>>>(Wproj, wph, wpl, D, D);

    // 1) qkv = x @ Wqkv + bqkv  (split output)
    gemm_sp<true><<<dim3(3 * D / 128, BN / 128), 256, GSMEM_BYTES>>>(
        xh, xl, wqh, wql, bqkv, nullptr, qh, ql, BN, 3 * D, D);

    // 1b) build V^T split
    vtrans_k<<<dim3(N / 64, B * H), 256>>>(qh, ql, vth, vtl);

    // 2) attention -> att (split)
    attn_sp<<<dim3(N / 128, H, B), 256, ATT_SMEM_U32 * 4>>>(qh, ql, vth, vtl, ath, atl);

    // 3) out = att @ Wproj + bproj  (fp32 output)
    gemm_sp<false><<<dim3(D / 128, BN / 128), 256, GSMEM_BYTES>>>(
        ath, atl, wph, wpl, bproj, out, nullptr, nullptr, BN, D, D);
}

// round 8
// speedup vs baseline: 4.4117x; 1.1178x over previous
#include <cuda_runtime.h>
#include <cuda_bf16.h>
#include <cuda_fp16.h>
#include <math.h>
#include <stdint.h>

// Problem constants
#define B 4
#define N 2048
#define D 1024
#define H 16
#define HD 64
#define BN (B * N)            // 8192
#define SCALE 0.125f

// Scratch (device globals)
__device__ uint32_t g_xh[BN * 512],      g_xl[BN * 512];       // x split fp16, d-pairs
__device__ uint32_t g_wqkvh[3072 * 512];                       // Wqkv^T fp16 [n][kpair]
__device__ uint32_t g_wprojh[1024 * 512];                      // Wproj^T fp16 [n][kpair]
__device__ uint32_t g_qkvh[BN * 1536],   g_qkvl[BN * 1536];    // qkv split bf16, col-pairs
__device__ uint32_t g_atth[BN * 512],    g_attl[BN * 512];     // att split fp16, d-pairs
__device__ uint32_t g_vth[64 * 64 * 1024], g_vtl[64 * 64 * 1024]; // V^T bf16 [bh][d][keypair]

// ---------------------------------------------------------------------------
// helpers
// ---------------------------------------------------------------------------
__device__ __forceinline__ void split2(float x0, float x1, uint32_t& h, uint32_t& l) {
    __nv_bfloat162 hh = __floats2bfloat162_rn(x0, x1);
    float r0 = x0 - __bfloat162float(hh.x);
    float r1 = x1 - __bfloat162float(hh.y);
    __nv_bfloat162 ll = __floats2bfloat162_rn(r0, r1);
    h = *reinterpret_cast<uint32_t*>(&hh);
    l = *reinterpret_cast<uint32_t*>(&ll);
}
__device__ __forceinline__ void split2h(float x0, float x1, uint32_t& h, uint32_t& l) {
    __half2 hh = __floats2half2_rn(x0, x1);
    float r0 = x0 - __half2float(__low2half(hh));
    float r1 = x1 - __half2float(__high2half(hh));
    __half2 ll = __floats2half2_rn(r0, r1);
    h = *reinterpret_cast<uint32_t*>(&hh);
    l = *reinterpret_cast<uint32_t*>(&ll);
}
__device__ __forceinline__ uint32_t pack_h2(float x0, float x1) {
    __half2 hh = __floats2half2_rn(x0, x1);
    return *reinterpret_cast<uint32_t*>(&hh);
}
// bf16 m16n8k16 mma, fp32 accumulate
__device__ __forceinline__ void mma16(float* c, const uint32_t* a, const uint32_t* b) {
    asm volatile(
        "mma.sync.aligned.m16n8k16.row.col.f32.bf16.bf16.f32 "
        "{%0,%1,%2,%3}, {%4,%5,%6,%7}, {%8,%9}, {%0,%1,%2,%3};"
        : "+f"(c[0]), "+f"(c[1]), "+f"(c[2]), "+f"(c[3])
        : "r"(a[0]), "r"(a[1]), "r"(a[2]), "r"(a[3]), "r"(b[0]), "r"(b[1]));
}
// fp16 m16n8k16 mma, fp32 accumulate
__device__ __forceinline__ void mma16h(float* c, const uint32_t* a, const uint32_t* b) {
    asm volatile(
        "mma.sync.aligned.m16n8k16.row.col.f32.f16.f16.f32 "
        "{%0,%1,%2,%3}, {%4,%5,%6,%7}, {%8,%9}, {%0,%1,%2,%3};"
        : "+f"(c[0]), "+f"(c[1]), "+f"(c[2]), "+f"(c[3])
        : "r"(a[0]), "r"(a[1]), "r"(a[2]), "r"(a[3]), "r"(b[0]), "r"(b[1]));
}
__device__ __forceinline__ void ldsm4(uint32_t addr, uint32_t* r) {
    asm volatile("ldmatrix.sync.aligned.m8n8.x4.shared.b16 {%0,%1,%2,%3}, [%4];"
        : "=r"(r[0]), "=r"(r[1]), "=r"(r[2]), "=r"(r[3]) : "r"(addr));
}
__device__ __forceinline__ uint32_t smem_u32(const void* p) {
    uint32_t a;
    asm("{ .reg .u64 t; cvta.to.shared.u64 t, %1; cvt.u32.u64 %0, t; }" : "=r"(a) : "l"(p));
    return a;
}
#define CP_ASYNC16(dst, src) \
    asm volatile("cp.async.cg.shared.global [%0], [%1], 16;" :: "r"(dst), "l"(src))
#define CP_COMMIT() asm volatile("cp.async.commit_group;" ::: "memory")
#define CP_WAIT(n)  asm volatile("cp.async.wait_group %0;" :: "n"(n) : "memory")

// ---------------------------------------------------------------------------
// split_x: x fp32 -> hi/lo fp16 pairs (d-pairs)
// ---------------------------------------------------------------------------
__global__ void split_x_k(const float* __restrict__ x,
                          uint32_t* __restrict__ xh, uint32_t* __restrict__ xl)
{
    int i = blockIdx.x * blockDim.x + threadIdx.x;
    float4 v = ((const float4*)x)[i];
    uint32_t h0, l0, h1, l1;
    split2h(v.x, v.y, h0, l0);
    split2h(v.z, v.w, h1, l1);
    ((uint2*)xh)[i] = make_uint2(h0, h1);
    ((uint2*)xl)[i] = make_uint2(l0, l1);
}

// ---------------------------------------------------------------------------
// wsplit: W[K][Nn] fp32 -> W^T fp16 (1-piece) [n][kpair]
// ---------------------------------------------------------------------------
__global__ __launch_bounds__(256) void wsplit_k(
    const float* __restrict__ W, uint32_t* __restrict__ Wth,
    int K, int Nn)
{
    __shared__ float sw[64 * 68];
    const int tid = threadIdx.x;
    const int k0 = blockIdx.y * 64, n0 = blockIdx.x * 64;
#pragma unroll
    for (int i = 0; i < 4; i++) {
        int f = tid + i * 256;
        int k = f >> 4, nq = f & 15;
        float4 v = *(const float4*)&W[(size_t)(k0 + k) * Nn + n0 + nq * 4];
        *(float4*)&sw[k * 68 + nq * 4] = v;
    }
    __syncthreads();
    const int n = tid >> 2, kq = tid & 3;
    uint32_t hb[8];
#pragma unroll
    for (int j = 0; j < 8; j++) {
        int kp = kq * 8 + j;
        hb[j] = pack_h2(sw[(2 * kp) * 68 + n], sw[(2 * kp + 1) * 68 + n]);
    }
    size_t o = (size_t)(n0 + n) * (K / 2) + k0 / 2 + kq * 8;
    *(uint4*)&Wth[o]     = make_uint4(hb[0], hb[1], hb[2], hb[3]);
    *(uint4*)&Wth[o + 4] = make_uint4(hb[4], hb[5], hb[6], hb[7]);
}

// ---------------------------------------------------------------------------
// vtrans: qkv split bf16 (v section, d-pairs) -> V^T split bf16 [bh][d][keypair]
// ---------------------------------------------------------------------------
__global__ __launch_bounds__(256) void vtrans_k(
    const uint32_t* __restrict__ qh, const uint32_t* __restrict__ ql,
    uint32_t* __restrict__ vth, uint32_t* __restrict__ vtl)
{
    __shared__ uint32_t sc[2][32 * 66];
    const int tid = threadIdx.x;
    const int kb = blockIdx.x, bh = blockIdx.y;
    const int b = bh >> 4, h = bh & 15;
#pragma unroll
    for (int i = 0; i < 2; i++) {
        int f = tid + i * 256;
        int key = f >> 3, q = (f & 7) * 4;
        size_t src = (size_t)(b * 2048 + kb * 64 + key) * 1536 + 1024 + h * 32 + q;
        uint4 vh = *(const uint4*)&qh[src];
        uint4 vl = *(const uint4*)&ql[src];
        sc[0][(q + 0) * 66 + key] = vh.x; sc[0][(q + 1) * 66 + key] = vh.y;
        sc[0][(q + 2) * 66 + key] = vh.z; sc[0][(q + 3) * 66 + key] = vh.w;
        sc[1][(q + 0) * 66 + key] = vl.x; sc[1][(q + 1) * 66 + key] = vl.y;
        sc[1][(q + 2) * 66 + key] = vl.z; sc[1][(q + 3) * 66 + key] = vl.w;
    }
    __syncthreads();
#pragma unroll
    for (int i = 0; i < 8; i++) {
        int f = tid + i * 256;
        int d = f >> 5, kp = f & 31;
        uint32_t sel = (d & 1) ? 0x7632u : 0x5410u;
        uint2 wh = *(const uint2*)&sc[0][(d >> 1) * 66 + 2 * kp];
        uint2 wl = *(const uint2*)&sc[1][(d >> 1) * 66 + 2 * kp];
        size_t dst = (size_t)(bh * 64 + d) * 1024 + kb * 32 + kp;
        vth[dst] = __byte_perm(wh.x, wh.y, sel);
        vtl[dst] = __byte_perm(wl.x, wl.y, sel);
    }
}

// ---------------------------------------------------------------------------
// GEMM fp16 2-term: C = A @ W + bias, A = ah+al (fp16 pieces), W = wh (fp16).
// 128x128 tile, BK=32 (16 kpairs), 256 thr, warps 4(m)x2(n), warp 32x64.
// smem/buf: Ah, Al, Bh each [128][20] u32 -> 7680 u32/buf, 2 bufs = 61440 B.
// Single-barrier-per-chunk double-buffered pipeline.
// ---------------------------------------------------------------------------
#define TSTR 20
#define TILE_U32 2560
#define BUF2_U32 7680
#define G2SMEM_BYTES (2 * BUF2_U32 * 4)

template <bool SPLIT_OUT>
__global__ __launch_bounds__(256, 2) void gemm_2t(
    const uint32_t* __restrict__ Ah_g, const uint32_t* __restrict__ Al_g,
    const uint32_t* __restrict__ Bh_g,
    const float* __restrict__ bias,
    float* __restrict__ C, uint32_t* __restrict__ Ch, uint32_t* __restrict__ Cl,
    int M, int Nn, int K)
{
    extern __shared__ uint32_t sm[];
    const uint32_t sb = smem_u32(sm);
    const int tid = threadIdx.x;
    const int lane = tid & 31, warp = tid >> 5;
    const int g = lane >> 2, cq = lane & 3;
    const int wm = (warp >> 1) * 32, wn = (warp & 1) * 64;
    const int m0 = blockIdx.y * 128, n0 = blockIdx.x * 128;
    const int kwtot = K / 2;

    const int a_r = lane & 15, a_c = (lane >> 4) * 4;

    float acc[2][8][4];
#pragma unroll
    for (int mt = 0; mt < 2; mt++)
#pragma unroll
        for (int nt = 0; nt < 8; nt++)
#pragma unroll
            for (int k = 0; k < 4; k++) acc[mt][nt][k] = 0.0f;

    auto issue = [&](int c, int buf) {
        const int kw = c * 16;
        const uint32_t bb = sb + buf * (BUF2_U32 * 4);
#pragma unroll
        for (int i = 0; i < 2; i++) {
            int f = tid + i * 256;
            int r = f >> 2, q = (f & 3) * 4;
            uint32_t d0 = bb + (r * TSTR + q) * 4;
            CP_ASYNC16(d0,                &Ah_g[(size_t)(m0 + r) * kwtot + kw + q]);
            CP_ASYNC16(d0 + TILE_U32 * 4, &Al_g[(size_t)(m0 + r) * kwtot + kw + q]);
            CP_ASYNC16(d0 + TILE_U32 * 8, &Bh_g[(size_t)(n0 + r) * kwtot + kw + q]);
        }
        CP_COMMIT();
    };

    const int nch = K / 32;
    issue(0, 0);
    for (int c = 0; c < nch; c++) {
        CP_WAIT(0);
        __syncthreads();
        if (c + 1 < nch) issue(c + 1, (c + 1) & 1);

        const uint32_t bufb = sb + (c & 1) * (BUF2_U32 * 4);
#pragma unroll
        for (int kc = 0; kc < 2; kc++) {
            uint32_t ah[2][4], al[2][4];
#pragma unroll
            for (int mt = 0; mt < 2; mt++) {
                uint32_t aoff = bufb + ((wm + mt * 16 + a_r) * TSTR + kc * 8 + a_c) * 4;
                ldsm4(aoff, ah[mt]);
                ldsm4(aoff + TILE_U32 * 4, al[mt]);
            }
#pragma unroll
            for (int ntp = 0; ntp < 4; ntp++) {
                uint32_t boff = bufb + TILE_U32 * 8 +
                                ((wn + ntp * 16 + a_r) * TSTR + kc * 8 + a_c) * 4;
                uint32_t b4[4];
                ldsm4(boff, b4);
                uint32_t b0[2] = {b4[0], b4[2]};   // n-tile 2*ntp
                uint32_t b1[2] = {b4[1], b4[3]};   // n-tile 2*ntp+1
#pragma unroll
                for (int mt = 0; mt < 2; mt++) mma16h(acc[mt][2 * ntp], ah[mt], b0);
#pragma unroll
                for (int mt = 0; mt < 2; mt++) mma16h(acc[mt][2 * ntp + 1], ah[mt], b1);
#pragma unroll
                for (int mt = 0; mt < 2; mt++) mma16h(acc[mt][2 * ntp], al[mt], b0);
#pragma unroll
                for (int mt = 0; mt < 2; mt++) mma16h(acc[mt][2 * ntp + 1], al[mt], b1);
            }
        }
    }

#pragma unroll
    for (int mt = 0; mt < 2; mt++) {
#pragma unroll
        for (int nt = 0; nt < 8; nt++) {
            int row = m0 + wm + mt * 16 + g;
            int col = n0 + wn + nt * 8 + 2 * cq;
            float b0 = bias[col], b1 = bias[col + 1];
            float v00 = acc[mt][nt][0] + b0, v01 = acc[mt][nt][1] + b1;
            float v10 = acc[mt][nt][2] + b0, v11 = acc[mt][nt][3] + b1;
            if (SPLIT_OUT) {
                int wc = col >> 1;
                uint32_t hh, ll;
                split2(v00, v01, hh, ll);          // bf16 pairs for attention
                Ch[(size_t)row * (Nn / 2) + wc] = hh;
                Cl[(size_t)row * (Nn / 2) + wc] = ll;
                split2(v10, v11, hh, ll);
                Ch[(size_t)(row + 8) * (Nn / 2) + wc] = hh;
                Cl[(size_t)(row + 8) * (Nn / 2) + wc] = ll;
            } else {
                *(float2*)&C[(size_t)row * Nn + col] = make_float2(v00, v01);
                *(float2*)&C[(size_t)(row + 8) * Nn + col] = make_float2(v10, v11);
            }
        }
    }
}

// ---------------------------------------------------------------------------
// Attention (3xBF16 flash): register-resident P, double-buffered K/V,
// one barrier per key-tile. Output att split to fp16 pairs (for gemm_2t).
// ---------------------------------------------------------------------------
#define QS2 36
#define KVBUF 9216
#define AKV0 9216
#define ATT_SMEM_U32 (9216 + 2 * KVBUF)   // 27648 u32 = 110592 B

__global__ __launch_bounds__(256, 2) void attn_sp(
    const uint32_t* __restrict__ qh_g, const uint32_t* __restrict__ ql_g,
    const uint32_t* __restrict__ vth,  const uint32_t* __restrict__ vtl,
    uint32_t* __restrict__ atth, uint32_t* __restrict__ attl)
{
    extern __shared__ uint32_t sm[];
    const uint32_t sb = smem_u32(sm);

    const int tid  = threadIdx.x;
    const int lane = tid & 31, warp = tid >> 5;
    const int g = lane >> 2, cq = lane & 3;
    const int b = blockIdx.z, h = blockIdx.y;
    const int bh = b * H + h;
    const int q0 = blockIdx.x * 128;

    const int a_r = lane & 15, a_c = (lane >> 4) * 4;
    const int b_r = lane & 7, b_c = ((lane >> 3) & 1) * 4;
    const uint32_t hl_off = (lane < 16 ? 0u : 2304u);

    // stage Q
#pragma unroll
    for (int i = 0; i < 4; i++) {
        int f = tid + i * 256;
        int row = f >> 3, q = (f & 7) * 4;
        size_t src = (size_t)(b * 2048 + q0 + row) * 1536 + h * 32 + q;
        uint32_t dst = sb + (row * QS2 + q) * 4;
        CP_ASYNC16(dst, &qh_g[src]);
        CP_ASYNC16(dst + 4608 * 4, &ql_g[src]);
    }
    CP_COMMIT();

    auto issue_kv = [&](int kb, int buf) {
        const uint32_t kvb = AKV0 + buf * KVBUF;
#pragma unroll
        for (int i = 0; i < 2; i++) {
            int f = tid + i * 256;
            int row = f >> 3, q = (f & 7) * 4;
            size_t ksrc = (size_t)(b * 2048 + kb * 64 + row) * 1536 + 512 + h * 32 + q;
            uint32_t kdst = sb + (kvb + row * QS2 + q) * 4;
            CP_ASYNC16(kdst, &qh_g[ksrc]);
            CP_ASYNC16(kdst + 2304 * 4, &ql_g[ksrc]);
            size_t vsrc = (size_t)(bh * 64 + row) * 1024 + kb * 32 + q;
            uint32_t vdst = sb + (kvb + 4608 + row * QS2 + q) * 4;
            CP_ASYNC16(vdst, &vth[vsrc]);
            CP_ASYNC16(vdst + 2304 * 4, &vtl[vsrc]);
        }
        CP_COMMIT();
    };
    issue_kv(0, 0);

    float m0v = -1e30f, m1v = -1e30f, l0s = 0.0f, l1s = 0.0f;
    float o[8][4];
#pragma unroll
    for (int nt = 0; nt < 8; nt++)
#pragma unroll
        for (int k = 0; k < 4; k++) o[nt][k] = 0.0f;

    const int rb_ = warp * 16;
    const int NKB = N / 64;

    for (int kb = 0; kb < NKB; kb++) {
        CP_WAIT(0);
        __syncthreads();
        if (kb + 1 < NKB) issue_kv(kb + 1, (kb + 1) & 1);

        const uint32_t kvb = AKV0 + (kb & 1) * KVBUF;
        const uint32_t k_tile = kvb + hl_off;
        const uint32_t v_tile = kvb + 4608 + hl_off;

        // S = Q @ K^T
        float s[8][4];
#pragma unroll
        for (int nt = 0; nt < 8; nt++)
#pragma unroll
            for (int k = 0; k < 4; k++) s[nt][k] = 0.0f;

#pragma unroll
        for (int kc = 0; kc < 4; kc++) {
            uint32_t qh4[4], ql4[4];
            uint32_t qoff = sb + ((rb_ + a_r) * QS2 + kc * 8 + a_c) * 4;
            ldsm4(qoff, qh4);
            ldsm4(qoff + 4608 * 4, ql4);
#pragma unroll
            for (int nt = 0; nt < 8; nt++) {
                uint32_t koff = sb + (k_tile + (nt * 8 + b_r) * QS2 + kc * 8 + b_c) * 4;
                uint32_t kk[4];
                ldsm4(koff, kk);
                mma16(s[nt], qh4, kk);
                mma16(s[nt], ql4, kk);
                mma16(s[nt], qh4, kk + 2);
            }
        }

        // online softmax -> register P fragments
        float rm0 = -1e30f, rm1 = -1e30f;
#pragma unroll
        for (int nt = 0; nt < 8; nt++) {
            s[nt][0] *= SCALE; s[nt][1] *= SCALE; s[nt][2] *= SCALE; s[nt][3] *= SCALE;
            rm0 = fmaxf(rm0, fmaxf(s[nt][0], s[nt][1]));
            rm1 = fmaxf(rm1, fmaxf(s[nt][2], s[nt][3]));
        }
        rm0 = fmaxf(rm0, __shfl_xor_sync(0xffffffff, rm0, 1));
        rm0 = fmaxf(rm0, __shfl_xor_sync(0xffffffff, rm0, 2));
        rm1 = fmaxf(rm1, __shfl_xor_sync(0xffffffff, rm1, 1));
        rm1 = fmaxf(rm1, __shfl_xor_sync(0xffffffff, rm1, 2));

        float nm0 = fmaxf(m0v, rm0), nm1 = fmaxf(m1v, rm1);
        float a0 = __expf(m0v - nm0), a1 = __expf(m1v - nm1);
        m0v = nm0; m1v = nm1;

        uint32_t phg[8], plg[8], phh[8], plh[8];
        float rs0 = 0.0f, rs1 = 0.0f;
#pragma unroll
        for (int nt = 0; nt < 8; nt++) {
            float p0 = __expf(s[nt][0] - nm0);
            float p1 = __expf(s[nt][1] - nm0);
            float p2 = __expf(s[nt][2] - nm1);
            float p3 = __expf(s[nt][3] - nm1);
            rs0 += p0 + p1;
            rs1 += p2 + p3;
            split2(p0, p1, phg[nt], plg[nt]);
            split2(p2, p3, phh[nt], plh[nt]);
        }
        rs0 += __shfl_xor_sync(0xffffffff, rs0, 1);
        rs0 += __shfl_xor_sync(0xffffffff, rs0, 2);
        rs1 += __shfl_xor_sync(0xffffffff, rs1, 1);
        rs1 += __shfl_xor_sync(0xffffffff, rs1, 2);
        l0s = l0s * a0 + rs0;
        l1s = l1s * a1 + rs1;
#pragma unroll
        for (int nt = 0; nt < 8; nt++) {
            o[nt][0] *= a0; o[nt][1] *= a0; o[nt][2] *= a1; o[nt][3] *= a1;
        }

        // O += P @ V
#pragma unroll
        for (int kcb = 0; kcb < 4; kcb++) {
            uint32_t ah4[4] = {phg[2 * kcb], phh[2 * kcb], phg[2 * kcb + 1], phh[2 * kcb + 1]};
            uint32_t al4[4] = {plg[2 * kcb], plh[2 * kcb], plg[2 * kcb + 1], plh[2 * kcb + 1]};
#pragma unroll
            for (int nt = 0; nt < 8; nt++) {
                uint32_t voff = sb + (v_tile + (nt * 8 + b_r) * QS2 + kcb * 8 + b_c) * 4;
                uint32_t vv[4];
                ldsm4(voff, vv);
                mma16(o[nt], ah4, vv);
                mma16(o[nt], al4, vv);
                mma16(o[nt], ah4, vv + 2);
            }
        }
    }

    // normalize + write split att (fp16 d-pairs, feeds gemm_2t)
    float inv0 = 1.0f / l0s, inv1 = 1.0f / l1s;
#pragma unroll
    for (int nt = 0; nt < 8; nt++) {
        int wc = h * 32 + nt * 4 + cq;
        size_t r0o = (size_t)(b * 2048 + q0 + rb_ + g) * 512 + wc;
        size_t r1o = (size_t)(b * 2048 + q0 + rb_ + g + 8) * 512 + wc;
        uint32_t hh, ll;
        split2h(o[nt][0] * inv0, o[nt][1] * inv0, hh, ll);
        atth[r0o] = hh; attl[r0o] = ll;
        split2h(o[nt][2] * inv1, o[nt][3] * inv1, hh, ll);
        atth[r1o] = hh; attl[r1o] = ll;
    }
}

// ---------------------------------------------------------------------------
extern "C" void kernel_launch(void* const* d_in, const int* in_sizes, int n_in,
                              void* d_out, int out_size)
{
    const float* x     = (const float*)d_in[0];
    const float* Wqkv  = (const float*)d_in[1];
    const float* bqkv  = (const float*)d_in[2];
    const float* Wproj = (const float*)d_in[3];
    const float* bproj = (const float*)d_in[4];
    float* out = (float*)d_out;

    void* p;
    uint32_t *xh, *xl, *wqh, *wph, *qh, *ql, *ath, *atl, *vth, *vtl;
    cudaGetSymbolAddress(&p, g_xh);    xh = (uint32_t*)p;
    cudaGetSymbolAddress(&p, g_xl);    xl = (uint32_t*)p;
    cudaGetSymbolAddress(&p, g_wqkvh); wqh = (uint32_t*)p;
    cudaGetSymbolAddress(&p, g_wprojh); wph = (uint32_t*)p;
    cudaGetSymbolAddress(&p, g_qkvh);  qh = (uint32_t*)p;
    cudaGetSymbolAddress(&p, g_qkvl);  ql = (uint32_t*)p;
    cudaGetSymbolAddress(&p, g_atth);  ath = (uint32_t*)p;
    cudaGetSymbolAddress(&p, g_attl);  atl = (uint32_t*)p;
    cudaGetSymbolAddress(&p, g_vth);   vth = (uint32_t*)p;
    cudaGetSymbolAddress(&p, g_vtl);   vtl = (uint32_t*)p;

    cudaFuncSetAttribute(gemm_2t<true>,  cudaFuncAttributeMaxDynamicSharedMemorySize, G2SMEM_BYTES);
    cudaFuncSetAttribute(gemm_2t<false>, cudaFuncAttributeMaxDynamicSharedMemorySize, G2SMEM_BYTES);
    cudaFuncSetAttribute(attn_sp, cudaFuncAttributeMaxDynamicSharedMemorySize, ATT_SMEM_U32 * 4);

    // prep: split x (fp16), transpose+convert weights (fp16, 1-piece)
    split_x_k<<<BN * D / 4 / 256, 256>>>(x, xh, xl);
    wsplit_k<<<dim3(3 * D / 64, D / 64), 256>>>(Wqkv, wqh, D, 3 * D);
    wsplit_k<<<dim3(D / 64, D / 64), 256>>>(Wproj, wph, D, D);

    // 1) qkv = x @ Wqkv + bqkv  (fp16 2-term; bf16-split output)
    gemm_2t<true><<<dim3(3 * D / 128, BN / 128), 256, G2SMEM_BYTES>>>(
        xh, xl, wqh, bqkv, nullptr, qh, ql, BN, 3 * D, D);

    // 1b) build V^T split (bf16)
    vtrans_k<<<dim3(N / 64, B * H), 256>>>(qh, ql, vth, vtl);

    // 2) attention -> att (fp16-split output)
    attn_sp<<<dim3(N / 128, H, B), 256, ATT_SMEM_U32 * 4>>>(qh, ql, vth, vtl, ath, atl);

    // 3) out = att @ Wproj + bproj  (fp16 2-term; fp32 output)
    gemm_2t<false><<<dim3(D / 128, BN / 128), 256, G2SMEM_BYTES>>>(
        ath, atl, wph, bproj, out, nullptr, nullptr, BN, D, D);
}

// round 9
// speedup vs baseline: 5.0047x; 1.1344x over previous
#include <cuda_runtime.h>
#include <cuda_bf16.h>
#include <cuda_fp16.h>
#include <math.h>
#include <stdint.h>

// Problem constants
#define B 4
#define N 2048
#define D 1024
#define H 16
#define HD 64
#define BN (B * N)            // 8192
#define SCALE 0.125f

// Scratch (device globals; u32 = packed fp16x2)
__device__ uint32_t g_xh[BN * 512],      g_xl[BN * 512];       // x split fp16, d-pairs
__device__ uint32_t g_wqkvh[3072 * 512];                       // Wqkv^T fp16 [n][kpair]
__device__ uint32_t g_wprojh[1024 * 512];                      // Wproj^T fp16 [n][kpair]
__device__ uint32_t g_qkvh[BN * 1536],   g_qkvl[BN * 1536];    // qkv split fp16, col-pairs
__device__ uint32_t g_atth[BN * 512],    g_attl[BN * 512];     // att split fp16, d-pairs
__device__ uint32_t g_vth[64 * 64 * 1024];                     // V^T fp16 [bh][d][keypair]

// ---------------------------------------------------------------------------
// helpers
// ---------------------------------------------------------------------------
__device__ __forceinline__ void split2h(float x0, float x1, uint32_t& h, uint32_t& l) {
    __half2 hh = __floats2half2_rn(x0, x1);
    float r0 = x0 - __half2float(__low2half(hh));
    float r1 = x1 - __half2float(__high2half(hh));
    __half2 ll = __floats2half2_rn(r0, r1);
    h = *reinterpret_cast<uint32_t*>(&hh);
    l = *reinterpret_cast<uint32_t*>(&ll);
}
__device__ __forceinline__ uint32_t pack_h2(float x0, float x1) {
    __half2 hh = __floats2half2_rn(x0, x1);
    return *reinterpret_cast<uint32_t*>(&hh);
}
// fp16 m16n8k16 mma, fp32 accumulate
__device__ __forceinline__ void mma16h(float* c, const uint32_t* a, const uint32_t* b) {
    asm volatile(
        "mma.sync.aligned.m16n8k16.row.col.f32.f16.f16.f32 "
        "{%0,%1,%2,%3}, {%4,%5,%6,%7}, {%8,%9}, {%0,%1,%2,%3};"
        : "+f"(c[0]), "+f"(c[1]), "+f"(c[2]), "+f"(c[3])
        : "r"(a[0]), "r"(a[1]), "r"(a[2]), "r"(a[3]), "r"(b[0]), "r"(b[1]));
}
__device__ __forceinline__ void ldsm4(uint32_t addr, uint32_t* r) {
    asm volatile("ldmatrix.sync.aligned.m8n8.x4.shared.b16 {%0,%1,%2,%3}, [%4];"
        : "=r"(r[0]), "=r"(r[1]), "=r"(r[2]), "=r"(r[3]) : "r"(addr));
}
__device__ __forceinline__ uint32_t smem_u32(const void* p) {
    uint32_t a;
    asm("{ .reg .u64 t; cvta.to.shared.u64 t, %1; cvt.u32.u64 %0, t; }" : "=r"(a) : "l"(p));
    return a;
}
#define CP_ASYNC16(dst, src) \
    asm volatile("cp.async.cg.shared.global [%0], [%1], 16;" :: "r"(dst), "l"(src))
#define CP_COMMIT() asm volatile("cp.async.commit_group;" ::: "memory")
#define CP_WAIT(n)  asm volatile("cp.async.wait_group %0;" :: "n"(n) : "memory")

// ---------------------------------------------------------------------------
// split_x: x fp32 -> hi/lo fp16 pairs (d-pairs)
// ---------------------------------------------------------------------------
__global__ void split_x_k(const float* __restrict__ x,
                          uint32_t* __restrict__ xh, uint32_t* __restrict__ xl)
{
    int i = blockIdx.x * blockDim.x + threadIdx.x;
    float4 v = ((const float4*)x)[i];
    uint32_t h0, l0, h1, l1;
    split2h(v.x, v.y, h0, l0);
    split2h(v.z, v.w, h1, l1);
    ((uint2*)xh)[i] = make_uint2(h0, h1);
    ((uint2*)xl)[i] = make_uint2(l0, l1);
}

// ---------------------------------------------------------------------------
// wsplit: W[K][Nn] fp32 -> W^T fp16 (1-piece) [n][kpair]
// ---------------------------------------------------------------------------
__global__ __launch_bounds__(256) void wsplit_k(
    const float* __restrict__ W, uint32_t* __restrict__ Wth,
    int K, int Nn)
{
    __shared__ float sw[64 * 68];
    const int tid = threadIdx.x;
    const int k0 = blockIdx.y * 64, n0 = blockIdx.x * 64;
#pragma unroll
    for (int i = 0; i < 4; i++) {
        int f = tid + i * 256;
        int k = f >> 4, nq = f & 15;
        float4 v = *(const float4*)&W[(size_t)(k0 + k) * Nn + n0 + nq * 4];
        *(float4*)&sw[k * 68 + nq * 4] = v;
    }
    __syncthreads();
    const int n = tid >> 2, kq = tid & 3;
    uint32_t hb[8];
#pragma unroll
    for (int j = 0; j < 8; j++) {
        int kp = kq * 8 + j;
        hb[j] = pack_h2(sw[(2 * kp) * 68 + n], sw[(2 * kp + 1) * 68 + n]);
    }
    size_t o = (size_t)(n0 + n) * (K / 2) + k0 / 2 + kq * 8;
    *(uint4*)&Wth[o]     = make_uint4(hb[0], hb[1], hb[2], hb[3]);
    *(uint4*)&Wth[o + 4] = make_uint4(hb[4], hb[5], hb[6], hb[7]);
}

// ---------------------------------------------------------------------------
// vtrans: qkv hi (v section, d-pairs fp16) -> V^T fp16 [bh][d][keypair]
// ---------------------------------------------------------------------------
__global__ __launch_bounds__(256) void vtrans_k(
    const uint32_t* __restrict__ qh, uint32_t* __restrict__ vth)
{
    __shared__ uint32_t sc[32 * 66];
    const int tid = threadIdx.x;
    const int kb = blockIdx.x, bh = blockIdx.y;
    const int b = bh >> 4, h = bh & 15;
#pragma unroll
    for (int i = 0; i < 2; i++) {
        int f = tid + i * 256;
        int key = f >> 3, q = (f & 7) * 4;
        size_t src = (size_t)(b * 2048 + kb * 64 + key) * 1536 + 1024 + h * 32 + q;
        uint4 vh = *(const uint4*)&qh[src];
        sc[(q + 0) * 66 + key] = vh.x; sc[(q + 1) * 66 + key] = vh.y;
        sc[(q + 2) * 66 + key] = vh.z; sc[(q + 3) * 66 + key] = vh.w;
    }
    __syncthreads();
#pragma unroll
    for (int i = 0; i < 8; i++) {
        int f = tid + i * 256;
        int d = f >> 5, kp = f & 31;
        uint32_t sel = (d & 1) ? 0x7632u : 0x5410u;
        uint2 wh = *(const uint2*)&sc[(d >> 1) * 66 + 2 * kp];
        size_t dst = (size_t)(bh * 64 + d) * 1024 + kb * 32 + kp;
        vth[dst] = __byte_perm(wh.x, wh.y, sel);
    }
}

// ---------------------------------------------------------------------------
// GEMM fp16 2-term: C = A @ W + bias, A = ah+al (fp16 pieces), W = wh (fp16).
// 128x128 tile, BK=32 (16 kpairs), 256 thr, warps 4(m)x2(n), warp 32x64.
// Single-barrier-per-chunk double-buffered pipeline.
// ---------------------------------------------------------------------------
#define TSTR 20
#define TILE_U32 2560
#define BUF2_U32 7680
#define G2SMEM_BYTES (2 * BUF2_U32 * 4)

template <bool SPLIT_OUT>
__global__ __launch_bounds__(256, 2) void gemm_2t(
    const uint32_t* __restrict__ Ah_g, const uint32_t* __restrict__ Al_g,
    const uint32_t* __restrict__ Bh_g,
    const float* __restrict__ bias,
    float* __restrict__ C, uint32_t* __restrict__ Ch, uint32_t* __restrict__ Cl,
    int M, int Nn, int K)
{
    extern __shared__ uint32_t sm[];
    const uint32_t sb = smem_u32(sm);
    const int tid = threadIdx.x;
    const int lane = tid & 31, warp = tid >> 5;
    const int g = lane >> 2, cq = lane & 3;
    const int wm = (warp >> 1) * 32, wn = (warp & 1) * 64;
    const int m0 = blockIdx.y * 128, n0 = blockIdx.x * 128;
    const int kwtot = K / 2;

    const int a_r = lane & 15, a_c = (lane >> 4) * 4;

    float acc[2][8][4];
#pragma unroll
    for (int mt = 0; mt < 2; mt++)
#pragma unroll
        for (int nt = 0; nt < 8; nt++)
#pragma unroll
            for (int k = 0; k < 4; k++) acc[mt][nt][k] = 0.0f;

    auto issue = [&](int c, int buf) {
        const int kw = c * 16;
        const uint32_t bb = sb + buf * (BUF2_U32 * 4);
#pragma unroll
        for (int i = 0; i < 2; i++) {
            int f = tid + i * 256;
            int r = f >> 2, q = (f & 3) * 4;
            uint32_t d0 = bb + (r * TSTR + q) * 4;
            CP_ASYNC16(d0,                &Ah_g[(size_t)(m0 + r) * kwtot + kw + q]);
            CP_ASYNC16(d0 + TILE_U32 * 4, &Al_g[(size_t)(m0 + r) * kwtot + kw + q]);
            CP_ASYNC16(d0 + TILE_U32 * 8, &Bh_g[(size_t)(n0 + r) * kwtot + kw + q]);
        }
        CP_COMMIT();
    };

    const int nch = K / 32;
    issue(0, 0);
    for (int c = 0; c < nch; c++) {
        CP_WAIT(0);
        __syncthreads();
        if (c + 1 < nch) issue(c + 1, (c + 1) & 1);

        const uint32_t bufb = sb + (c & 1) * (BUF2_U32 * 4);
#pragma unroll
        for (int kc = 0; kc < 2; kc++) {
            uint32_t ah[2][4], al[2][4];
#pragma unroll
            for (int mt = 0; mt < 2; mt++) {
                uint32_t aoff = bufb + ((wm + mt * 16 + a_r) * TSTR + kc * 8 + a_c) * 4;
                ldsm4(aoff, ah[mt]);
                ldsm4(aoff + TILE_U32 * 4, al[mt]);
            }
#pragma unroll
            for (int ntp = 0; ntp < 4; ntp++) {
                uint32_t boff = bufb + TILE_U32 * 8 +
                                ((wn + ntp * 16 + a_r) * TSTR + kc * 8 + a_c) * 4;
                uint32_t b4[4];
                ldsm4(boff, b4);
                uint32_t b0[2] = {b4[0], b4[2]};
                uint32_t b1[2] = {b4[1], b4[3]};
#pragma unroll
                for (int mt = 0; mt < 2; mt++) mma16h(acc[mt][2 * ntp], ah[mt], b0);
#pragma unroll
                for (int mt = 0; mt < 2; mt++) mma16h(acc[mt][2 * ntp + 1], ah[mt], b1);
#pragma unroll
                for (int mt = 0; mt < 2; mt++) mma16h(acc[mt][2 * ntp], al[mt], b0);
#pragma unroll
                for (int mt = 0; mt < 2; mt++) mma16h(acc[mt][2 * ntp + 1], al[mt], b1);
            }
        }
    }

#pragma unroll
    for (int mt = 0; mt < 2; mt++) {
#pragma unroll
        for (int nt = 0; nt < 8; nt++) {
            int row = m0 + wm + mt * 16 + g;
            int col = n0 + wn + nt * 8 + 2 * cq;
            float b0 = bias[col], b1 = bias[col + 1];
            float v00 = acc[mt][nt][0] + b0, v01 = acc[mt][nt][1] + b1;
            float v10 = acc[mt][nt][2] + b0, v11 = acc[mt][nt][3] + b1;
            if (SPLIT_OUT) {
                int wc = col >> 1;
                uint32_t hh, ll;
                split2h(v00, v01, hh, ll);         // fp16 pairs for attention
                Ch[(size_t)row * (Nn / 2) + wc] = hh;
                Cl[(size_t)row * (Nn / 2) + wc] = ll;
                split2h(v10, v11, hh, ll);
                Ch[(size_t)(row + 8) * (Nn / 2) + wc] = hh;
                Cl[(size_t)(row + 8) * (Nn / 2) + wc] = ll;
            } else {
                *(float2*)&C[(size_t)row * Nn + col] = make_float2(v00, v01);
                *(float2*)&C[(size_t)(row + 8) * Nn + col] = make_float2(v10, v11);
            }
        }
    }
}

// ---------------------------------------------------------------------------
// Attention (fp16 2-term flash): Q,P split fp16 hi/lo; K,V single fp16.
// Register-resident P, double-buffered K/V, one barrier per key-tile.
// smem u32: Qh@0 (4608), Ql@4608 (4608), 2 KV bufs of 4608: KH@0, VH@2304.
// ---------------------------------------------------------------------------
#define QS2 36
#define KVBUF 4608
#define AKV0 9216
#define ATT_SMEM_U32 (9216 + 2 * KVBUF)   // 18432 u32 = 73728 B

__global__ __launch_bounds__(256, 2) void attn_sp(
    const uint32_t* __restrict__ qh_g, const uint32_t* __restrict__ ql_g,
    const uint32_t* __restrict__ vth,
    uint32_t* __restrict__ atth, uint32_t* __restrict__ attl)
{
    extern __shared__ uint32_t sm[];
    const uint32_t sb = smem_u32(sm);

    const int tid  = threadIdx.x;
    const int lane = tid & 31, warp = tid >> 5;
    const int g = lane >> 2, cq = lane & 3;
    const int b = blockIdx.z, h = blockIdx.y;
    const int bh = b * H + h;
    const int q0 = blockIdx.x * 128;

    const int a_r = lane & 15, a_c = (lane >> 4) * 4;

    // stage Q (hi+lo)
#pragma unroll
    for (int i = 0; i < 4; i++) {
        int f = tid + i * 256;
        int row = f >> 3, q = (f & 7) * 4;
        size_t src = (size_t)(b * 2048 + q0 + row) * 1536 + h * 32 + q;
        uint32_t dst = sb + (row * QS2 + q) * 4;
        CP_ASYNC16(dst, &qh_g[src]);
        CP_ASYNC16(dst + 4608 * 4, &ql_g[src]);
    }
    CP_COMMIT();

    auto issue_kv = [&](int kb, int buf) {
        const uint32_t kvb = AKV0 + buf * KVBUF;
#pragma unroll
        for (int i = 0; i < 2; i++) {
            int f = tid + i * 256;
            int row = f >> 3, q = (f & 7) * 4;
            size_t ksrc = (size_t)(b * 2048 + kb * 64 + row) * 1536 + 512 + h * 32 + q;
            CP_ASYNC16(sb + (kvb + row * QS2 + q) * 4, &qh_g[ksrc]);
            size_t vsrc = (size_t)(bh * 64 + row) * 1024 + kb * 32 + q;
            CP_ASYNC16(sb + (kvb + 2304 + row * QS2 + q) * 4, &vth[vsrc]);
        }
        CP_COMMIT();
    };
    issue_kv(0, 0);

    float m0v = -1e30f, m1v = -1e30f, l0s = 0.0f, l1s = 0.0f;
    float o[8][4];
#pragma unroll
    for (int nt = 0; nt < 8; nt++)
#pragma unroll
        for (int k = 0; k < 4; k++) o[nt][k] = 0.0f;

    const int rb_ = warp * 16;
    const int NKB = N / 64;

    for (int kb = 0; kb < NKB; kb++) {
        CP_WAIT(0);
        __syncthreads();
        if (kb + 1 < NKB) issue_kv(kb + 1, (kb + 1) & 1);

        const uint32_t kvb = AKV0 + (kb & 1) * KVBUF;

        // S = Q @ K^T   (2-term: qh*kh + ql*kh)
        float s[8][4];
#pragma unroll
        for (int nt = 0; nt < 8; nt++)
#pragma unroll
            for (int k = 0; k < 4; k++) s[nt][k] = 0.0f;

#pragma unroll
        for (int kc = 0; kc < 4; kc++) {
            uint32_t qh4[4], ql4[4];
            uint32_t qoff = sb + ((rb_ + a_r) * QS2 + kc * 8 + a_c) * 4;
            ldsm4(qoff, qh4);
            ldsm4(qoff + 4608 * 4, ql4);
#pragma unroll
            for (int ntp = 0; ntp < 4; ntp++) {
                uint32_t koff = sb + (kvb + (ntp * 16 + a_r) * QS2 + kc * 8 + a_c) * 4;
                uint32_t k4[4];
                ldsm4(koff, k4);
                uint32_t k0[2] = {k4[0], k4[2]};
                uint32_t k1[2] = {k4[1], k4[3]};
                mma16h(s[2 * ntp], qh4, k0);
                mma16h(s[2 * ntp + 1], qh4, k1);
                mma16h(s[2 * ntp], ql4, k0);
                mma16h(s[2 * ntp + 1], ql4, k1);
            }
        }

        // online softmax -> register P fragments (fp16 hi/lo)
        float rm0 = -1e30f, rm1 = -1e30f;
#pragma unroll
        for (int nt = 0; nt < 8; nt++) {
            s[nt][0] *= SCALE; s[nt][1] *= SCALE; s[nt][2] *= SCALE; s[nt][3] *= SCALE;
            rm0 = fmaxf(rm0, fmaxf(s[nt][0], s[nt][1]));
            rm1 = fmaxf(rm1, fmaxf(s[nt][2], s[nt][3]));
        }
        rm0 = fmaxf(rm0, __shfl_xor_sync(0xffffffff, rm0, 1));
        rm0 = fmaxf(rm0, __shfl_xor_sync(0xffffffff, rm0, 2));
        rm1 = fmaxf(rm1, __shfl_xor_sync(0xffffffff, rm1, 1));
        rm1 = fmaxf(rm1, __shfl_xor_sync(0xffffffff, rm1, 2));

        float nm0 = fmaxf(m0v, rm0), nm1 = fmaxf(m1v, rm1);
        float a0 = __expf(m0v - nm0), a1 = __expf(m1v - nm1);
        m0v = nm0; m1v = nm1;

        uint32_t phg[8], plg[8], phh[8], plh[8];
        float rs0 = 0.0f, rs1 = 0.0f;
#pragma unroll
        for (int nt = 0; nt < 8; nt++) {
            float p0 = __expf(s[nt][0] - nm0);
            float p1 = __expf(s[nt][1] - nm0);
            float p2 = __expf(s[nt][2] - nm1);
            float p3 = __expf(s[nt][3] - nm1);
            rs0 += p0 + p1;
            rs1 += p2 + p3;
            split2h(p0, p1, phg[nt], plg[nt]);
            split2h(p2, p3, phh[nt], plh[nt]);
        }
        rs0 += __shfl_xor_sync(0xffffffff, rs0, 1);
        rs0 += __shfl_xor_sync(0xffffffff, rs0, 2);
        rs1 += __shfl_xor_sync(0xffffffff, rs1, 1);
        rs1 += __shfl_xor_sync(0xffffffff, rs1, 2);
        l0s = l0s * a0 + rs0;
        l1s = l1s * a1 + rs1;
#pragma unroll
        for (int nt = 0; nt < 8; nt++) {
            o[nt][0] *= a0; o[nt][1] *= a0; o[nt][2] *= a1; o[nt][3] *= a1;
        }

        // O += P @ V   (2-term: ph*vh + pl*vh)
#pragma unroll
        for (int kcb = 0; kcb < 4; kcb++) {
            uint32_t ah4[4] = {phg[2 * kcb], phh[2 * kcb], phg[2 * kcb + 1], phh[2 * kcb + 1]};
            uint32_t al4[4] = {plg[2 * kcb], plh[2 * kcb], plg[2 * kcb + 1], plh[2 * kcb + 1]};
#pragma unroll
            for (int ntp = 0; ntp < 4; ntp++) {
                uint32_t voff = sb + (kvb + 2304 + (ntp * 16 + a_r) * QS2 + kcb * 8 + a_c) * 4;
                uint32_t v4[4];
                ldsm4(voff, v4);
                uint32_t v0[2] = {v4[0], v4[2]};
                uint32_t v1[2] = {v4[1], v4[3]};
                mma16h(o[2 * ntp], ah4, v0);
                mma16h(o[2 * ntp + 1], ah4, v1);
                mma16h(o[2 * ntp], al4, v0);
                mma16h(o[2 * ntp + 1], al4, v1);
            }
        }
    }

    // normalize + write split att (fp16 d-pairs, feeds gemm_2t)
    float inv0 = 1.0f / l0s, inv1 = 1.0f / l1s;
#pragma unroll
    for (int nt = 0; nt < 8; nt++) {
        int wc = h * 32 + nt * 4 + cq;
        size_t r0o = (size_t)(b * 2048 + q0 + rb_ + g) * 512 + wc;
        size_t r1o = (size_t)(b * 2048 + q0 + rb_ + g + 8) * 512 + wc;
        uint32_t hh, ll;
        split2h(o[nt][0] * inv0, o[nt][1] * inv0, hh, ll);
        atth[r0o] = hh; attl[r0o] = ll;
        split2h(o[nt][2] * inv1, o[nt][3] * inv1, hh, ll);
        atth[r1o] = hh; attl[r1o] = ll;
    }
}

// ---------------------------------------------------------------------------
extern "C" void kernel_launch(void* const* d_in, const int* in_sizes, int n_in,
                              void* d_out, int out_size)
{
    const float* x     = (const float*)d_in[0];
    const float* Wqkv  = (const float*)d_in[1];
    const float* bqkv  = (const float*)d_in[2];
    const float* Wproj = (const float*)d_in[3];
    const float* bproj = (const float*)d_in[4];
    float* out = (float*)d_out;

    void* p;
    uint32_t *xh, *xl, *wqh, *wph, *qh, *ql, *ath, *atl, *vth;
    cudaGetSymbolAddress(&p, g_xh);    xh = (uint32_t*)p;
    cudaGetSymbolAddress(&p, g_xl);    xl = (uint32_t*)p;
    cudaGetSymbolAddress(&p, g_wqkvh); wqh = (uint32_t*)p;
    cudaGetSymbolAddress(&p, g_wprojh); wph = (uint32_t*)p;
    cudaGetSymbolAddress(&p, g_qkvh);  qh = (uint32_t*)p;
    cudaGetSymbolAddress(&p, g_qkvl);  ql = (uint32_t*)p;
    cudaGetSymbolAddress(&p, g_atth);  ath = (uint32_t*)p;
    cudaGetSymbolAddress(&p, g_attl);  atl = (uint32_t*)p;
    cudaGetSymbolAddress(&p, g_vth);   vth = (uint32_t*)p;

    cudaFuncSetAttribute(gemm_2t<true>,  cudaFuncAttributeMaxDynamicSharedMemorySize, G2SMEM_BYTES);
    cudaFuncSetAttribute(gemm_2t<false>, cudaFuncAttributeMaxDynamicSharedMemorySize, G2SMEM_BYTES);
    cudaFuncSetAttribute(attn_sp, cudaFuncAttributeMaxDynamicSharedMemorySize, ATT_SMEM_U32 * 4);

    // prep: split x (fp16), transpose+convert weights (fp16, 1-piece)
    split_x_k<<<BN * D / 4 / 256, 256>>>(x, xh, xl);
    wsplit_k<<<dim3(3 * D / 64, D / 64), 256>>>(Wqkv, wqh, D, 3 * D);
    wsplit_k<<<dim3(D / 64, D / 64), 256>>>(Wproj, wph, D, D);

    // 1) qkv = x @ Wqkv + bqkv  (fp16 2-term; fp16-split output)
    gemm_2t<true><<<dim3(3 * D / 128, BN / 128), 256, G2SMEM_BYTES>>>(
        xh, xl, wqh, bqkv, nullptr, qh, ql, BN, 3 * D, D);

    // 1b) build V^T (fp16 hi only)
    vtrans_k<<<dim3(N / 64, B * H), 256>>>(qh, vth);

    // 2) attention -> att (fp16-split output)
    attn_sp<<<dim3(N / 128, H, B), 256, ATT_SMEM_U32 * 4>>>(qh, ql, vth, ath, atl);

    // 3) out = att @ Wproj + bproj  (fp16 2-term; fp32 output)
    gemm_2t<false><<<dim3(D / 128, BN / 128), 256, G2SMEM_BYTES>>>(
        ath, atl, wph, bproj, out, nullptr, nullptr, BN, D, D);
}

// round 10
// speedup vs baseline: 5.8921x; 1.1773x over previous
#include <cuda_runtime.h>
#include <cuda_bf16.h>
#include <cuda_fp16.h>
#include <math.h>
#include <stdint.h>

// Problem constants
#define B 4
#define N 2048
#define D 1024
#define H 16
#define HD 64
#define BN (B * N)            // 8192
#define SCALE 0.125f

// Scratch (device globals; u32 = packed fp16x2)
__device__ uint32_t g_xh[BN * 512],      g_xl[BN * 512];       // x split fp16, d-pairs
__device__ uint32_t g_wqkvh[3072 * 512];                       // Wqkv^T fp16 [n][kpair]
__device__ uint32_t g_wprojh[1024 * 512];                      // Wproj^T fp16 [n][kpair]
__device__ uint32_t g_qkvh[BN * 1536],   g_qkvl[BN * 1536];    // qkv split fp16 (lo only written for q cols)
__device__ uint32_t g_atth[BN * 512];                          // att fp16, d-pairs
__device__ uint32_t g_vth[64 * 64 * 1024];                     // V^T fp16 [bh][d][keypair]

// ---------------------------------------------------------------------------
// helpers
// ---------------------------------------------------------------------------
__device__ __forceinline__ void split2h(float x0, float x1, uint32_t& h, uint32_t& l) {
    __half2 hh = __floats2half2_rn(x0, x1);
    float r0 = x0 - __half2float(__low2half(hh));
    float r1 = x1 - __half2float(__high2half(hh));
    __half2 ll = __floats2half2_rn(r0, r1);
    h = *reinterpret_cast<uint32_t*>(&hh);
    l = *reinterpret_cast<uint32_t*>(&ll);
}
__device__ __forceinline__ uint32_t pack_h2(float x0, float x1) {
    __half2 hh = __floats2half2_rn(x0, x1);
    return *reinterpret_cast<uint32_t*>(&hh);
}
// fp16 m16n8k16 mma, fp32 accumulate
__device__ __forceinline__ void mma16h(float* c, const uint32_t* a, const uint32_t* b) {
    asm volatile(
        "mma.sync.aligned.m16n8k16.row.col.f32.f16.f16.f32 "
        "{%0,%1,%2,%3}, {%4,%5,%6,%7}, {%8,%9}, {%0,%1,%2,%3};"
        : "+f"(c[0]), "+f"(c[1]), "+f"(c[2]), "+f"(c[3])
        : "r"(a[0]), "r"(a[1]), "r"(a[2]), "r"(a[3]), "r"(b[0]), "r"(b[1]));
}
__device__ __forceinline__ void ldsm4(uint32_t addr, uint32_t* r) {
    asm volatile("ldmatrix.sync.aligned.m8n8.x4.shared.b16 {%0,%1,%2,%3}, [%4];"
        : "=r"(r[0]), "=r"(r[1]), "=r"(r[2]), "=r"(r[3]) : "r"(addr));
}
__device__ __forceinline__ uint32_t smem_u32(const void* p) {
    uint32_t a;
    asm("{ .reg .u64 t; cvta.to.shared.u64 t, %1; cvt.u32.u64 %0, t; }" : "=r"(a) : "l"(p));
    return a;
}
#define CP_ASYNC16(dst, src) \
    asm volatile("cp.async.cg.shared.global [%0], [%1], 16;" :: "r"(dst), "l"(src))
#define CP_COMMIT() asm volatile("cp.async.commit_group;" ::: "memory")
#define CP_WAIT(n)  asm volatile("cp.async.wait_group %0;" :: "n"(n) : "memory")

// ---------------------------------------------------------------------------
// split_x: x fp32 -> hi/lo fp16 pairs (d-pairs)
// ---------------------------------------------------------------------------
__global__ void split_x_k(const float* __restrict__ x,
                          uint32_t* __restrict__ xh, uint32_t* __restrict__ xl)
{
    int i = blockIdx.x * blockDim.x + threadIdx.x;
    float4 v = ((const float4*)x)[i];
    uint32_t h0, l0, h1, l1;
    split2h(v.x, v.y, h0, l0);
    split2h(v.z, v.w, h1, l1);
    ((uint2*)xh)[i] = make_uint2(h0, h1);
    ((uint2*)xl)[i] = make_uint2(l0, l1);
}

// ---------------------------------------------------------------------------
// wsplit: W[K][Nn] fp32 -> W^T fp16 (1-piece) [n][kpair]
// ---------------------------------------------------------------------------
__global__ __launch_bounds__(256) void wsplit_k(
    const float* __restrict__ W, uint32_t* __restrict__ Wth,
    int K, int Nn)
{
    __shared__ float sw[64 * 68];
    const int tid = threadIdx.x;
    const int k0 = blockIdx.y * 64, n0 = blockIdx.x * 64;
#pragma unroll
    for (int i = 0; i < 4; i++) {
        int f = tid + i * 256;
        int k = f >> 4, nq = f & 15;
        float4 v = *(const float4*)&W[(size_t)(k0 + k) * Nn + n0 + nq * 4];
        *(float4*)&sw[k * 68 + nq * 4] = v;
    }
    __syncthreads();
    const int n = tid >> 2, kq = tid & 3;
    uint32_t hb[8];
#pragma unroll
    for (int j = 0; j < 8; j++) {
        int kp = kq * 8 + j;
        hb[j] = pack_h2(sw[(2 * kp) * 68 + n], sw[(2 * kp + 1) * 68 + n]);
    }
    size_t o = (size_t)(n0 + n) * (K / 2) + k0 / 2 + kq * 8;
    *(uint4*)&Wth[o]     = make_uint4(hb[0], hb[1], hb[2], hb[3]);
    *(uint4*)&Wth[o + 4] = make_uint4(hb[4], hb[5], hb[6], hb[7]);
}

// ---------------------------------------------------------------------------
// vtrans: qkv hi (v section, d-pairs fp16) -> V^T fp16 [bh][d][keypair]
// ---------------------------------------------------------------------------
__global__ __launch_bounds__(256) void vtrans_k(
    const uint32_t* __restrict__ qh, uint32_t* __restrict__ vth)
{
    __shared__ uint32_t sc[32 * 66];
    const int tid = threadIdx.x;
    const int kb = blockIdx.x, bh = blockIdx.y;
    const int b = bh >> 4, h = bh & 15;
#pragma unroll
    for (int i = 0; i < 2; i++) {
        int f = tid + i * 256;
        int key = f >> 3, q = (f & 7) * 4;
        size_t src = (size_t)(b * 2048 + kb * 64 + key) * 1536 + 1024 + h * 32 + q;
        uint4 vh = *(const uint4*)&qh[src];
        sc[(q + 0) * 66 + key] = vh.x; sc[(q + 1) * 66 + key] = vh.y;
        sc[(q + 2) * 66 + key] = vh.z; sc[(q + 3) * 66 + key] = vh.w;
    }
    __syncthreads();
#pragma unroll
    for (int i = 0; i < 8; i++) {
        int f = tid + i * 256;
        int d = f >> 5, kp = f & 31;
        uint32_t sel = (d & 1) ? 0x7632u : 0x5410u;
        uint2 wh = *(const uint2*)&sc[(d >> 1) * 66 + 2 * kp];
        size_t dst = (size_t)(bh * 64 + d) * 1024 + kb * 32 + kp;
        vth[dst] = __byte_perm(wh.x, wh.y, sel);
    }
}

// ---------------------------------------------------------------------------
// GEMM fp16: C = A @ W + bias.  Columns with n < TWO_LIMIT use 2-term A
// (ah+al); remaining columns use 1-term (ah only).
// 128x128 tile, BK=32 (16 kpairs), 256 thr, warps 4(m)x2(n), warp 32x64.
// Single-barrier-per-chunk double-buffered pipeline.
// ---------------------------------------------------------------------------
#define TSTR 20
#define TILE_U32 2560
#define BUF2_U32 7680
#define G2SMEM_BYTES (2 * BUF2_U32 * 4)

template <bool SPLIT_OUT, int TWO_LIMIT>
__global__ __launch_bounds__(256, 2) void gemm_2t(
    const uint32_t* __restrict__ Ah_g, const uint32_t* __restrict__ Al_g,
    const uint32_t* __restrict__ Bh_g,
    const float* __restrict__ bias,
    float* __restrict__ C, uint32_t* __restrict__ Ch, uint32_t* __restrict__ Cl,
    int M, int Nn, int K)
{
    extern __shared__ uint32_t sm[];
    const uint32_t sb = smem_u32(sm);
    const int tid = threadIdx.x;
    const int lane = tid & 31, warp = tid >> 5;
    const int g = lane >> 2, cq = lane & 3;
    const int wm = (warp >> 1) * 32, wn = (warp & 1) * 64;
    const int m0 = blockIdx.y * 128, n0 = blockIdx.x * 128;
    const int kwtot = K / 2;
    const bool two = (TWO_LIMIT > 0) && (n0 < TWO_LIMIT);

    const int a_r = lane & 15, a_c = (lane >> 4) * 4;

    float acc[2][8][4];
#pragma unroll
    for (int mt = 0; mt < 2; mt++)
#pragma unroll
        for (int nt = 0; nt < 8; nt++)
#pragma unroll
            for (int k = 0; k < 4; k++) acc[mt][nt][k] = 0.0f;

    auto issue = [&](int c, int buf) {
        const int kw = c * 16;
        const uint32_t bb = sb + buf * (BUF2_U32 * 4);
#pragma unroll
        for (int i = 0; i < 2; i++) {
            int f = tid + i * 256;
            int r = f >> 2, q = (f & 3) * 4;
            uint32_t d0 = bb + (r * TSTR + q) * 4;
            CP_ASYNC16(d0,                &Ah_g[(size_t)(m0 + r) * kwtot + kw + q]);
            if (two)
                CP_ASYNC16(d0 + TILE_U32 * 4, &Al_g[(size_t)(m0 + r) * kwtot + kw + q]);
            CP_ASYNC16(d0 + TILE_U32 * 8, &Bh_g[(size_t)(n0 + r) * kwtot + kw + q]);
        }
        CP_COMMIT();
    };

    const int nch = K / 32;
    issue(0, 0);
    for (int c = 0; c < nch; c++) {
        CP_WAIT(0);
        __syncthreads();
        if (c + 1 < nch) issue(c + 1, (c + 1) & 1);

        const uint32_t bufb = sb + (c & 1) * (BUF2_U32 * 4);
#pragma unroll
        for (int kc = 0; kc < 2; kc++) {
            uint32_t ah[2][4], al[2][4];
#pragma unroll
            for (int mt = 0; mt < 2; mt++) {
                uint32_t aoff = bufb + ((wm + mt * 16 + a_r) * TSTR + kc * 8 + a_c) * 4;
                ldsm4(aoff, ah[mt]);
                if (two) ldsm4(aoff + TILE_U32 * 4, al[mt]);
            }
#pragma unroll
            for (int ntp = 0; ntp < 4; ntp++) {
                uint32_t boff = bufb + TILE_U32 * 8 +
                                ((wn + ntp * 16 + a_r) * TSTR + kc * 8 + a_c) * 4;
                uint32_t b4[4];
                ldsm4(boff, b4);
                uint32_t b0[2] = {b4[0], b4[2]};
                uint32_t b1[2] = {b4[1], b4[3]};
#pragma unroll
                for (int mt = 0; mt < 2; mt++) mma16h(acc[mt][2 * ntp], ah[mt], b0);
#pragma unroll
                for (int mt = 0; mt < 2; mt++) mma16h(acc[mt][2 * ntp + 1], ah[mt], b1);
                if (two) {
#pragma unroll
                    for (int mt = 0; mt < 2; mt++) mma16h(acc[mt][2 * ntp], al[mt], b0);
#pragma unroll
                    for (int mt = 0; mt < 2; mt++) mma16h(acc[mt][2 * ntp + 1], al[mt], b1);
                }
            }
        }
    }

#pragma unroll
    for (int mt = 0; mt < 2; mt++) {
#pragma unroll
        for (int nt = 0; nt < 8; nt++) {
            int row = m0 + wm + mt * 16 + g;
            int col = n0 + wn + nt * 8 + 2 * cq;
            float b0 = bias[col], b1 = bias[col + 1];
            float v00 = acc[mt][nt][0] + b0, v01 = acc[mt][nt][1] + b1;
            float v10 = acc[mt][nt][2] + b0, v11 = acc[mt][nt][3] + b1;
            if (SPLIT_OUT) {
                int wc = col >> 1;
                uint32_t hh, ll;
                split2h(v00, v01, hh, ll);
                Ch[(size_t)row * (Nn / 2) + wc] = hh;
                if (two) Cl[(size_t)row * (Nn / 2) + wc] = ll;
                split2h(v10, v11, hh, ll);
                Ch[(size_t)(row + 8) * (Nn / 2) + wc] = hh;
                if (two) Cl[(size_t)(row + 8) * (Nn / 2) + wc] = ll;
            } else {
                *(float2*)&C[(size_t)row * Nn + col] = make_float2(v00, v01);
                *(float2*)&C[(size_t)(row + 8) * Nn + col] = make_float2(v10, v11);
            }
        }
    }
}

// ---------------------------------------------------------------------------
// Attention (fp16 flash): Q,P split fp16 hi/lo (2-term); K,V single fp16.
// Register-resident P, double-buffered K/V, one barrier per key-tile.
// Output att: single fp16 (feeds 1-term GEMM2).
// smem u32: Qh@0 (4608), Ql@4608 (4608), 2 KV bufs of 4608: KH@0, VH@2304.
// ---------------------------------------------------------------------------
#define QS2 36
#define KVBUF 4608
#define AKV0 9216
#define ATT_SMEM_U32 (9216 + 2 * KVBUF)   // 18432 u32 = 73728 B

__global__ __launch_bounds__(256, 2) void attn_sp(
    const uint32_t* __restrict__ qh_g, const uint32_t* __restrict__ ql_g,
    const uint32_t* __restrict__ vth,
    uint32_t* __restrict__ atth)
{
    extern __shared__ uint32_t sm[];
    const uint32_t sb = smem_u32(sm);

    const int tid  = threadIdx.x;
    const int lane = tid & 31, warp = tid >> 5;
    const int g = lane >> 2, cq = lane & 3;
    const int b = blockIdx.z, h = blockIdx.y;
    const int bh = b * H + h;
    const int q0 = blockIdx.x * 128;

    const int a_r = lane & 15, a_c = (lane >> 4) * 4;

    // stage Q (hi+lo)
#pragma unroll
    for (int i = 0; i < 4; i++) {
        int f = tid + i * 256;
        int row = f >> 3, q = (f & 7) * 4;
        size_t src = (size_t)(b * 2048 + q0 + row) * 1536 + h * 32 + q;
        uint32_t dst = sb + (row * QS2 + q) * 4;
        CP_ASYNC16(dst, &qh_g[src]);
        CP_ASYNC16(dst + 4608 * 4, &ql_g[src]);
    }
    CP_COMMIT();

    auto issue_kv = [&](int kb, int buf) {
        const uint32_t kvb = AKV0 + buf * KVBUF;
#pragma unroll
        for (int i = 0; i < 2; i++) {
            int f = tid + i * 256;
            int row = f >> 3, q = (f & 7) * 4;
            size_t ksrc = (size_t)(b * 2048 + kb * 64 + row) * 1536 + 512 + h * 32 + q;
            CP_ASYNC16(sb + (kvb + row * QS2 + q) * 4, &qh_g[ksrc]);
            size_t vsrc = (size_t)(bh * 64 + row) * 1024 + kb * 32 + q;
            CP_ASYNC16(sb + (kvb + 2304 + row * QS2 + q) * 4, &vth[vsrc]);
        }
        CP_COMMIT();
    };
    issue_kv(0, 0);

    float m0v = -1e30f, m1v = -1e30f, l0s = 0.0f, l1s = 0.0f;
    float o[8][4];
#pragma unroll
    for (int nt = 0; nt < 8; nt++)
#pragma unroll
        for (int k = 0; k < 4; k++) o[nt][k] = 0.0f;

    const int rb_ = warp * 16;
    const int NKB = N / 64;

    for (int kb = 0; kb < NKB; kb++) {
        CP_WAIT(0);
        __syncthreads();
        if (kb + 1 < NKB) issue_kv(kb + 1, (kb + 1) & 1);

        const uint32_t kvb = AKV0 + (kb & 1) * KVBUF;

        // S = Q @ K^T   (2-term: qh*kh + ql*kh)
        float s[8][4];
#pragma unroll
        for (int nt = 0; nt < 8; nt++)
#pragma unroll
            for (int k = 0; k < 4; k++) s[nt][k] = 0.0f;

#pragma unroll
        for (int kc = 0; kc < 4; kc++) {
            uint32_t qh4[4], ql4[4];
            uint32_t qoff = sb + ((rb_ + a_r) * QS2 + kc * 8 + a_c) * 4;
            ldsm4(qoff, qh4);
            ldsm4(qoff + 4608 * 4, ql4);
#pragma unroll
            for (int ntp = 0; ntp < 4; ntp++) {
                uint32_t koff = sb + (kvb + (ntp * 16 + a_r) * QS2 + kc * 8 + a_c) * 4;
                uint32_t k4[4];
                ldsm4(koff, k4);
                uint32_t k0[2] = {k4[0], k4[2]};
                uint32_t k1[2] = {k4[1], k4[3]};
                mma16h(s[2 * ntp], qh4, k0);
                mma16h(s[2 * ntp + 1], qh4, k1);
                mma16h(s[2 * ntp], ql4, k0);
                mma16h(s[2 * ntp + 1], ql4, k1);
            }
        }

        // online softmax -> register P fragments (fp16 hi/lo)
        float rm0 = -1e30f, rm1 = -1e30f;
#pragma unroll
        for (int nt = 0; nt < 8; nt++) {
            s[nt][0] *= SCALE; s[nt][1] *= SCALE; s[nt][2] *= SCALE; s[nt][3] *= SCALE;
            rm0 = fmaxf(rm0, fmaxf(s[nt][0], s[nt][1]));
            rm1 = fmaxf(rm1, fmaxf(s[nt][2], s[nt][3]));
        }
        rm0 = fmaxf(rm0, __shfl_xor_sync(0xffffffff, rm0, 1));
        rm0 = fmaxf(rm0, __shfl_xor_sync(0xffffffff, rm0, 2));
        rm1 = fmaxf(rm1, __shfl_xor_sync(0xffffffff, rm1, 1));
        rm1 = fmaxf(rm1, __shfl_xor_sync(0xffffffff, rm1, 2));

        float nm0 = fmaxf(m0v, rm0), nm1 = fmaxf(m1v, rm1);
        float a0 = __expf(m0v - nm0), a1 = __expf(m1v - nm1);
        m0v = nm0; m1v = nm1;

        uint32_t phg[8], plg[8], phh[8], plh[8];
        float rs0 = 0.0f, rs1 = 0.0f;
#pragma unroll
        for (int nt = 0; nt < 8; nt++) {
            float p0 = __expf(s[nt][0] - nm0);
            float p1 = __expf(s[nt][1] - nm0);
            float p2 = __expf(s[nt][2] - nm1);
            float p3 = __expf(s[nt][3] - nm1);
            rs0 += p0 + p1;
            rs1 += p2 + p3;
            split2h(p0, p1, phg[nt], plg[nt]);
            split2h(p2, p3, phh[nt], plh[nt]);
        }
        rs0 += __shfl_xor_sync(0xffffffff, rs0, 1);
        rs0 += __shfl_xor_sync(0xffffffff, rs0, 2);
        rs1 += __shfl_xor_sync(0xffffffff, rs1, 1);
        rs1 += __shfl_xor_sync(0xffffffff, rs1, 2);
        l0s = l0s * a0 + rs0;
        l1s = l1s * a1 + rs1;
#pragma unroll
        for (int nt = 0; nt < 8; nt++) {
            o[nt][0] *= a0; o[nt][1] *= a0; o[nt][2] *= a1; o[nt][3] *= a1;
        }

        // O += P @ V   (2-term: ph*vh + pl*vh)
#pragma unroll
        for (int kcb = 0; kcb < 4; kcb++) {
            uint32_t ah4[4] = {phg[2 * kcb], phh[2 * kcb], phg[2 * kcb + 1], phh[2 * kcb + 1]};
            uint32_t al4[4] = {plg[2 * kcb], plh[2 * kcb], plg[2 * kcb + 1], plh[2 * kcb + 1]};
#pragma unroll
            for (int ntp = 0; ntp < 4; ntp++) {
                uint32_t voff = sb + (kvb + 2304 + (ntp * 16 + a_r) * QS2 + kcb * 8 + a_c) * 4;
                uint32_t v4[4];
                ldsm4(voff, v4);
                uint32_t v0[2] = {v4[0], v4[2]};
                uint32_t v1[2] = {v4[1], v4[3]};
                mma16h(o[2 * ntp], ah4, v0);
                mma16h(o[2 * ntp + 1], ah4, v1);
                mma16h(o[2 * ntp], al4, v0);
                mma16h(o[2 * ntp + 1], al4, v1);
            }
        }
    }

    // normalize + write att (single fp16 d-pairs, feeds 1-term gemm)
    float inv0 = 1.0f / l0s, inv1 = 1.0f / l1s;
#pragma unroll
    for (int nt = 0; nt < 8; nt++) {
        int wc = h * 32 + nt * 4 + cq;
        size_t r0o = (size_t)(b * 2048 + q0 + rb_ + g) * 512 + wc;
        size_t r1o = (size_t)(b * 2048 + q0 + rb_ + g + 8) * 512 + wc;
        atth[r0o] = pack_h2(o[nt][0] * inv0, o[nt][1] * inv0);
        atth[r1o] = pack_h2(o[nt][2] * inv1, o[nt][3] * inv1);
    }
}

// ---------------------------------------------------------------------------
extern "C" void kernel_launch(void* const* d_in, const int* in_sizes, int n_in,
                              void* d_out, int out_size)
{
    const float* x     = (const float*)d_in[0];
    const float* Wqkv  = (const float*)d_in[1];
    const float* bqkv  = (const float*)d_in[2];
    const float* Wproj = (const float*)d_in[3];
    const float* bproj = (const float*)d_in[4];
    float* out = (float*)d_out;

    void* p;
    uint32_t *xh, *xl, *wqh, *wph, *qh, *ql, *ath, *vth;
    cudaGetSymbolAddress(&p, g_xh);    xh = (uint32_t*)p;
    cudaGetSymbolAddress(&p, g_xl);    xl = (uint32_t*)p;
    cudaGetSymbolAddress(&p, g_wqkvh); wqh = (uint32_t*)p;
    cudaGetSymbolAddress(&p, g_wprojh); wph = (uint32_t*)p;
    cudaGetSymbolAddress(&p, g_qkvh);  qh = (uint32_t*)p;
    cudaGetSymbolAddress(&p, g_qkvl);  ql = (uint32_t*)p;
    cudaGetSymbolAddress(&p, g_atth);  ath = (uint32_t*)p;
    cudaGetSymbolAddress(&p, g_vth);   vth = (uint32_t*)p;

    cudaFuncSetAttribute(gemm_2t<true, 1024>, cudaFuncAttributeMaxDynamicSharedMemorySize, G2SMEM_BYTES);
    cudaFuncSetAttribute(gemm_2t<false, 0>,   cudaFuncAttributeMaxDynamicSharedMemorySize, G2SMEM_BYTES);
    cudaFuncSetAttribute(attn_sp, cudaFuncAttributeMaxDynamicSharedMemorySize, ATT_SMEM_U32 * 4);

    // prep: split x (fp16), transpose+convert weights (fp16, 1-piece)
    split_x_k<<<BN * D / 4 / 256, 256>>>(x, xh, xl);
    wsplit_k<<<dim3(3 * D / 64, D / 64), 256>>>(Wqkv, wqh, D, 3 * D);
    wsplit_k<<<dim3(D / 64, D / 64), 256>>>(Wproj, wph, D, D);

    // 1) qkv = x @ Wqkv + bqkv  (2-term for q cols, 1-term for k/v cols)
    gemm_2t<true, 1024><<<dim3(3 * D / 128, BN / 128), 256, G2SMEM_BYTES>>>(
        xh, xl, wqh, bqkv, nullptr, qh, ql, BN, 3 * D, D);

    // 1b) build V^T (fp16 hi only)
    vtrans_k<<<dim3(N / 64, B * H), 256>>>(qh, vth);

    // 2) attention -> att (single fp16 output)
    attn_sp<<<dim3(N / 128, H, B), 256, ATT_SMEM_U32 * 4>>>(qh, ql, vth, ath);

    // 3) out = att @ Wproj + bproj  (1-term; fp32 output)
    gemm_2t<false, 0><<<dim3(D / 128, BN / 128), 256, G2SMEM_BYTES>>>(
        ath, nullptr, wph, bproj, out, nullptr, nullptr, BN, D, D);
}

// round 11
// speedup vs baseline: 8.4498x; 1.4341x over previous
#include <cuda_runtime.h>
#include <cuda_bf16.h>
#include <cuda_fp16.h>
#include <math.h>
#include <stdint.h>

// Problem constants
#define B 4
#define N 2048
#define D 1024
#define H 16
#define HD 64
#define BN (B * N)            // 8192
#define SCALE 0.125f

// Scratch (device globals; u32 = packed fp16x2)
__device__ uint32_t g_xh[BN * 512];        // x fp16, d-pairs
__device__ uint32_t g_wqkvh[3072 * 512];   // Wqkv^T fp16 [n][kpair]
__device__ uint32_t g_wprojh[1024 * 512];  // Wproj^T fp16 [n][kpair]
__device__ uint32_t g_qkvh[BN * 1536];     // qkv fp16, col-pairs
__device__ uint32_t g_atth[BN * 512];      // att fp16, d-pairs
__device__ uint32_t g_vth[64 * 64 * 1024]; // V^T fp16 [bh][d][keypair]

// ---------------------------------------------------------------------------
// helpers
// ---------------------------------------------------------------------------
__device__ __forceinline__ uint32_t pack_h2(float x0, float x1) {
    __half2 hh = __floats2half2_rn(x0, x1);
    return *reinterpret_cast<uint32_t*>(&hh);
}
// fp16 m16n8k16 mma, fp32 accumulate
__device__ __forceinline__ void mma16h(float* c, const uint32_t* a, const uint32_t* b) {
    asm volatile(
        "mma.sync.aligned.m16n8k16.row.col.f32.f16.f16.f32 "
        "{%0,%1,%2,%3}, {%4,%5,%6,%7}, {%8,%9}, {%0,%1,%2,%3};"
        : "+f"(c[0]), "+f"(c[1]), "+f"(c[2]), "+f"(c[3])
        : "r"(a[0]), "r"(a[1]), "r"(a[2]), "r"(a[3]), "r"(b[0]), "r"(b[1]));
}
__device__ __forceinline__ void ldsm4(uint32_t addr, uint32_t* r) {
    asm volatile("ldmatrix.sync.aligned.m8n8.x4.shared.b16 {%0,%1,%2,%3}, [%4];"
        : "=r"(r[0]), "=r"(r[1]), "=r"(r[2]), "=r"(r[3]) : "r"(addr));
}
__device__ __forceinline__ uint32_t smem_u32(const void* p) {
    uint32_t a;
    asm("{ .reg .u64 t; cvta.to.shared.u64 t, %1; cvt.u32.u64 %0, t; }" : "=r"(a) : "l"(p));
    return a;
}
#define CP_ASYNC16(dst, src) \
    asm volatile("cp.async.cg.shared.global [%0], [%1], 16;" :: "r"(dst), "l"(src))
#define CP_COMMIT() asm volatile("cp.async.commit_group;" ::: "memory")
#define CP_WAIT(n)  asm volatile("cp.async.wait_group %0;" :: "n"(n) : "memory")

// ---------------------------------------------------------------------------
// split_x: x fp32 -> fp16 pairs (d-pairs)
// ---------------------------------------------------------------------------
__global__ void split_x_k(const float* __restrict__ x, uint32_t* __restrict__ xh)
{
    int i = blockIdx.x * blockDim.x + threadIdx.x;
    float4 v = ((const float4*)x)[i];
    ((uint2*)xh)[i] = make_uint2(pack_h2(v.x, v.y), pack_h2(v.z, v.w));
}

// ---------------------------------------------------------------------------
// wsplit: W[K][Nn] fp32 -> W^T fp16 [n][kpair]
// ---------------------------------------------------------------------------
__global__ __launch_bounds__(256) void wsplit_k(
    const float* __restrict__ W, uint32_t* __restrict__ Wth,
    int K, int Nn)
{
    __shared__ float sw[64 * 68];
    const int tid = threadIdx.x;
    const int k0 = blockIdx.y * 64, n0 = blockIdx.x * 64;
#pragma unroll
    for (int i = 0; i < 4; i++) {
        int f = tid + i * 256;
        int k = f >> 4, nq = f & 15;
        float4 v = *(const float4*)&W[(size_t)(k0 + k) * Nn + n0 + nq * 4];
        *(float4*)&sw[k * 68 + nq * 4] = v;
    }
    __syncthreads();
    const int n = tid >> 2, kq = tid & 3;
    uint32_t hb[8];
#pragma unroll
    for (int j = 0; j < 8; j++) {
        int kp = kq * 8 + j;
        hb[j] = pack_h2(sw[(2 * kp) * 68 + n], sw[(2 * kp + 1) * 68 + n]);
    }
    size_t o = (size_t)(n0 + n) * (K / 2) + k0 / 2 + kq * 8;
    *(uint4*)&Wth[o]     = make_uint4(hb[0], hb[1], hb[2], hb[3]);
    *(uint4*)&Wth[o + 4] = make_uint4(hb[4], hb[5], hb[6], hb[7]);
}

// ---------------------------------------------------------------------------
// vtrans: qkv (v section, d-pairs fp16) -> V^T fp16 [bh][d][keypair]
// ---------------------------------------------------------------------------
__global__ __launch_bounds__(256) void vtrans_k(
    const uint32_t* __restrict__ qh, uint32_t* __restrict__ vth)
{
    __shared__ uint32_t sc[32 * 66];
    const int tid = threadIdx.x;
    const int kb = blockIdx.x, bh = blockIdx.y;
    const int b = bh >> 4, h = bh & 15;
#pragma unroll
    for (int i = 0; i < 2; i++) {
        int f = tid + i * 256;
        int key = f >> 3, q = (f & 7) * 4;
        size_t src = (size_t)(b * 2048 + kb * 64 + key) * 1536 + 1024 + h * 32 + q;
        uint4 vh = *(const uint4*)&qh[src];
        sc[(q + 0) * 66 + key] = vh.x; sc[(q + 1) * 66 + key] = vh.y;
        sc[(q + 2) * 66 + key] = vh.z; sc[(q + 3) * 66 + key] = vh.w;
    }
    __syncthreads();
#pragma unroll
    for (int i = 0; i < 8; i++) {
        int f = tid + i * 256;
        int d = f >> 5, kp = f & 31;
        uint32_t sel = (d & 1) ? 0x7632u : 0x5410u;
        uint2 wh = *(const uint2*)&sc[(d >> 1) * 66 + 2 * kp];
        size_t dst = (size_t)(bh * 64 + d) * 1024 + kb * 32 + kp;
        vth[dst] = __byte_perm(wh.x, wh.y, sel);
    }
}

// ---------------------------------------------------------------------------
// GEMM fp16 1-term: C = A @ W + bias.
// 128x128 tile, BK=32 (16 kpairs), 256 thr, warps 4(m)x2(n), warp 32x64.
// Single-barrier-per-chunk double-buffered pipeline.
// smem/buf: Ah, Bh each [128][20] u32 -> 5120 u32/buf, 2 bufs = 40960 B.
// ---------------------------------------------------------------------------
#define TSTR 20
#define TILE_U32 2560
#define BUF1_U32 5120
#define G1SMEM_BYTES (2 * BUF1_U32 * 4)

template <bool SPLIT_OUT>
__global__ __launch_bounds__(256, 2) void gemm_1t(
    const uint32_t* __restrict__ Ah_g,
    const uint32_t* __restrict__ Bh_g,
    const float* __restrict__ bias,
    float* __restrict__ C, uint32_t* __restrict__ Ch,
    int M, int Nn, int K)
{
    extern __shared__ uint32_t sm[];
    const uint32_t sb = smem_u32(sm);
    const int tid = threadIdx.x;
    const int lane = tid & 31, warp = tid >> 5;
    const int g = lane >> 2, cq = lane & 3;
    const int wm = (warp >> 1) * 32, wn = (warp & 1) * 64;
    const int m0 = blockIdx.y * 128, n0 = blockIdx.x * 128;
    const int kwtot = K / 2;

    const int a_r = lane & 15, a_c = (lane >> 4) * 4;

    float acc[2][8][4];
#pragma unroll
    for (int mt = 0; mt < 2; mt++)
#pragma unroll
        for (int nt = 0; nt < 8; nt++)
#pragma unroll
            for (int k = 0; k < 4; k++) acc[mt][nt][k] = 0.0f;

    auto issue = [&](int c, int buf) {
        const int kw = c * 16;
        const uint32_t bb = sb + buf * (BUF1_U32 * 4);
#pragma unroll
        for (int i = 0; i < 2; i++) {
            int f = tid + i * 256;
            int r = f >> 2, q = (f & 3) * 4;
            uint32_t d0 = bb + (r * TSTR + q) * 4;
            CP_ASYNC16(d0,                &Ah_g[(size_t)(m0 + r) * kwtot + kw + q]);
            CP_ASYNC16(d0 + TILE_U32 * 4, &Bh_g[(size_t)(n0 + r) * kwtot + kw + q]);
        }
        CP_COMMIT();
    };

    const int nch = K / 32;
    issue(0, 0);
    for (int c = 0; c < nch; c++) {
        CP_WAIT(0);
        __syncthreads();
        if (c + 1 < nch) issue(c + 1, (c + 1) & 1);

        const uint32_t bufb = sb + (c & 1) * (BUF1_U32 * 4);
#pragma unroll
        for (int kc = 0; kc < 2; kc++) {
            uint32_t ah[2][4];
#pragma unroll
            for (int mt = 0; mt < 2; mt++) {
                uint32_t aoff = bufb + ((wm + mt * 16 + a_r) * TSTR + kc * 8 + a_c) * 4;
                ldsm4(aoff, ah[mt]);
            }
#pragma unroll
            for (int ntp = 0; ntp < 4; ntp++) {
                uint32_t boff = bufb + TILE_U32 * 4 +
                                ((wn + ntp * 16 + a_r) * TSTR + kc * 8 + a_c) * 4;
                uint32_t b4[4];
                ldsm4(boff, b4);
                uint32_t b0[2] = {b4[0], b4[2]};
                uint32_t b1[2] = {b4[1], b4[3]};
#pragma unroll
                for (int mt = 0; mt < 2; mt++) mma16h(acc[mt][2 * ntp], ah[mt], b0);
#pragma unroll
                for (int mt = 0; mt < 2; mt++) mma16h(acc[mt][2 * ntp + 1], ah[mt], b1);
            }
        }
    }

#pragma unroll
    for (int mt = 0; mt < 2; mt++) {
#pragma unroll
        for (int nt = 0; nt < 8; nt++) {
            int row = m0 + wm + mt * 16 + g;
            int col = n0 + wn + nt * 8 + 2 * cq;
            float b0 = bias[col], b1 = bias[col + 1];
            float v00 = acc[mt][nt][0] + b0, v01 = acc[mt][nt][1] + b1;
            float v10 = acc[mt][nt][2] + b0, v11 = acc[mt][nt][3] + b1;
            if (SPLIT_OUT) {
                int wc = col >> 1;
                Ch[(size_t)row * (Nn / 2) + wc]       = pack_h2(v00, v01);
                Ch[(size_t)(row + 8) * (Nn / 2) + wc] = pack_h2(v10, v11);
            } else {
                *(float2*)&C[(size_t)row * Nn + col] = make_float2(v00, v01);
                *(float2*)&C[(size_t)(row + 8) * Nn + col] = make_float2(v10, v11);
            }
        }
    }
}

// ---------------------------------------------------------------------------
// Attention (fp16 1-term flash): Q,K,P,V all single fp16, fp32 accum/softmax.
// Register-resident P, double-buffered K/V, one barrier per key-tile.
// smem u32: Q@0 (4608), 2 KV bufs of 4608 at 4608: KH@0, VH@2304.
// Total 13824 u32 = 55296 B.
// ---------------------------------------------------------------------------
#define QS2 36
#define KVBUF 4608
#define AKV0 4608
#define ATT_SMEM_U32 (4608 + 2 * KVBUF)

__global__ __launch_bounds__(256, 2) void attn_1t(
    const uint32_t* __restrict__ qh_g,
    const uint32_t* __restrict__ vth,
    uint32_t* __restrict__ atth)
{
    extern __shared__ uint32_t sm[];
    const uint32_t sb = smem_u32(sm);

    const int tid  = threadIdx.x;
    const int lane = tid & 31, warp = tid >> 5;
    const int g = lane >> 2, cq = lane & 3;
    const int b = blockIdx.z, h = blockIdx.y;
    const int bh = b * H + h;
    const int q0 = blockIdx.x * 128;

    const int a_r = lane & 15, a_c = (lane >> 4) * 4;

    // stage Q
#pragma unroll
    for (int i = 0; i < 4; i++) {
        int f = tid + i * 256;
        int row = f >> 3, q = (f & 7) * 4;
        size_t src = (size_t)(b * 2048 + q0 + row) * 1536 + h * 32 + q;
        CP_ASYNC16(sb + (row * QS2 + q) * 4, &qh_g[src]);
    }
    CP_COMMIT();

    auto issue_kv = [&](int kb, int buf) {
        const uint32_t kvb = AKV0 + buf * KVBUF;
#pragma unroll
        for (int i = 0; i < 2; i++) {
            int f = tid + i * 256;
            int row = f >> 3, q = (f & 7) * 4;
            size_t ksrc = (size_t)(b * 2048 + kb * 64 + row) * 1536 + 512 + h * 32 + q;
            CP_ASYNC16(sb + (kvb + row * QS2 + q) * 4, &qh_g[ksrc]);
            size_t vsrc = (size_t)(bh * 64 + row) * 1024 + kb * 32 + q;
            CP_ASYNC16(sb + (kvb + 2304 + row * QS2 + q) * 4, &vth[vsrc]);
        }
        CP_COMMIT();
    };
    issue_kv(0, 0);

    float m0v = -1e30f, m1v = -1e30f, l0s = 0.0f, l1s = 0.0f;
    float o[8][4];
#pragma unroll
    for (int nt = 0; nt < 8; nt++)
#pragma unroll
        for (int k = 0; k < 4; k++) o[nt][k] = 0.0f;

    const int rb_ = warp * 16;
    const int NKB = N / 64;

    for (int kb = 0; kb < NKB; kb++) {
        CP_WAIT(0);
        __syncthreads();
        if (kb + 1 < NKB) issue_kv(kb + 1, (kb + 1) & 1);

        const uint32_t kvb = AKV0 + (kb & 1) * KVBUF;

        // S = Q @ K^T
        float s[8][4];
#pragma unroll
        for (int nt = 0; nt < 8; nt++)
#pragma unroll
            for (int k = 0; k < 4; k++) s[nt][k] = 0.0f;

#pragma unroll
        for (int kc = 0; kc < 4; kc++) {
            uint32_t qh4[4];
            ldsm4(sb + ((rb_ + a_r) * QS2 + kc * 8 + a_c) * 4, qh4);
#pragma unroll
            for (int ntp = 0; ntp < 4; ntp++) {
                uint32_t koff = sb + (kvb + (ntp * 16 + a_r) * QS2 + kc * 8 + a_c) * 4;
                uint32_t k4[4];
                ldsm4(koff, k4);
                uint32_t k0[2] = {k4[0], k4[2]};
                uint32_t k1[2] = {k4[1], k4[3]};
                mma16h(s[2 * ntp], qh4, k0);
                mma16h(s[2 * ntp + 1], qh4, k1);
            }
        }

        // online softmax -> register P fragments (fp16)
        float rm0 = -1e30f, rm1 = -1e30f;
#pragma unroll
        for (int nt = 0; nt < 8; nt++) {
            s[nt][0] *= SCALE; s[nt][1] *= SCALE; s[nt][2] *= SCALE; s[nt][3] *= SCALE;
            rm0 = fmaxf(rm0, fmaxf(s[nt][0], s[nt][1]));
            rm1 = fmaxf(rm1, fmaxf(s[nt][2], s[nt][3]));
        }
        rm0 = fmaxf(rm0, __shfl_xor_sync(0xffffffff, rm0, 1));
        rm0 = fmaxf(rm0, __shfl_xor_sync(0xffffffff, rm0, 2));
        rm1 = fmaxf(rm1, __shfl_xor_sync(0xffffffff, rm1, 1));
        rm1 = fmaxf(rm1, __shfl_xor_sync(0xffffffff, rm1, 2));

        float nm0 = fmaxf(m0v, rm0), nm1 = fmaxf(m1v, rm1);
        float a0 = __expf(m0v - nm0), a1 = __expf(m1v - nm1);
        m0v = nm0; m1v = nm1;

        uint32_t phg[8], phh[8];
        float rs0 = 0.0f, rs1 = 0.0f;
#pragma unroll
        for (int nt = 0; nt < 8; nt++) {
            float p0 = __expf(s[nt][0] - nm0);
            float p1 = __expf(s[nt][1] - nm0);
            float p2 = __expf(s[nt][2] - nm1);
            float p3 = __expf(s[nt][3] - nm1);
            rs0 += p0 + p1;
            rs1 += p2 + p3;
            phg[nt] = pack_h2(p0, p1);
            phh[nt] = pack_h2(p2, p3);
        }
        rs0 += __shfl_xor_sync(0xffffffff, rs0, 1);
        rs0 += __shfl_xor_sync(0xffffffff, rs0, 2);
        rs1 += __shfl_xor_sync(0xffffffff, rs1, 1);
        rs1 += __shfl_xor_sync(0xffffffff, rs1, 2);
        l0s = l0s * a0 + rs0;
        l1s = l1s * a1 + rs1;
#pragma unroll
        for (int nt = 0; nt < 8; nt++) {
            o[nt][0] *= a0; o[nt][1] *= a0; o[nt][2] *= a1; o[nt][3] *= a1;
        }

        // O += P @ V
#pragma unroll
        for (int kcb = 0; kcb < 4; kcb++) {
            uint32_t ah4[4] = {phg[2 * kcb], phh[2 * kcb], phg[2 * kcb + 1], phh[2 * kcb + 1]};
#pragma unroll
            for (int ntp = 0; ntp < 4; ntp++) {
                uint32_t voff = sb + (kvb + 2304 + (ntp * 16 + a_r) * QS2 + kcb * 8 + a_c) * 4;
                uint32_t v4[4];
                ldsm4(voff, v4);
                uint32_t v0[2] = {v4[0], v4[2]};
                uint32_t v1[2] = {v4[1], v4[3]};
                mma16h(o[2 * ntp], ah4, v0);
                mma16h(o[2 * ntp + 1], ah4, v1);
            }
        }
    }

    // normalize + write att (fp16 d-pairs)
    float inv0 = 1.0f / l0s, inv1 = 1.0f / l1s;
#pragma unroll
    for (int nt = 0; nt < 8; nt++) {
        int wc = h * 32 + nt * 4 + cq;
        size_t r0o = (size_t)(b * 2048 + q0 + rb_ + g) * 512 + wc;
        size_t r1o = (size_t)(b * 2048 + q0 + rb_ + g + 8) * 512 + wc;
        atth[r0o] = pack_h2(o[nt][0] * inv0, o[nt][1] * inv0);
        atth[r1o] = pack_h2(o[nt][2] * inv1, o[nt][3] * inv1);
    }
}

// ---------------------------------------------------------------------------
extern "C" void kernel_launch(void* const* d_in, const int* in_sizes, int n_in,
                              void* d_out, int out_size)
{
    const float* x     = (const float*)d_in[0];
    const float* Wqkv  = (const float*)d_in[1];
    const float* bqkv  = (const float*)d_in[2];
    const float* Wproj = (const float*)d_in[3];
    const float* bproj = (const float*)d_in[4];
    float* out = (float*)d_out;

    void* p;
    uint32_t *xh, *wqh, *wph, *qh, *ath, *vth;
    cudaGetSymbolAddress(&p, g_xh);     xh = (uint32_t*)p;
    cudaGetSymbolAddress(&p, g_wqkvh);  wqh = (uint32_t*)p;
    cudaGetSymbolAddress(&p, g_wprojh); wph = (uint32_t*)p;
    cudaGetSymbolAddress(&p, g_qkvh);   qh = (uint32_t*)p;
    cudaGetSymbolAddress(&p, g_atth);   ath = (uint32_t*)p;
    cudaGetSymbolAddress(&p, g_vth);    vth = (uint32_t*)p;

    cudaFuncSetAttribute(gemm_1t<true>,  cudaFuncAttributeMaxDynamicSharedMemorySize, G1SMEM_BYTES);
    cudaFuncSetAttribute(gemm_1t<false>, cudaFuncAttributeMaxDynamicSharedMemorySize, G1SMEM_BYTES);
    cudaFuncSetAttribute(attn_1t, cudaFuncAttributeMaxDynamicSharedMemorySize, ATT_SMEM_U32 * 4);

    // prep: convert x (fp16 pairs), transpose+convert weights (fp16)
    split_x_k<<<BN * D / 4 / 256, 256>>>(x, xh);
    wsplit_k<<<dim3(3 * D / 64, D / 64), 256>>>(Wqkv, wqh, D, 3 * D);
    wsplit_k<<<dim3(D / 64, D / 64), 256>>>(Wproj, wph, D, D);

    // 1) qkv = x @ Wqkv + bqkv  (fp16 out)
    gemm_1t<true><<<dim3(3 * D / 128, BN / 128), 256, G1SMEM_BYTES>>>(
        xh, wqh, bqkv, nullptr, qh, BN, 3 * D, D);

    // 1b) build V^T (fp16)
    vtrans_k<<<dim3(N / 64, B * H), 256>>>(qh, vth);

    // 2) attention -> att (fp16 out)
    attn_1t<<<dim3(N / 128, H, B), 256, ATT_SMEM_U32 * 4>>>(qh, vth, ath);

    // 3) out = att @ Wproj + bproj  (fp32 out)
    gemm_1t<false><<<dim3(D / 128, BN / 128), 256, G1SMEM_BYTES>>>(
        ath, wph, bproj, out, nullptr, BN, D, D);
}